// round 9
// baseline (speedup 1.0000x reference)
#include <cuda_runtime.h>
#include <math.h>
#include <stdint.h>

// Problem constants
#define BDIM   2
#define LDIM   2048
#define DMODEL 1024
#define HEADS  16
#define DKH    64
#define D3     (3 * DMODEL)
#define ROWS   (BDIM * LDIM)   // 4096
#define GK     1024            // K for both projection GEMMs

// Scratch (allocation-free: __device__ globals)
__device__ float g_qkv[(size_t)ROWS * D3];       // [B*L, 3*D], tf32-rounded values
__device__ float g_attn[(size_t)ROWS * DMODEL];  // [B,L,H,dk] (tf32-rounded)
__device__ float g_x[(size_t)ROWS * DMODEL];     // tf32-rounded x
__device__ float g_wqkvT[(size_t)D3 * GK];       // [3072][1024] k-major, tf32-rounded
__device__ float g_woutT[(size_t)DMODEL * GK];   // [1024][1024] k-major, tf32-rounded
__device__ float g_vt[(size_t)BDIM * HEADS * DKH * LDIM]; // [bh][d][L]

// ===========================================================================
// Helpers
// ===========================================================================
__device__ __forceinline__ float tf32r(float x) {
    uint32_t y;
    asm("cvt.rna.tf32.f32 %0, %1;" : "=r"(y) : "f"(x));
    return __uint_as_float(y);
}
__device__ __forceinline__ uint32_t smem_u32(const void* p) {
    uint32_t a;
    asm("{ .reg .u64 t; cvta.to.shared.u64 t, %1; cvt.u32.u64 %0, t; }" : "=r"(a) : "l"(p));
    return a;
}
#define SWZ128(x) ((x) ^ (((x) >> 3) & 0x70))

__device__ __forceinline__ void cp16(uint32_t dst, const void* src) {
    asm volatile("cp.async.cg.shared.global [%0], [%1], 16;" :: "r"(dst), "l"(src));
}
__device__ __forceinline__ void ldsm4(uint32_t& r0, uint32_t& r1, uint32_t& r2, uint32_t& r3,
                                      uint32_t addr) {
    asm volatile("ldmatrix.sync.aligned.m8n8.x4.shared.b16 {%0,%1,%2,%3}, [%4];"
                 : "=r"(r0), "=r"(r1), "=r"(r2), "=r"(r3) : "r"(addr));
}
__device__ __forceinline__ void mma_tf32(float* c, const uint32_t* a, uint32_t b0, uint32_t b1) {
    asm volatile("mma.sync.aligned.m16n8k8.row.col.f32.tf32.tf32.f32 "
                 "{%0,%1,%2,%3}, {%4,%5,%6,%7}, {%8,%9}, {%0,%1,%2,%3};"
                 : "+f"(c[0]), "+f"(c[1]), "+f"(c[2]), "+f"(c[3])
                 : "r"(a[0]), "r"(a[1]), "r"(a[2]), "r"(a[3]), "r"(b0), "r"(b1));
}

// ===========================================================================
// Prep kernels
// ===========================================================================
__global__ void round_tf32_kernel(const float* __restrict__ in, float* __restrict__ out, int n4) {
    int i = blockIdx.x * blockDim.x + threadIdx.x;
    if (i < n4) {
        float4 v = ((const float4*)in)[i];
        v.x = tf32r(v.x); v.y = tf32r(v.y); v.z = tf32r(v.z); v.w = tf32r(v.w);
        ((float4*)out)[i] = v;
    }
}

// in [K][N] row-major -> out [N][K] row-major, tf32-rounded. block (32,8)
__global__ void transpose_tf32_kernel(const float* __restrict__ in, float* __restrict__ out,
                                      int K, int N) {
    __shared__ float t[32][33];
    int n0 = blockIdx.x * 32, k0 = blockIdx.y * 32;
    for (int j = threadIdx.y; j < 32; j += 8)
        t[j][threadIdx.x] = tf32r(in[(size_t)(k0 + j) * N + n0 + threadIdx.x]);
    __syncthreads();
    for (int j = threadIdx.y; j < 32; j += 8)
        out[(size_t)(n0 + j) * K + k0 + threadIdx.x] = t[threadIdx.x][j];
}

// Transpose the V third of qkv (already tf32-rounded) into [bh][d=64][L].
__global__ void vtrans_kernel(const float* __restrict__ qkv, float* __restrict__ vt) {
    __shared__ float t[32][33];
    int l0 = blockIdx.x * 32, d0 = blockIdx.y * 32;
    int bh = blockIdx.z;
    int b  = bh >> 4, h = bh & 15;
    const float* src = qkv + (size_t)b * LDIM * D3 + 2 * DMODEL + h * DKH;
    for (int j = threadIdx.y; j < 32; j += 8)
        t[j][threadIdx.x] = src[(size_t)(l0 + j) * D3 + d0 + threadIdx.x];
    __syncthreads();
    float* dst = vt + ((size_t)bh * DKH) * LDIM;
    for (int j = threadIdx.y; j < 32; j += 8)
        dst[(size_t)(d0 + j) * LDIM + l0 + threadIdx.x] = t[threadIdx.x][j];
}

// ===========================================================================
// tf32 mma.sync GEMM: C[M,N] = A[M,K] @ Bt[N,K]^T + bias[N]
// 3-stage cp.async pipeline, ONE __syncthreads per K-chunk.
// ===========================================================================
#define GBK    32
#define GTILE  (128 * GBK * 4)          // 16KB per operand tile
#define GSTG   3
#define GS_TOTAL (GSTG * 2 * GTILE)     // 96KB

__device__ __forceinline__ void gemm_load_tile(const float* __restrict__ src, int row0, int k0,
                                               uint32_t smemBase, int tid) {
    #pragma unroll
    for (int j = 0; j < 4; j++) {
        int i   = tid + j * 256;
        int row = i >> 3;
        int c   = i & 7;
        cp16(smemBase + SWZ128(row * 128 + c * 16),
             src + (size_t)(row0 + row) * GK + k0 + c * 4);
    }
}

template<bool RND>
__global__ __launch_bounds__(256) void gemm_mma_kernel(
    const float* __restrict__ A, const float* __restrict__ Bt,
    const float* __restrict__ bias, float* __restrict__ C, int N)
{
    extern __shared__ char smc[];
    const uint32_t sb = smem_u32(smc);
    const int tid  = threadIdx.x;
    const int lane = tid & 31;
    const int w    = tid >> 5;
    const int m0   = blockIdx.y * 128;
    const int n0   = blockIdx.x * 128;
    const int wm   = (w & 1) * 64;
    const int wn   = (w >> 1) * 32;

    const int aOff = (wm + (lane & 15)) * 128 + ((lane >> 4) << 4);
    const int bOff = (wn + ((lane >> 4) << 3) + (lane & 7)) * 128 + (((lane >> 3) & 1) << 4);

    float acc[16][4];
    #pragma unroll
    for (int t = 0; t < 16; t++)
        #pragma unroll
        for (int j = 0; j < 4; j++) acc[t][j] = 0.0f;

    // prime stages 0 and 1
    gemm_load_tile(A,  m0, 0, sb, tid);
    gemm_load_tile(Bt, n0, 0, sb + GTILE, tid);
    asm volatile("cp.async.commit_group;" ::: "memory");
    gemm_load_tile(A,  m0, GBK, sb + 2 * GTILE, tid);
    gemm_load_tile(Bt, n0, GBK, sb + 3 * GTILE, tid);
    asm volatile("cp.async.commit_group;" ::: "memory");

    const int NCHUNK = GK / GBK;   // 32
    for (int c = 0; c < NCHUNK; c++) {
        // chunk c must be resident (pending groups at loop head: {c, c+1})
        if (c < NCHUNK - 1) { asm volatile("cp.async.wait_group 1;" ::: "memory"); }
        else                { asm volatile("cp.async.wait_group 0;" ::: "memory"); }
        __syncthreads();

        // prefetch chunk c+2 into slot (c+2)%3 == (c-1)%3 (drained by the sync)
        if (c + 2 < NCHUNK) {
            const uint32_t sp = sb + ((c + 2) % GSTG) * 2 * GTILE;
            gemm_load_tile(A,  m0, (c + 2) * GBK, sp, tid);
            gemm_load_tile(Bt, n0, (c + 2) * GBK, sp + GTILE, tid);
            asm volatile("cp.async.commit_group;" ::: "memory");
        }

        const uint32_t ba = sb + (c % GSTG) * 2 * GTILE;
        const uint32_t bb = ba + GTILE;
        #pragma unroll
        for (int ks = 0; ks < 4; ks++) {
            uint32_t a[4][4], b[2][4];
            #pragma unroll
            for (int mt = 0; mt < 4; mt++)
                ldsm4(a[mt][0], a[mt][1], a[mt][2], a[mt][3],
                      ba + SWZ128(aOff + mt * 2048 + ks * 32));
            #pragma unroll
            for (int np = 0; np < 2; np++)
                ldsm4(b[np][0], b[np][1], b[np][2], b[np][3],
                      bb + SWZ128(bOff + np * 2048 + ks * 32));
            #pragma unroll
            for (int mt = 0; mt < 4; mt++)
                #pragma unroll
                for (int nt = 0; nt < 4; nt++)
                    mma_tf32(acc[mt * 4 + nt], a[mt],
                             b[nt >> 1][(nt & 1) * 2], b[nt >> 1][(nt & 1) * 2 + 1]);
        }
    }

    #pragma unroll
    for (int mt = 0; mt < 4; mt++) {
        #pragma unroll
        for (int nt = 0; nt < 4; nt++) {
            const float* cc = acc[mt * 4 + nt];
            int row = m0 + wm + mt * 16 + (lane >> 2);
            int col = n0 + wn + nt * 8 + (lane & 3) * 2;
            float2 bv = *(const float2*)&bias[col];
            float2 o0 = make_float2(cc[0] + bv.x, cc[1] + bv.y);
            float2 o1 = make_float2(cc[2] + bv.x, cc[3] + bv.y);
            if (RND) {
                o0.x = tf32r(o0.x); o0.y = tf32r(o0.y);
                o1.x = tf32r(o1.x); o1.y = tf32r(o1.y);
            }
            *(float2*)&C[(size_t)row * N + col]       = o0;
            *(float2*)&C[(size_t)(row + 8) * N + col] = o1;
        }
    }
}

// ===========================================================================
// Tensor-core flash attention (R6-proven, 528us/6.9e-4):
//  - all-tf32 MMA, inputs pre-rounded, cp.async double-buffered tiles,
//    fixed-base softmax, PV A-frag via quad shuffles, V via ldmatrix on Vt
// ===========================================================================
#define ABQ 128
#define ABK 64
#define AST 68
#define AKSTG (ABK * AST)
#define AQS 0
#define AKS (ABQ * AST)
#define AVS (AKS + 2 * AKSTG)
#define AMS (AVS + 2 * AKSTG)
#define ATTN_SM_BYTES ((AMS + 2 * 64) * 4)

__global__ void __launch_bounds__(256, 2) attn_mma_kernel(
    const float* __restrict__ qkv, const float* __restrict__ vt,
    const int* __restrict__ mask, float* __restrict__ out)
{
    extern __shared__ float smf[];
    const uint32_t sb = smem_u32(smf);

    const int tid  = threadIdx.x;
    const int lane = tid & 31;
    const int w    = tid >> 5;
    const int g    = lane >> 2;
    const int q    = lane & 3;
    const int b    = blockIdx.y >> 4;
    const int h    = blockIdx.y & 15;
    const int q0   = blockIdx.x * ABQ;
    const int wq0  = w * 16;

    const size_t base = (size_t)b * LDIM * D3 + (size_t)h * DKH;
    const float* vtb  = vt + ((size_t)blockIdx.y * DKH) * LDIM;
    const int*   mkb  = mask + b * LDIM;

    for (int i = tid; i < ABQ * 16; i += 256) {
        int r = i >> 4, c4 = (i & 15) * 4;
        cp16(sb + (AQS + r * AST + c4) * 4, &qkv[base + (size_t)(q0 + r) * D3 + c4]);
    }
    #define LOAD_TILE(t, s) do {                                                     \
        int _k0 = (t) * ABK;                                                         \
        uint32_t _ks = sb + (AKS + (s) * AKSTG) * 4;                                 \
        uint32_t _vs = sb + (AVS + (s) * AKSTG) * 4;                                 \
        for (int _i = tid; _i < ABK * 16; _i += 256) {                               \
            int _r = _i >> 4, _c4 = (_i & 15) * 4;                                   \
            cp16(_ks + (_r * AST + _c4) * 4,                                         \
                 &qkv[base + (size_t)(_k0 + _r) * D3 + DMODEL + _c4]);               \
            cp16(_vs + (_r * AST + _c4) * 4,                                         \
                 &vtb[(size_t)_r * LDIM + _k0 + _c4]);                               \
        }                                                                            \
        if (tid < 16) cp16(sb + (AMS + (s) * 64 + tid * 4) * 4, &mkb[_k0 + tid * 4]);\
    } while (0)

    LOAD_TILE(0, 0);
    asm volatile("cp.async.commit_group;" ::: "memory");
    LOAD_TILE(1, 1);
    asm volatile("cp.async.commit_group;" ::: "memory");

    float O[8][4];
    #pragma unroll
    for (int t = 0; t < 8; t++)
        #pragma unroll
        for (int j = 0; j < 4; j++) O[t][j] = 0.0f;
    float lsum0 = 0.0f, lsum1 = 0.0f;

    const uint32_t aAddr = sb + (AQS + (wq0 + (lane & 15)) * AST) * 4 + ((lane >> 4) << 4);
    const uint32_t bKrow = (((lane >> 4) << 3) + (lane & 7)) * AST;
    const uint32_t bK0   = sb + (AKS + bKrow) * 4 + (((lane >> 3) & 1) << 4);
    const uint32_t bV0   = sb + (AVS + bKrow) * 4 + (((lane >> 3) & 1) << 4);

    const int NT = LDIM / ABK;   // 32
    for (int t = 0; t < NT; t++) {
        const int s = t & 1;
        if (t < NT - 1) { asm volatile("cp.async.wait_group 1;" ::: "memory"); }
        else            { asm volatile("cp.async.wait_group 0;" ::: "memory"); }
        __syncthreads();

        const uint32_t bAddrK = bK0 + s * AKSTG * 4;
        const uint32_t bAddrV = bV0 + s * AKSTG * 4;
        const int* ms = (const int*)(smf + AMS + s * 64);

        float S[8][4];
        #pragma unroll
        for (int x = 0; x < 8; x++)
            #pragma unroll
            for (int j = 0; j < 4; j++) S[x][j] = 0.0f;

        #pragma unroll
        for (int ks = 0; ks < 8; ks++) {
            uint32_t av[4];
            ldsm4(av[0], av[1], av[2], av[3], aAddr + ks * 32);
            #pragma unroll
            for (int ntp = 0; ntp < 4; ntp++) {
                uint32_t b0, b1, b2, b3;
                ldsm4(b0, b1, b2, b3, bAddrK + ntp * 16 * AST * 4 + ks * 32);
                mma_tf32(S[2 * ntp],     av, b0, b1);
                mma_tf32(S[2 * ntp + 1], av, b2, b3);
            }
        }

        #pragma unroll
        for (int nt = 0; nt < 8; nt++) {
            int2 mk = *(const int2*)&ms[nt * 8 + 2 * q];
            float p0 = mk.x ? __expf(S[nt][0] * 0.125f) : 0.0f;
            float p1 = mk.y ? __expf(S[nt][1] * 0.125f) : 0.0f;
            float p2 = mk.x ? __expf(S[nt][2] * 0.125f) : 0.0f;
            float p3 = mk.y ? __expf(S[nt][3] * 0.125f) : 0.0f;
            S[nt][0] = p0; S[nt][1] = p1; S[nt][2] = p2; S[nt][3] = p3;
            lsum0 += p0 + p1;
            lsum1 += p2 + p3;
        }

        const int srcb = lane & ~3;
        const int sl0  = srcb | (q >> 1);
        const int sl1  = sl0 + 2;
        #pragma unroll
        for (int j = 0; j < 8; j++) {
            float x00 = __shfl_sync(0xffffffffu, S[j][0], sl0);
            float x01 = __shfl_sync(0xffffffffu, S[j][1], sl0);
            float x02 = __shfl_sync(0xffffffffu, S[j][2], sl0);
            float x03 = __shfl_sync(0xffffffffu, S[j][3], sl0);
            float x10 = __shfl_sync(0xffffffffu, S[j][0], sl1);
            float x11 = __shfl_sync(0xffffffffu, S[j][1], sl1);
            float x12 = __shfl_sync(0xffffffffu, S[j][2], sl1);
            float x13 = __shfl_sync(0xffffffffu, S[j][3], sl1);
            uint32_t pa[4];
            pa[0] = __float_as_uint(tf32r((q & 1) ? x01 : x00));
            pa[1] = __float_as_uint(tf32r((q & 1) ? x03 : x02));
            pa[2] = __float_as_uint(tf32r((q & 1) ? x11 : x10));
            pa[3] = __float_as_uint(tf32r((q & 1) ? x13 : x12));

            #pragma unroll
            for (int np = 0; np < 4; np++) {
                uint32_t b0, b1, b2, b3;
                ldsm4(b0, b1, b2, b3, bAddrV + np * 16 * AST * 4 + j * 32);
                mma_tf32(O[2 * np],     pa, b0, b1);
                mma_tf32(O[2 * np + 1], pa, b2, b3);
            }
        }

        __syncthreads();
        if (t + 2 < NT) {
            LOAD_TILE(t + 2, s);
            asm volatile("cp.async.commit_group;" ::: "memory");
        }
    }

    lsum0 += __shfl_xor_sync(0xffffffffu, lsum0, 1);
    lsum0 += __shfl_xor_sync(0xffffffffu, lsum0, 2);
    lsum1 += __shfl_xor_sync(0xffffffffu, lsum1, 1);
    lsum1 += __shfl_xor_sync(0xffffffffu, lsum1, 2);
    float il0 = 1.0f / lsum0, il1 = 1.0f / lsum1;

    int row0 = q0 + wq0 + g;
    size_t o0 = ((size_t)(b * LDIM + row0)) * DMODEL + h * DKH;
    #pragma unroll
    for (int nt = 0; nt < 8; nt++) {
        int col = nt * 8 + 2 * q;
        float2 v0 = make_float2(tf32r(O[nt][0] * il0), tf32r(O[nt][1] * il0));
        float2 v1 = make_float2(tf32r(O[nt][2] * il1), tf32r(O[nt][3] * il1));
        *(float2*)&out[o0 + col]              = v0;
        *(float2*)&out[o0 + 8 * DMODEL + col] = v1;
    }
    #undef LOAD_TILE
}

// ---------------------------------------------------------------------------
// Launch
// ---------------------------------------------------------------------------
extern "C" void kernel_launch(void* const* d_in, const int* in_sizes, int n_in,
                              void* d_out, int out_size)
{
    const float* x     = (const float*)d_in[0];
    const int*   mask  = (const int*)  d_in[1];
    const float* Wqkv  = (const float*)d_in[2];
    const float* bqkv  = (const float*)d_in[3];
    const float* Wout  = (const float*)d_in[4];
    const float* bout  = (const float*)d_in[5];
    float* out = (float*)d_out;

    float *qkv, *attn, *xr, *wqkvT, *woutT, *vt;
    cudaGetSymbolAddress((void**)&qkv,   g_qkv);
    cudaGetSymbolAddress((void**)&attn,  g_attn);
    cudaGetSymbolAddress((void**)&xr,    g_x);
    cudaGetSymbolAddress((void**)&wqkvT, g_wqkvT);
    cudaGetSymbolAddress((void**)&woutT, g_woutT);
    cudaGetSymbolAddress((void**)&vt,    g_vt);

    cudaFuncSetAttribute(gemm_mma_kernel<true>,
                         cudaFuncAttributeMaxDynamicSharedMemorySize, GS_TOTAL);
    cudaFuncSetAttribute(gemm_mma_kernel<false>,
                         cudaFuncAttributeMaxDynamicSharedMemorySize, GS_TOTAL);
    cudaFuncSetAttribute(attn_mma_kernel,
                         cudaFuncAttributeMaxDynamicSharedMemorySize, ATTN_SM_BYTES);

    // Prep
    round_tf32_kernel<<<(ROWS * DMODEL / 4 + 255) / 256, 256>>>(x, xr, ROWS * DMODEL / 4);
    transpose_tf32_kernel<<<dim3(D3 / 32, GK / 32), dim3(32, 8)>>>(Wqkv, wqkvT, GK, D3);
    transpose_tf32_kernel<<<dim3(DMODEL / 32, GK / 32), dim3(32, 8)>>>(Wout, woutT, GK, DMODEL);

    // 1) QKV projection (tf32-rounded output)
    gemm_mma_kernel<true><<<dim3(D3 / 128, ROWS / 128), 256, GS_TOTAL>>>(
        xr, wqkvT, bqkv, qkv, D3);

    // 1b) V -> Vt [bh][d][L]
    vtrans_kernel<<<dim3(LDIM / 32, DKH / 32, BDIM * HEADS), dim3(32, 8)>>>(qkv, vt);

    // 2) Flash attention (all-tf32)
    attn_mma_kernel<<<dim3(LDIM / ABQ, BDIM * HEADS), 256, ATTN_SM_BYTES>>>(
        qkv, vt, mask, attn);

    // 3) Output projection (full-precision output)
    gemm_mma_kernel<false><<<dim3(DMODEL / 128, ROWS / 128), 256, GS_TOTAL>>>(
        attn, woutT, bout, out, DMODEL);
}

// round 11
// speedup vs baseline: 1.0486x; 1.0486x over previous
#include <cuda_runtime.h>
#include <math.h>
#include <stdint.h>

// Problem constants
#define BDIM   2
#define LDIM   2048
#define DMODEL 1024
#define HEADS  16
#define DKH    64
#define D3     (3 * DMODEL)
#define ROWS   (BDIM * LDIM)   // 4096
#define GK     1024            // K for both projection GEMMs

// Scratch (allocation-free: __device__ globals)
__device__ float g_qkv[(size_t)ROWS * D3];       // [B*L, 3*D], tf32-rounded values
__device__ float g_attn[(size_t)ROWS * DMODEL];  // [B,L,H,dk] (tf32-rounded)
__device__ float g_x[(size_t)ROWS * DMODEL];     // tf32-rounded x
__device__ float g_wqkvT[(size_t)D3 * GK];       // [3072][1024] k-major, tf32-rounded
__device__ float g_woutT[(size_t)DMODEL * GK];   // [1024][1024] k-major, tf32-rounded
__device__ float g_vt[(size_t)BDIM * HEADS * DKH * LDIM]; // [bh][d][L]

// ===========================================================================
// Helpers
// ===========================================================================
__device__ __forceinline__ float tf32r(float x) {
    uint32_t y;
    asm("cvt.rna.tf32.f32 %0, %1;" : "=r"(y) : "f"(x));
    return __uint_as_float(y);
}
__device__ __forceinline__ float ex2(float x) {
    float y;
    asm("ex2.approx.f32 %0, %1;" : "=f"(y) : "f"(x));
    return y;
}
__device__ __forceinline__ uint32_t smem_u32(const void* p) {
    uint32_t a;
    asm("{ .reg .u64 t; cvta.to.shared.u64 t, %1; cvt.u32.u64 %0, t; }" : "=r"(a) : "l"(p));
    return a;
}
#define SWZ128(x) ((x) ^ (((x) >> 3) & 0x70))

__device__ __forceinline__ void cp16(uint32_t dst, const void* src) {
    asm volatile("cp.async.cg.shared.global [%0], [%1], 16;" :: "r"(dst), "l"(src));
}
__device__ __forceinline__ void ldsm4(uint32_t& r0, uint32_t& r1, uint32_t& r2, uint32_t& r3,
                                      uint32_t addr) {
    asm volatile("ldmatrix.sync.aligned.m8n8.x4.shared.b16 {%0,%1,%2,%3}, [%4];"
                 : "=r"(r0), "=r"(r1), "=r"(r2), "=r"(r3) : "r"(addr));
}
__device__ __forceinline__ void mma_tf32(float* c, const uint32_t* a, uint32_t b0, uint32_t b1) {
    asm volatile("mma.sync.aligned.m16n8k8.row.col.f32.tf32.tf32.f32 "
                 "{%0,%1,%2,%3}, {%4,%5,%6,%7}, {%8,%9}, {%0,%1,%2,%3};"
                 : "+f"(c[0]), "+f"(c[1]), "+f"(c[2]), "+f"(c[3])
                 : "r"(a[0]), "r"(a[1]), "r"(a[2]), "r"(a[3]), "r"(b0), "r"(b1));
}

// ===========================================================================
// Prep kernels
// ===========================================================================
__global__ void round_tf32_kernel(const float* __restrict__ in, float* __restrict__ out, int n4) {
    int i = blockIdx.x * blockDim.x + threadIdx.x;
    if (i < n4) {
        float4 v = ((const float4*)in)[i];
        v.x = tf32r(v.x); v.y = tf32r(v.y); v.z = tf32r(v.z); v.w = tf32r(v.w);
        ((float4*)out)[i] = v;
    }
}

// in [K][N] row-major -> out [N][K] row-major, tf32-rounded. block (32,8)
__global__ void transpose_tf32_kernel(const float* __restrict__ in, float* __restrict__ out,
                                      int K, int N) {
    __shared__ float t[32][33];
    int n0 = blockIdx.x * 32, k0 = blockIdx.y * 32;
    for (int j = threadIdx.y; j < 32; j += 8)
        t[j][threadIdx.x] = tf32r(in[(size_t)(k0 + j) * N + n0 + threadIdx.x]);
    __syncthreads();
    for (int j = threadIdx.y; j < 32; j += 8)
        out[(size_t)(n0 + j) * K + k0 + threadIdx.x] = t[threadIdx.x][j];
}

// Transpose the V third of qkv (already tf32-rounded) into [bh][d=64][L].
__global__ void vtrans_kernel(const float* __restrict__ qkv, float* __restrict__ vt) {
    __shared__ float t[32][33];
    int l0 = blockIdx.x * 32, d0 = blockIdx.y * 32;
    int bh = blockIdx.z;
    int b  = bh >> 4, h = bh & 15;
    const float* src = qkv + (size_t)b * LDIM * D3 + 2 * DMODEL + h * DKH;
    for (int j = threadIdx.y; j < 32; j += 8)
        t[j][threadIdx.x] = src[(size_t)(l0 + j) * D3 + d0 + threadIdx.x];
    __syncthreads();
    float* dst = vt + ((size_t)bh * DKH) * LDIM;
    for (int j = threadIdx.y; j < 32; j += 8)
        dst[(size_t)(d0 + j) * LDIM + l0 + threadIdx.x] = t[threadIdx.x][j];
}

// ===========================================================================
// tf32 mma.sync GEMM: C[M,N] = A[M,K] @ Bt[N,K]^T + bias[N]
// 3-stage cp.async pipeline, ONE __syncthreads per K-chunk.  (R9-validated)
// ===========================================================================
#define GBK    32
#define GTILE  (128 * GBK * 4)          // 16KB per operand tile
#define GSTG   3
#define GS_TOTAL (GSTG * 2 * GTILE)     // 96KB

__device__ __forceinline__ void gemm_load_tile(const float* __restrict__ src, int row0, int k0,
                                               uint32_t smemBase, int tid) {
    #pragma unroll
    for (int j = 0; j < 4; j++) {
        int i   = tid + j * 256;
        int row = i >> 3;
        int c   = i & 7;
        cp16(smemBase + SWZ128(row * 128 + c * 16),
             src + (size_t)(row0 + row) * GK + k0 + c * 4);
    }
}

template<bool RND>
__global__ __launch_bounds__(256) void gemm_mma_kernel(
    const float* __restrict__ A, const float* __restrict__ Bt,
    const float* __restrict__ bias, float* __restrict__ C, int N)
{
    extern __shared__ char smc[];
    const uint32_t sb = smem_u32(smc);
    const int tid  = threadIdx.x;
    const int lane = tid & 31;
    const int w    = tid >> 5;
    const int m0   = blockIdx.y * 128;
    const int n0   = blockIdx.x * 128;
    const int wm   = (w & 1) * 64;
    const int wn   = (w >> 1) * 32;

    const int aOff = (wm + (lane & 15)) * 128 + ((lane >> 4) << 4);
    const int bOff = (wn + ((lane >> 4) << 3) + (lane & 7)) * 128 + (((lane >> 3) & 1) << 4);

    float acc[16][4];
    #pragma unroll
    for (int t = 0; t < 16; t++)
        #pragma unroll
        for (int j = 0; j < 4; j++) acc[t][j] = 0.0f;

    gemm_load_tile(A,  m0, 0, sb, tid);
    gemm_load_tile(Bt, n0, 0, sb + GTILE, tid);
    asm volatile("cp.async.commit_group;" ::: "memory");
    gemm_load_tile(A,  m0, GBK, sb + 2 * GTILE, tid);
    gemm_load_tile(Bt, n0, GBK, sb + 3 * GTILE, tid);
    asm volatile("cp.async.commit_group;" ::: "memory");

    const int NCHUNK = GK / GBK;   // 32
    for (int c = 0; c < NCHUNK; c++) {
        if (c < NCHUNK - 1) { asm volatile("cp.async.wait_group 1;" ::: "memory"); }
        else                { asm volatile("cp.async.wait_group 0;" ::: "memory"); }
        __syncthreads();

        if (c + 2 < NCHUNK) {
            const uint32_t sp = sb + ((c + 2) % GSTG) * 2 * GTILE;
            gemm_load_tile(A,  m0, (c + 2) * GBK, sp, tid);
            gemm_load_tile(Bt, n0, (c + 2) * GBK, sp + GTILE, tid);
            asm volatile("cp.async.commit_group;" ::: "memory");
        }

        const uint32_t ba = sb + (c % GSTG) * 2 * GTILE;
        const uint32_t bb = ba + GTILE;
        #pragma unroll
        for (int ks = 0; ks < 4; ks++) {
            uint32_t a[4][4], b[2][4];
            #pragma unroll
            for (int mt = 0; mt < 4; mt++)
                ldsm4(a[mt][0], a[mt][1], a[mt][2], a[mt][3],
                      ba + SWZ128(aOff + mt * 2048 + ks * 32));
            #pragma unroll
            for (int np = 0; np < 2; np++)
                ldsm4(b[np][0], b[np][1], b[np][2], b[np][3],
                      bb + SWZ128(bOff + np * 2048 + ks * 32));
            #pragma unroll
            for (int mt = 0; mt < 4; mt++)
                #pragma unroll
                for (int nt = 0; nt < 4; nt++)
                    mma_tf32(acc[mt * 4 + nt], a[mt],
                             b[nt >> 1][(nt & 1) * 2], b[nt >> 1][(nt & 1) * 2 + 1]);
        }
    }

    #pragma unroll
    for (int mt = 0; mt < 4; mt++) {
        #pragma unroll
        for (int nt = 0; nt < 4; nt++) {
            const float* cc = acc[mt * 4 + nt];
            int row = m0 + wm + mt * 16 + (lane >> 2);
            int col = n0 + wn + nt * 8 + (lane & 3) * 2;
            float2 bv = *(const float2*)&bias[col];
            float2 o0 = make_float2(cc[0] + bv.x, cc[1] + bv.y);
            float2 o1 = make_float2(cc[2] + bv.x, cc[3] + bv.y);
            if (RND) {
                o0.x = tf32r(o0.x); o0.y = tf32r(o0.y);
                o1.x = tf32r(o1.x); o1.y = tf32r(o1.y);
            }
            *(float2*)&C[(size_t)row * N + col]       = o0;
            *(float2*)&C[(size_t)(row + 8) * N + col] = o1;
        }
    }
}

// ===========================================================================
// Tensor-core flash attention (all-tf32 core, R6-proven), with:
//  - mask folded into S accumulator init (mask ? 0 : -3e38); ex2(-big) = 0
//  - exp via single ex2 with merged constant (0.125 * log2 e)
// ===========================================================================
#define ABQ 128
#define ABK 64
#define AST 68
#define AKSTG (ABK * AST)
#define AQS 0
#define AKS (ABQ * AST)
#define AVS (AKS + 2 * AKSTG)
#define AMS (AVS + 2 * AKSTG)
#define ATTN_SM_BYTES ((AMS + 2 * 64) * 4)
#define EXPC 0.18033688011112042f   // 0.125 * log2(e)

__global__ void __launch_bounds__(256, 2) attn_mma_kernel(
    const float* __restrict__ qkv, const float* __restrict__ vt,
    const int* __restrict__ mask, float* __restrict__ out)
{
    extern __shared__ float smf[];
    const uint32_t sb = smem_u32(smf);

    const int tid  = threadIdx.x;
    const int lane = tid & 31;
    const int w    = tid >> 5;
    const int g    = lane >> 2;
    const int q    = lane & 3;
    const int b    = blockIdx.y >> 4;
    const int h    = blockIdx.y & 15;
    const int q0   = blockIdx.x * ABQ;
    const int wq0  = w * 16;

    const size_t base = (size_t)b * LDIM * D3 + (size_t)h * DKH;
    const float* vtb  = vt + ((size_t)blockIdx.y * DKH) * LDIM;
    const int*   mkb  = mask + b * LDIM;

    for (int i = tid; i < ABQ * 16; i += 256) {
        int r = i >> 4, c4 = (i & 15) * 4;
        cp16(sb + (AQS + r * AST + c4) * 4, &qkv[base + (size_t)(q0 + r) * D3 + c4]);
    }
    #define LOAD_TILE(t, s) do {                                                     \
        int _k0 = (t) * ABK;                                                         \
        uint32_t _ks = sb + (AKS + (s) * AKSTG) * 4;                                 \
        uint32_t _vs = sb + (AVS + (s) * AKSTG) * 4;                                 \
        for (int _i = tid; _i < ABK * 16; _i += 256) {                               \
            int _r = _i >> 4, _c4 = (_i & 15) * 4;                                   \
            cp16(_ks + (_r * AST + _c4) * 4,                                         \
                 &qkv[base + (size_t)(_k0 + _r) * D3 + DMODEL + _c4]);               \
            cp16(_vs + (_r * AST + _c4) * 4,                                         \
                 &vtb[(size_t)_r * LDIM + _k0 + _c4]);                               \
        }                                                                            \
        if (tid < 16) cp16(sb + (AMS + (s) * 64 + tid * 4) * 4, &mkb[_k0 + tid * 4]);\
    } while (0)

    LOAD_TILE(0, 0);
    asm volatile("cp.async.commit_group;" ::: "memory");
    LOAD_TILE(1, 1);
    asm volatile("cp.async.commit_group;" ::: "memory");

    float O[8][4];
    #pragma unroll
    for (int t = 0; t < 8; t++)
        #pragma unroll
        for (int j = 0; j < 4; j++) O[t][j] = 0.0f;
    float lsum0 = 0.0f, lsum1 = 0.0f;

    const uint32_t aAddr = sb + (AQS + (wq0 + (lane & 15)) * AST) * 4 + ((lane >> 4) << 4);
    const uint32_t bKrow = (((lane >> 4) << 3) + (lane & 7)) * AST;
    const uint32_t bK0   = sb + (AKS + bKrow) * 4 + (((lane >> 3) & 1) << 4);
    const uint32_t bV0   = sb + (AVS + bKrow) * 4 + (((lane >> 3) & 1) << 4);

    const int NT = LDIM / ABK;   // 32
    for (int t = 0; t < NT; t++) {
        const int s = t & 1;
        if (t < NT - 1) { asm volatile("cp.async.wait_group 1;" ::: "memory"); }
        else            { asm volatile("cp.async.wait_group 0;" ::: "memory"); }
        __syncthreads();

        const uint32_t bAddrK = bK0 + s * AKSTG * 4;
        const uint32_t bAddrV = bV0 + s * AKSTG * 4;
        const int* ms = (const int*)(smf + AMS + s * 64);

        // ---- S init = mask bias (masked -> -3e38; exp2 drives it to 0) ----
        float S[8][4];
        #pragma unroll
        for (int nt = 0; nt < 8; nt++) {
            int2 mk = *(const int2*)&ms[nt * 8 + 2 * q];
            float bx = mk.x ? 0.0f : -3.0e38f;
            float by = mk.y ? 0.0f : -3.0e38f;
            S[nt][0] = bx; S[nt][1] = by; S[nt][2] = bx; S[nt][3] = by;
        }

        // ---- S += Q K^T (tf32) ----
        #pragma unroll
        for (int ks = 0; ks < 8; ks++) {
            uint32_t av[4];
            ldsm4(av[0], av[1], av[2], av[3], aAddr + ks * 32);
            #pragma unroll
            for (int ntp = 0; ntp < 4; ntp++) {
                uint32_t b0, b1, b2, b3;
                ldsm4(b0, b1, b2, b3, bAddrK + ntp * 16 * AST * 4 + ks * 32);
                mma_tf32(S[2 * ntp],     av, b0, b1);
                mma_tf32(S[2 * ntp + 1], av, b2, b3);
            }
        }

        // ---- P = exp2(S * 0.125*log2e); masked entries -> exactly 0 ----
        #pragma unroll
        for (int nt = 0; nt < 8; nt++) {
            float p0 = ex2(S[nt][0] * EXPC);
            float p1 = ex2(S[nt][1] * EXPC);
            float p2 = ex2(S[nt][2] * EXPC);
            float p3 = ex2(S[nt][3] * EXPC);
            S[nt][0] = p0; S[nt][1] = p1; S[nt][2] = p2; S[nt][3] = p3;
            lsum0 += p0 + p1;
            lsum1 += p2 + p3;
        }

        // ---- O += P V : A-frag via quad shuffles, B-frag via ldmatrix on Vt ----
        const int srcb = lane & ~3;
        const int sl0  = srcb | (q >> 1);
        const int sl1  = sl0 + 2;
        #pragma unroll
        for (int j = 0; j < 8; j++) {
            float x00 = __shfl_sync(0xffffffffu, S[j][0], sl0);
            float x01 = __shfl_sync(0xffffffffu, S[j][1], sl0);
            float x02 = __shfl_sync(0xffffffffu, S[j][2], sl0);
            float x03 = __shfl_sync(0xffffffffu, S[j][3], sl0);
            float x10 = __shfl_sync(0xffffffffu, S[j][0], sl1);
            float x11 = __shfl_sync(0xffffffffu, S[j][1], sl1);
            float x12 = __shfl_sync(0xffffffffu, S[j][2], sl1);
            float x13 = __shfl_sync(0xffffffffu, S[j][3], sl1);
            uint32_t pa[4];
            pa[0] = __float_as_uint(tf32r((q & 1) ? x01 : x00));
            pa[1] = __float_as_uint(tf32r((q & 1) ? x03 : x02));
            pa[2] = __float_as_uint(tf32r((q & 1) ? x11 : x10));
            pa[3] = __float_as_uint(tf32r((q & 1) ? x13 : x12));

            #pragma unroll
            for (int np = 0; np < 4; np++) {
                uint32_t b0, b1, b2, b3;
                ldsm4(b0, b1, b2, b3, bAddrV + np * 16 * AST * 4 + j * 32);
                mma_tf32(O[2 * np],     pa, b0, b1);
                mma_tf32(O[2 * np + 1], pa, b2, b3);
            }
        }

        __syncthreads();
        if (t + 2 < NT) {
            LOAD_TILE(t + 2, s);
            asm volatile("cp.async.commit_group;" ::: "memory");
        }
    }

    lsum0 += __shfl_xor_sync(0xffffffffu, lsum0, 1);
    lsum0 += __shfl_xor_sync(0xffffffffu, lsum0, 2);
    lsum1 += __shfl_xor_sync(0xffffffffu, lsum1, 1);
    lsum1 += __shfl_xor_sync(0xffffffffu, lsum1, 2);
    float il0 = 1.0f / lsum0, il1 = 1.0f / lsum1;

    int row0 = q0 + wq0 + g;
    size_t o0 = ((size_t)(b * LDIM + row0)) * DMODEL + h * DKH;
    #pragma unroll
    for (int nt = 0; nt < 8; nt++) {
        int col = nt * 8 + 2 * q;
        float2 v0 = make_float2(tf32r(O[nt][0] * il0), tf32r(O[nt][1] * il0));
        float2 v1 = make_float2(tf32r(O[nt][2] * il1), tf32r(O[nt][3] * il1));
        *(float2*)&out[o0 + col]              = v0;
        *(float2*)&out[o0 + 8 * DMODEL + col] = v1;
    }
    #undef LOAD_TILE
}

// ---------------------------------------------------------------------------
// Launch
// ---------------------------------------------------------------------------
extern "C" void kernel_launch(void* const* d_in, const int* in_sizes, int n_in,
                              void* d_out, int out_size)
{
    const float* x     = (const float*)d_in[0];
    const int*   mask  = (const int*)  d_in[1];
    const float* Wqkv  = (const float*)d_in[2];
    const float* bqkv  = (const float*)d_in[3];
    const float* Wout  = (const float*)d_in[4];
    const float* bout  = (const float*)d_in[5];
    float* out = (float*)d_out;

    float *qkv, *attn, *xr, *wqkvT, *woutT, *vt;
    cudaGetSymbolAddress((void**)&qkv,   g_qkv);
    cudaGetSymbolAddress((void**)&attn,  g_attn);
    cudaGetSymbolAddress((void**)&xr,    g_x);
    cudaGetSymbolAddress((void**)&wqkvT, g_wqkvT);
    cudaGetSymbolAddress((void**)&woutT, g_woutT);
    cudaGetSymbolAddress((void**)&vt,    g_vt);

    cudaFuncSetAttribute(gemm_mma_kernel<true>,
                         cudaFuncAttributeMaxDynamicSharedMemorySize, GS_TOTAL);
    cudaFuncSetAttribute(gemm_mma_kernel<false>,
                         cudaFuncAttributeMaxDynamicSharedMemorySize, GS_TOTAL);
    cudaFuncSetAttribute(attn_mma_kernel,
                         cudaFuncAttributeMaxDynamicSharedMemorySize, ATTN_SM_BYTES);

    // Prep
    round_tf32_kernel<<<(ROWS * DMODEL / 4 + 255) / 256, 256>>>(x, xr, ROWS * DMODEL / 4);
    transpose_tf32_kernel<<<dim3(D3 / 32, GK / 32), dim3(32, 8)>>>(Wqkv, wqkvT, GK, D3);
    transpose_tf32_kernel<<<dim3(DMODEL / 32, GK / 32), dim3(32, 8)>>>(Wout, woutT, GK, DMODEL);

    // 1) QKV projection (tf32-rounded output)
    gemm_mma_kernel<true><<<dim3(D3 / 128, ROWS / 128), 256, GS_TOTAL>>>(
        xr, wqkvT, bqkv, qkv, D3);

    // 1b) V -> Vt [bh][d][L]
    vtrans_kernel<<<dim3(LDIM / 32, DKH / 32, BDIM * HEADS), dim3(32, 8)>>>(qkv, vt);

    // 2) Flash attention (all-tf32)
    attn_mma_kernel<<<dim3(LDIM / ABQ, BDIM * HEADS), 256, ATTN_SM_BYTES>>>(
        qkv, vt, mask, attn);

    // 3) Output projection (full-precision output)
    gemm_mma_kernel<false><<<dim3(DMODEL / 128, ROWS / 128), 256, GS_TOTAL>>>(
        attn, woutT, bout, out, DMODEL);
}

// round 12
// speedup vs baseline: 1.1123x; 1.0608x over previous
#include <cuda_runtime.h>
#include <math.h>
#include <stdint.h>

// Problem constants
#define BDIM   2
#define LDIM   2048
#define DMODEL 1024
#define HEADS  16
#define DKH    64
#define D3     (3 * DMODEL)
#define ROWS   (BDIM * LDIM)   // 4096
#define GK     1024            // K for both projection GEMMs

// Scratch (allocation-free: __device__ globals)
__device__ float g_qkv[(size_t)ROWS * D3];       // [B*L, 3*D], tf32-rounded values
__device__ float g_attn[(size_t)ROWS * DMODEL];  // [B,L,H,dk] (tf32-rounded)
__device__ float g_x[(size_t)ROWS * DMODEL];     // tf32-rounded x
__device__ float g_wqkvT[(size_t)D3 * GK];       // [3072][1024] k-major, tf32-rounded
__device__ float g_woutT[(size_t)DMODEL * GK];   // [1024][1024] k-major, tf32-rounded
__device__ float g_vt[(size_t)BDIM * HEADS * DKH * LDIM]; // [bh][d][L]

// ===========================================================================
// Helpers
// ===========================================================================
__device__ __forceinline__ float tf32r(float x) {
    uint32_t y;
    asm("cvt.rna.tf32.f32 %0, %1;" : "=r"(y) : "f"(x));
    return __uint_as_float(y);
}
__device__ __forceinline__ float ex2(float x) {
    float y;
    asm("ex2.approx.f32 %0, %1;" : "=f"(y) : "f"(x));
    return y;
}
__device__ __forceinline__ uint32_t smem_u32(const void* p) {
    uint32_t a;
    asm("{ .reg .u64 t; cvta.to.shared.u64 t, %1; cvt.u32.u64 %0, t; }" : "=r"(a) : "l"(p));
    return a;
}
#define SWZ128(x) ((x) ^ (((x) >> 3) & 0x70))

__device__ __forceinline__ void cp16(uint32_t dst, const void* src) {
    asm volatile("cp.async.cg.shared.global [%0], [%1], 16;" :: "r"(dst), "l"(src));
}
__device__ __forceinline__ void ldsm4(uint32_t& r0, uint32_t& r1, uint32_t& r2, uint32_t& r3,
                                      uint32_t addr) {
    asm volatile("ldmatrix.sync.aligned.m8n8.x4.shared.b16 {%0,%1,%2,%3}, [%4];"
                 : "=r"(r0), "=r"(r1), "=r"(r2), "=r"(r3) : "r"(addr));
}
__device__ __forceinline__ void mma_tf32(float* c, const uint32_t* a, uint32_t b0, uint32_t b1) {
    asm volatile("mma.sync.aligned.m16n8k8.row.col.f32.tf32.tf32.f32 "
                 "{%0,%1,%2,%3}, {%4,%5,%6,%7}, {%8,%9}, {%0,%1,%2,%3};"
                 : "+f"(c[0]), "+f"(c[1]), "+f"(c[2]), "+f"(c[3])
                 : "r"(a[0]), "r"(a[1]), "r"(a[2]), "r"(a[3]), "r"(b0), "r"(b1));
}

// ===========================================================================
// Prep kernels (unchanged)
// ===========================================================================
__global__ void round_tf32_kernel(const float* __restrict__ in, float* __restrict__ out, int n4) {
    int i = blockIdx.x * blockDim.x + threadIdx.x;
    if (i < n4) {
        float4 v = ((const float4*)in)[i];
        v.x = tf32r(v.x); v.y = tf32r(v.y); v.z = tf32r(v.z); v.w = tf32r(v.w);
        ((float4*)out)[i] = v;
    }
}

__global__ void transpose_tf32_kernel(const float* __restrict__ in, float* __restrict__ out,
                                      int K, int N) {
    __shared__ float t[32][33];
    int n0 = blockIdx.x * 32, k0 = blockIdx.y * 32;
    for (int j = threadIdx.y; j < 32; j += 8)
        t[j][threadIdx.x] = tf32r(in[(size_t)(k0 + j) * N + n0 + threadIdx.x]);
    __syncthreads();
    for (int j = threadIdx.y; j < 32; j += 8)
        out[(size_t)(n0 + j) * K + k0 + threadIdx.x] = t[threadIdx.x][j];
}

__global__ void vtrans_kernel(const float* __restrict__ qkv, float* __restrict__ vt) {
    __shared__ float t[32][33];
    int l0 = blockIdx.x * 32, d0 = blockIdx.y * 32;
    int bh = blockIdx.z;
    int b  = bh >> 4, h = bh & 15;
    const float* src = qkv + (size_t)b * LDIM * D3 + 2 * DMODEL + h * DKH;
    for (int j = threadIdx.y; j < 32; j += 8)
        t[j][threadIdx.x] = src[(size_t)(l0 + j) * D3 + d0 + threadIdx.x];
    __syncthreads();
    float* dst = vt + ((size_t)bh * DKH) * LDIM;
    for (int j = threadIdx.y; j < 32; j += 8)
        dst[(size_t)(d0 + j) * LDIM + l0 + threadIdx.x] = t[threadIdx.x][j];
}

// ===========================================================================
// tf32 mma.sync GEMM: 128 threads, 4 warps of 64x64 (2x smem reuse).
// 3-stage cp.async pipeline, one __syncthreads per K-chunk.
// ===========================================================================
#define GBK    32
#define GTILE  (128 * GBK * 4)          // 16KB per operand tile
#define GSTG   3
#define GS_TOTAL (GSTG * 2 * GTILE)     // 96KB

__device__ __forceinline__ void gemm_load_tile(const float* __restrict__ src, int row0, int k0,
                                               uint32_t smemBase, int tid) {
    #pragma unroll
    for (int j = 0; j < 8; j++) {
        int i   = tid + j * 128;
        int row = i >> 3;
        int c   = i & 7;
        cp16(smemBase + SWZ128(row * 128 + c * 16),
             src + (size_t)(row0 + row) * GK + k0 + c * 4);
    }
}

template<bool RND>
__global__ __launch_bounds__(128, 2) void gemm_mma_kernel(
    const float* __restrict__ A, const float* __restrict__ Bt,
    const float* __restrict__ bias, float* __restrict__ C, int N)
{
    extern __shared__ char smc[];
    const uint32_t sb = smem_u32(smc);
    const int tid  = threadIdx.x;
    const int lane = tid & 31;
    const int w    = tid >> 5;      // 0..3
    const int m0   = blockIdx.y * 128;
    const int n0   = blockIdx.x * 128;
    const int wm   = (w & 1) * 64;
    const int wn   = (w >> 1) * 64;

    const int aOff = (wm + (lane & 15)) * 128 + ((lane >> 4) << 4);
    const int bOff = (wn + ((lane >> 4) << 3) + (lane & 7)) * 128 + (((lane >> 3) & 1) << 4);

    float acc[32][4];
    #pragma unroll
    for (int t = 0; t < 32; t++)
        #pragma unroll
        for (int j = 0; j < 4; j++) acc[t][j] = 0.0f;

    gemm_load_tile(A,  m0, 0, sb, tid);
    gemm_load_tile(Bt, n0, 0, sb + GTILE, tid);
    asm volatile("cp.async.commit_group;" ::: "memory");
    gemm_load_tile(A,  m0, GBK, sb + 2 * GTILE, tid);
    gemm_load_tile(Bt, n0, GBK, sb + 3 * GTILE, tid);
    asm volatile("cp.async.commit_group;" ::: "memory");

    const int NCHUNK = GK / GBK;   // 32
    for (int c = 0; c < NCHUNK; c++) {
        if (c < NCHUNK - 1) { asm volatile("cp.async.wait_group 1;" ::: "memory"); }
        else                { asm volatile("cp.async.wait_group 0;" ::: "memory"); }
        __syncthreads();

        if (c + 2 < NCHUNK) {
            const uint32_t sp = sb + ((c + 2) % GSTG) * 2 * GTILE;
            gemm_load_tile(A,  m0, (c + 2) * GBK, sp, tid);
            gemm_load_tile(Bt, n0, (c + 2) * GBK, sp + GTILE, tid);
            asm volatile("cp.async.commit_group;" ::: "memory");
        }

        const uint32_t ba = sb + (c % GSTG) * 2 * GTILE;
        const uint32_t bb = ba + GTILE;
        #pragma unroll
        for (int ks = 0; ks < 4; ks++) {
            uint32_t a[4][4], b[4][4];
            #pragma unroll
            for (int mt = 0; mt < 4; mt++)
                ldsm4(a[mt][0], a[mt][1], a[mt][2], a[mt][3],
                      ba + SWZ128(aOff + mt * 2048 + ks * 32));
            #pragma unroll
            for (int np = 0; np < 4; np++)
                ldsm4(b[np][0], b[np][1], b[np][2], b[np][3],
                      bb + SWZ128(bOff + np * 2048 + ks * 32));
            #pragma unroll
            for (int mt = 0; mt < 4; mt++)
                #pragma unroll
                for (int nt = 0; nt < 8; nt++)
                    mma_tf32(acc[mt * 8 + nt], a[mt],
                             b[nt >> 1][(nt & 1) * 2], b[nt >> 1][(nt & 1) * 2 + 1]);
        }
    }

    #pragma unroll
    for (int mt = 0; mt < 4; mt++) {
        #pragma unroll
        for (int nt = 0; nt < 8; nt++) {
            const float* cc = acc[mt * 8 + nt];
            int row = m0 + wm + mt * 16 + (lane >> 2);
            int col = n0 + wn + nt * 8 + (lane & 3) * 2;
            float2 bv = *(const float2*)&bias[col];
            float2 o0 = make_float2(cc[0] + bv.x, cc[1] + bv.y);
            float2 o1 = make_float2(cc[2] + bv.x, cc[3] + bv.y);
            if (RND) {
                o0.x = tf32r(o0.x); o0.y = tf32r(o0.y);
                o1.x = tf32r(o1.x); o1.y = tf32r(o1.y);
            }
            *(float2*)&C[(size_t)row * N + col]       = o0;
            *(float2*)&C[(size_t)(row + 8) * N + col] = o1;
        }
    }
}

// ===========================================================================
// Tensor-core flash attention: 128 threads, 4 warps of 32 q-rows (2x reuse).
// All-tf32 MMA core; mask folded into S init; single-ex2 softmax.
// Smem layout identical to R11 (105 KB, 2 CTA/SM).
// ===========================================================================
#define ABQ 128
#define ABK 64
#define AST 68
#define AKSTG (ABK * AST)
#define AQS 0
#define AKS (ABQ * AST)
#define AVS (AKS + 2 * AKSTG)
#define AMS (AVS + 2 * AKSTG)
#define ATTN_SM_BYTES ((AMS + 2 * 64) * 4)
#define EXPC 0.18033688011112042f   // 0.125 * log2(e)

__global__ void __launch_bounds__(128, 2) attn_mma_kernel(
    const float* __restrict__ qkv, const float* __restrict__ vt,
    const int* __restrict__ mask, float* __restrict__ out)
{
    extern __shared__ float smf[];
    const uint32_t sb = smem_u32(smf);

    const int tid  = threadIdx.x;
    const int lane = tid & 31;
    const int w    = tid >> 5;      // 0..3
    const int g    = lane >> 2;
    const int q    = lane & 3;
    const int b    = blockIdx.y >> 4;
    const int h    = blockIdx.y & 15;
    const int q0   = blockIdx.x * ABQ;
    const int wq0  = w * 32;        // 32 q-rows per warp

    const size_t base = (size_t)b * LDIM * D3 + (size_t)h * DKH;
    const float* vtb  = vt + ((size_t)blockIdx.y * DKH) * LDIM;
    const int*   mkb  = mask + b * LDIM;

    for (int i = tid; i < ABQ * 16; i += 128) {
        int r = i >> 4, c4 = (i & 15) * 4;
        cp16(sb + (AQS + r * AST + c4) * 4, &qkv[base + (size_t)(q0 + r) * D3 + c4]);
    }
    #define LOAD_TILE(t, s) do {                                                     \
        int _k0 = (t) * ABK;                                                         \
        uint32_t _ks = sb + (AKS + (s) * AKSTG) * 4;                                 \
        uint32_t _vs = sb + (AVS + (s) * AKSTG) * 4;                                 \
        for (int _i = tid; _i < ABK * 16; _i += 128) {                               \
            int _r = _i >> 4, _c4 = (_i & 15) * 4;                                   \
            cp16(_ks + (_r * AST + _c4) * 4,                                         \
                 &qkv[base + (size_t)(_k0 + _r) * D3 + DMODEL + _c4]);               \
            cp16(_vs + (_r * AST + _c4) * 4,                                         \
                 &vtb[(size_t)_r * LDIM + _k0 + _c4]);                               \
        }                                                                            \
        if (tid < 16) cp16(sb + (AMS + (s) * 64 + tid * 4) * 4, &mkb[_k0 + tid * 4]);\
    } while (0)

    LOAD_TILE(0, 0);
    asm volatile("cp.async.commit_group;" ::: "memory");
    LOAD_TILE(1, 1);
    asm volatile("cp.async.commit_group;" ::: "memory");

    float O[2][8][4];
    #pragma unroll
    for (int mt = 0; mt < 2; mt++)
        #pragma unroll
        for (int t = 0; t < 8; t++)
            #pragma unroll
            for (int j = 0; j < 4; j++) O[mt][t][j] = 0.0f;
    float lsum[2][2] = {{0.0f, 0.0f}, {0.0f, 0.0f}};

    const uint32_t aAddr = sb + (AQS + (wq0 + (lane & 15)) * AST) * 4 + ((lane >> 4) << 4);
    const uint32_t bKrow = (((lane >> 4) << 3) + (lane & 7)) * AST;
    const uint32_t bK0   = sb + (AKS + bKrow) * 4 + (((lane >> 3) & 1) << 4);
    const uint32_t bV0   = sb + (AVS + bKrow) * 4 + (((lane >> 3) & 1) << 4);

    const int NT = LDIM / ABK;   // 32
    for (int t = 0; t < NT; t++) {
        const int s = t & 1;
        if (t < NT - 1) { asm volatile("cp.async.wait_group 1;" ::: "memory"); }
        else            { asm volatile("cp.async.wait_group 0;" ::: "memory"); }
        __syncthreads();

        const uint32_t bAddrK = bK0 + s * AKSTG * 4;
        const uint32_t bAddrV = bV0 + s * AKSTG * 4;
        const int* ms = (const int*)(smf + AMS + s * 64);

        // ---- S init = mask bias (masked -> -3e38; ex2 drives to 0) ----
        float S[2][8][4];
        #pragma unroll
        for (int nt = 0; nt < 8; nt++) {
            int2 mk = *(const int2*)&ms[nt * 8 + 2 * q];
            float bx = mk.x ? 0.0f : -3.0e38f;
            float by = mk.y ? 0.0f : -3.0e38f;
            S[0][nt][0] = bx; S[0][nt][1] = by; S[0][nt][2] = bx; S[0][nt][3] = by;
            S[1][nt][0] = bx; S[1][nt][1] = by; S[1][nt][2] = bx; S[1][nt][3] = by;
        }

        // ---- S += Q K^T (tf32); two 16-row halves share each K ldsm ----
        #pragma unroll
        for (int ks = 0; ks < 8; ks++) {
            uint32_t av0[4], av1[4];
            ldsm4(av0[0], av0[1], av0[2], av0[3], aAddr + ks * 32);
            ldsm4(av1[0], av1[1], av1[2], av1[3], aAddr + 16 * AST * 4 + ks * 32);
            #pragma unroll
            for (int ntp = 0; ntp < 4; ntp++) {
                uint32_t b0, b1, b2, b3;
                ldsm4(b0, b1, b2, b3, bAddrK + ntp * 16 * AST * 4 + ks * 32);
                mma_tf32(S[0][2 * ntp],     av0, b0, b1);
                mma_tf32(S[0][2 * ntp + 1], av0, b2, b3);
                mma_tf32(S[1][2 * ntp],     av1, b0, b1);
                mma_tf32(S[1][2 * ntp + 1], av1, b2, b3);
            }
        }

        // ---- P = exp2(S * 0.125*log2e) ----
        #pragma unroll
        for (int mt = 0; mt < 2; mt++)
            #pragma unroll
            for (int nt = 0; nt < 8; nt++) {
                float p0 = ex2(S[mt][nt][0] * EXPC);
                float p1 = ex2(S[mt][nt][1] * EXPC);
                float p2 = ex2(S[mt][nt][2] * EXPC);
                float p3 = ex2(S[mt][nt][3] * EXPC);
                S[mt][nt][0] = p0; S[mt][nt][1] = p1;
                S[mt][nt][2] = p2; S[mt][nt][3] = p3;
                lsum[mt][0] += p0 + p1;
                lsum[mt][1] += p2 + p3;
            }

        // ---- O += P V : V ldsm shared across both 16-row halves ----
        const int srcb = lane & ~3;
        const int sl0  = srcb | (q >> 1);
        const int sl1  = sl0 + 2;
        #pragma unroll
        for (int j = 0; j < 8; j++) {
            uint32_t pa[2][4];
            #pragma unroll
            for (int mt = 0; mt < 2; mt++) {
                float x00 = __shfl_sync(0xffffffffu, S[mt][j][0], sl0);
                float x01 = __shfl_sync(0xffffffffu, S[mt][j][1], sl0);
                float x02 = __shfl_sync(0xffffffffu, S[mt][j][2], sl0);
                float x03 = __shfl_sync(0xffffffffu, S[mt][j][3], sl0);
                float x10 = __shfl_sync(0xffffffffu, S[mt][j][0], sl1);
                float x11 = __shfl_sync(0xffffffffu, S[mt][j][1], sl1);
                float x12 = __shfl_sync(0xffffffffu, S[mt][j][2], sl1);
                float x13 = __shfl_sync(0xffffffffu, S[mt][j][3], sl1);
                pa[mt][0] = __float_as_uint(tf32r((q & 1) ? x01 : x00));
                pa[mt][1] = __float_as_uint(tf32r((q & 1) ? x03 : x02));
                pa[mt][2] = __float_as_uint(tf32r((q & 1) ? x11 : x10));
                pa[mt][3] = __float_as_uint(tf32r((q & 1) ? x13 : x12));
            }
            #pragma unroll
            for (int np = 0; np < 4; np++) {
                uint32_t b0, b1, b2, b3;
                ldsm4(b0, b1, b2, b3, bAddrV + np * 16 * AST * 4 + j * 32);
                mma_tf32(O[0][2 * np],     pa[0], b0, b1);
                mma_tf32(O[0][2 * np + 1], pa[0], b2, b3);
                mma_tf32(O[1][2 * np],     pa[1], b0, b1);
                mma_tf32(O[1][2 * np + 1], pa[1], b2, b3);
            }
        }

        __syncthreads();
        if (t + 2 < NT) {
            LOAD_TILE(t + 2, s);
            asm volatile("cp.async.commit_group;" ::: "memory");
        }
    }

    // ---- row-sum reduce + epilogue (per 16-row half) ----
    #pragma unroll
    for (int mt = 0; mt < 2; mt++) {
        float l0 = lsum[mt][0], l1 = lsum[mt][1];
        l0 += __shfl_xor_sync(0xffffffffu, l0, 1);
        l0 += __shfl_xor_sync(0xffffffffu, l0, 2);
        l1 += __shfl_xor_sync(0xffffffffu, l1, 1);
        l1 += __shfl_xor_sync(0xffffffffu, l1, 2);
        float il0 = 1.0f / l0, il1 = 1.0f / l1;

        int row0 = q0 + wq0 + mt * 16 + g;
        size_t o0 = ((size_t)(b * LDIM + row0)) * DMODEL + h * DKH;
        #pragma unroll
        for (int nt = 0; nt < 8; nt++) {
            int col = nt * 8 + 2 * q;
            float2 v0 = make_float2(tf32r(O[mt][nt][0] * il0), tf32r(O[mt][nt][1] * il0));
            float2 v1 = make_float2(tf32r(O[mt][nt][2] * il1), tf32r(O[mt][nt][3] * il1));
            *(float2*)&out[o0 + col]              = v0;
            *(float2*)&out[o0 + 8 * DMODEL + col] = v1;
        }
    }
    #undef LOAD_TILE
}

// ---------------------------------------------------------------------------
// Launch
// ---------------------------------------------------------------------------
extern "C" void kernel_launch(void* const* d_in, const int* in_sizes, int n_in,
                              void* d_out, int out_size)
{
    const float* x     = (const float*)d_in[0];
    const int*   mask  = (const int*)  d_in[1];
    const float* Wqkv  = (const float*)d_in[2];
    const float* bqkv  = (const float*)d_in[3];
    const float* Wout  = (const float*)d_in[4];
    const float* bout  = (const float*)d_in[5];
    float* out = (float*)d_out;

    float *qkv, *attn, *xr, *wqkvT, *woutT, *vt;
    cudaGetSymbolAddress((void**)&qkv,   g_qkv);
    cudaGetSymbolAddress((void**)&attn,  g_attn);
    cudaGetSymbolAddress((void**)&xr,    g_x);
    cudaGetSymbolAddress((void**)&wqkvT, g_wqkvT);
    cudaGetSymbolAddress((void**)&woutT, g_woutT);
    cudaGetSymbolAddress((void**)&vt,    g_vt);

    cudaFuncSetAttribute(gemm_mma_kernel<true>,
                         cudaFuncAttributeMaxDynamicSharedMemorySize, GS_TOTAL);
    cudaFuncSetAttribute(gemm_mma_kernel<false>,
                         cudaFuncAttributeMaxDynamicSharedMemorySize, GS_TOTAL);
    cudaFuncSetAttribute(attn_mma_kernel,
                         cudaFuncAttributeMaxDynamicSharedMemorySize, ATTN_SM_BYTES);

    // Prep
    round_tf32_kernel<<<(ROWS * DMODEL / 4 + 255) / 256, 256>>>(x, xr, ROWS * DMODEL / 4);
    transpose_tf32_kernel<<<dim3(D3 / 32, GK / 32), dim3(32, 8)>>>(Wqkv, wqkvT, GK, D3);
    transpose_tf32_kernel<<<dim3(DMODEL / 32, GK / 32), dim3(32, 8)>>>(Wout, woutT, GK, DMODEL);

    // 1) QKV projection (tf32-rounded output)
    gemm_mma_kernel<true><<<dim3(D3 / 128, ROWS / 128), 128, GS_TOTAL>>>(
        xr, wqkvT, bqkv, qkv, D3);

    // 1b) V -> Vt [bh][d][L]
    vtrans_kernel<<<dim3(LDIM / 32, DKH / 32, BDIM * HEADS), dim3(32, 8)>>>(qkv, vt);

    // 2) Flash attention (all-tf32)
    attn_mma_kernel<<<dim3(LDIM / ABQ, BDIM * HEADS), 128, ATTN_SM_BYTES>>>(
        qkv, vt, mask, attn);

    // 3) Output projection (full-precision output)
    gemm_mma_kernel<false><<<dim3(DMODEL / 128, ROWS / 128), 128, GS_TOTAL>>>(
        attn, woutT, bout, out, DMODEL);
}

// round 13
// speedup vs baseline: 1.1350x; 1.0204x over previous
#include <cuda_runtime.h>
#include <math.h>
#include <stdint.h>

// Problem constants
#define BDIM   2
#define LDIM   2048
#define DMODEL 1024
#define HEADS  16
#define DKH    64
#define D3     (3 * DMODEL)
#define ROWS   (BDIM * LDIM)   // 4096
#define GK     1024            // K for both projection GEMMs

// Scratch (allocation-free: __device__ globals)
__device__ float g_qkv[(size_t)ROWS * D3];       // [B*L, 3*D], tf32-rounded values
__device__ float g_attn[(size_t)ROWS * DMODEL];  // [B,L,H,dk] (tf32-rounded)
__device__ float g_x[(size_t)ROWS * DMODEL];     // tf32-rounded x
__device__ float g_wqkvT[(size_t)D3 * GK];       // [3072][1024] k-major, tf32-rounded
__device__ float g_woutT[(size_t)DMODEL * GK];   // [1024][1024] k-major, tf32-rounded
__device__ float g_vt[(size_t)BDIM * HEADS * DKH * LDIM]; // [bh][d][L]

// ===========================================================================
// Helpers
// ===========================================================================
__device__ __forceinline__ float tf32r(float x) {
    uint32_t y;
    asm("cvt.rna.tf32.f32 %0, %1;" : "=r"(y) : "f"(x));
    return __uint_as_float(y);
}
__device__ __forceinline__ float ex2(float x) {
    float y;
    asm("ex2.approx.f32 %0, %1;" : "=f"(y) : "f"(x));
    return y;
}
__device__ __forceinline__ uint32_t smem_u32(const void* p) {
    uint32_t a;
    asm("{ .reg .u64 t; cvta.to.shared.u64 t, %1; cvt.u32.u64 %0, t; }" : "=r"(a) : "l"(p));
    return a;
}
#define SWZ128(x) ((x) ^ (((x) >> 3) & 0x70))

__device__ __forceinline__ void cp16(uint32_t dst, const void* src) {
    asm volatile("cp.async.cg.shared.global [%0], [%1], 16;" :: "r"(dst), "l"(src));
}
__device__ __forceinline__ void ldsm4(uint32_t& r0, uint32_t& r1, uint32_t& r2, uint32_t& r3,
                                      uint32_t addr) {
    asm volatile("ldmatrix.sync.aligned.m8n8.x4.shared.b16 {%0,%1,%2,%3}, [%4];"
                 : "=r"(r0), "=r"(r1), "=r"(r2), "=r"(r3) : "r"(addr));
}
__device__ __forceinline__ void mma_tf32(float* c, const uint32_t* a, uint32_t b0, uint32_t b1) {
    asm volatile("mma.sync.aligned.m16n8k8.row.col.f32.tf32.tf32.f32 "
                 "{%0,%1,%2,%3}, {%4,%5,%6,%7}, {%8,%9}, {%0,%1,%2,%3};"
                 : "+f"(c[0]), "+f"(c[1]), "+f"(c[2]), "+f"(c[3])
                 : "r"(a[0]), "r"(a[1]), "r"(a[2]), "r"(a[3]), "r"(b0), "r"(b1));
}

// ===========================================================================
// Prep kernels (unchanged)
// ===========================================================================
__global__ void round_tf32_kernel(const float* __restrict__ in, float* __restrict__ out, int n4) {
    int i = blockIdx.x * blockDim.x + threadIdx.x;
    if (i < n4) {
        float4 v = ((const float4*)in)[i];
        v.x = tf32r(v.x); v.y = tf32r(v.y); v.z = tf32r(v.z); v.w = tf32r(v.w);
        ((float4*)out)[i] = v;
    }
}

__global__ void transpose_tf32_kernel(const float* __restrict__ in, float* __restrict__ out,
                                      int K, int N) {
    __shared__ float t[32][33];
    int n0 = blockIdx.x * 32, k0 = blockIdx.y * 32;
    for (int j = threadIdx.y; j < 32; j += 8)
        t[j][threadIdx.x] = tf32r(in[(size_t)(k0 + j) * N + n0 + threadIdx.x]);
    __syncthreads();
    for (int j = threadIdx.y; j < 32; j += 8)
        out[(size_t)(n0 + j) * K + k0 + threadIdx.x] = t[threadIdx.x][j];
}

__global__ void vtrans_kernel(const float* __restrict__ qkv, float* __restrict__ vt) {
    __shared__ float t[32][33];
    int l0 = blockIdx.x * 32, d0 = blockIdx.y * 32;
    int bh = blockIdx.z;
    int b  = bh >> 4, h = bh & 15;
    const float* src = qkv + (size_t)b * LDIM * D3 + 2 * DMODEL + h * DKH;
    for (int j = threadIdx.y; j < 32; j += 8)
        t[j][threadIdx.x] = src[(size_t)(l0 + j) * D3 + d0 + threadIdx.x];
    __syncthreads();
    float* dst = vt + ((size_t)bh * DKH) * LDIM;
    for (int j = threadIdx.y; j < 32; j += 8)
        dst[(size_t)(d0 + j) * LDIM + l0 + threadIdx.x] = t[threadIdx.x][j];
}

// ===========================================================================
// tf32 mma.sync GEMM (R12-validated): 128 threads, 4 warps of 64x64,
// 3-stage cp.async pipeline, one __syncthreads per K-chunk.
// ===========================================================================
#define GBK    32
#define GTILE  (128 * GBK * 4)          // 16KB per operand tile
#define GSTG   3
#define GS_TOTAL (GSTG * 2 * GTILE)     // 96KB

__device__ __forceinline__ void gemm_load_tile(const float* __restrict__ src, int row0, int k0,
                                               uint32_t smemBase, int tid) {
    #pragma unroll
    for (int j = 0; j < 8; j++) {
        int i   = tid + j * 128;
        int row = i >> 3;
        int c   = i & 7;
        cp16(smemBase + SWZ128(row * 128 + c * 16),
             src + (size_t)(row0 + row) * GK + k0 + c * 4);
    }
}

template<bool RND>
__global__ __launch_bounds__(128, 2) void gemm_mma_kernel(
    const float* __restrict__ A, const float* __restrict__ Bt,
    const float* __restrict__ bias, float* __restrict__ C, int N)
{
    extern __shared__ char smc[];
    const uint32_t sb = smem_u32(smc);
    const int tid  = threadIdx.x;
    const int lane = tid & 31;
    const int w    = tid >> 5;
    const int m0   = blockIdx.y * 128;
    const int n0   = blockIdx.x * 128;
    const int wm   = (w & 1) * 64;
    const int wn   = (w >> 1) * 64;

    const int aOff = (wm + (lane & 15)) * 128 + ((lane >> 4) << 4);
    const int bOff = (wn + ((lane >> 4) << 3) + (lane & 7)) * 128 + (((lane >> 3) & 1) << 4);

    float acc[32][4];
    #pragma unroll
    for (int t = 0; t < 32; t++)
        #pragma unroll
        for (int j = 0; j < 4; j++) acc[t][j] = 0.0f;

    gemm_load_tile(A,  m0, 0, sb, tid);
    gemm_load_tile(Bt, n0, 0, sb + GTILE, tid);
    asm volatile("cp.async.commit_group;" ::: "memory");
    gemm_load_tile(A,  m0, GBK, sb + 2 * GTILE, tid);
    gemm_load_tile(Bt, n0, GBK, sb + 3 * GTILE, tid);
    asm volatile("cp.async.commit_group;" ::: "memory");

    const int NCHUNK = GK / GBK;   // 32
    for (int c = 0; c < NCHUNK; c++) {
        if (c < NCHUNK - 1) { asm volatile("cp.async.wait_group 1;" ::: "memory"); }
        else                { asm volatile("cp.async.wait_group 0;" ::: "memory"); }
        __syncthreads();

        if (c + 2 < NCHUNK) {
            const uint32_t sp = sb + ((c + 2) % GSTG) * 2 * GTILE;
            gemm_load_tile(A,  m0, (c + 2) * GBK, sp, tid);
            gemm_load_tile(Bt, n0, (c + 2) * GBK, sp + GTILE, tid);
            asm volatile("cp.async.commit_group;" ::: "memory");
        }

        const uint32_t ba = sb + (c % GSTG) * 2 * GTILE;
        const uint32_t bb = ba + GTILE;
        #pragma unroll
        for (int ks = 0; ks < 4; ks++) {
            uint32_t a[4][4], b[4][4];
            #pragma unroll
            for (int mt = 0; mt < 4; mt++)
                ldsm4(a[mt][0], a[mt][1], a[mt][2], a[mt][3],
                      ba + SWZ128(aOff + mt * 2048 + ks * 32));
            #pragma unroll
            for (int np = 0; np < 4; np++)
                ldsm4(b[np][0], b[np][1], b[np][2], b[np][3],
                      bb + SWZ128(bOff + np * 2048 + ks * 32));
            #pragma unroll
            for (int mt = 0; mt < 4; mt++)
                #pragma unroll
                for (int nt = 0; nt < 8; nt++)
                    mma_tf32(acc[mt * 8 + nt], a[mt],
                             b[nt >> 1][(nt & 1) * 2], b[nt >> 1][(nt & 1) * 2 + 1]);
        }
    }

    #pragma unroll
    for (int mt = 0; mt < 4; mt++) {
        #pragma unroll
        for (int nt = 0; nt < 8; nt++) {
            const float* cc = acc[mt * 8 + nt];
            int row = m0 + wm + mt * 16 + (lane >> 2);
            int col = n0 + wn + nt * 8 + (lane & 3) * 2;
            float2 bv = *(const float2*)&bias[col];
            float2 o0 = make_float2(cc[0] + bv.x, cc[1] + bv.y);
            float2 o1 = make_float2(cc[2] + bv.x, cc[3] + bv.y);
            if (RND) {
                o0.x = tf32r(o0.x); o0.y = tf32r(o0.y);
                o1.x = tf32r(o1.x); o1.y = tf32r(o1.y);
            }
            *(float2*)&C[(size_t)row * N + col]       = o0;
            *(float2*)&C[(size_t)(row + 8) * N + col] = o1;
        }
    }
}

// ===========================================================================
// Tensor-core flash attention: 128 threads, 4 warps of 32 q-rows.
//  - single-buffered K and V with phase-split prefetch:
//      K(t+1) loads during PV(t);  V(t+1) loads during S(t+1)
//  - P staged per-warp in smem; PV A-frags via ldmatrix (NO shuffles)
//  - mask folded into S init; single-ex2 softmax
// Smem (floats): Q 128x68 | K 64x68 | V 64x68 | P 128x68 | mask 64 ints
// ===========================================================================
#define ABQ 128
#define ABK 64
#define AST 68
#define AQS_F 0
#define AKS_F (ABQ * AST)            // 8704
#define AVS_F (AKS_F + ABK * AST)    // 13056
#define APS_F (AVS_F + ABK * AST)    // 17408
#define AMS_F (APS_F + ABQ * AST)    // 26112
#define ATTN_SM_BYTES (AMS_F * 4 + 256)   // 104704
#define EXPC 0.18033688011112042f   // 0.125 * log2(e)

__global__ void __launch_bounds__(128, 2) attn_mma_kernel(
    const float* __restrict__ qkv, const float* __restrict__ vt,
    const int* __restrict__ mask, float* __restrict__ out)
{
    extern __shared__ float smf[];
    const uint32_t sb = smem_u32(smf);

    const int tid  = threadIdx.x;
    const int lane = tid & 31;
    const int w    = tid >> 5;      // 0..3
    const int g    = lane >> 2;
    const int q    = lane & 3;
    const int b    = blockIdx.y >> 4;
    const int h    = blockIdx.y & 15;
    const int q0   = blockIdx.x * ABQ;
    const int wq0  = w * 32;        // 32 q-rows per warp

    const size_t base = (size_t)b * LDIM * D3 + (size_t)h * DKH;
    const float* vtb  = vt + ((size_t)blockIdx.y * DKH) * LDIM;
    const int*   mkb  = mask + b * LDIM;

    // Q tile (joins K(0)'s cp.async group)
    for (int i = tid; i < ABQ * 16; i += 128) {
        int r = i >> 4, c4 = (i & 15) * 4;
        cp16(sb + (AQS_F + r * AST + c4) * 4, &qkv[base + (size_t)(q0 + r) * D3 + c4]);
    }
    #define LOAD_K(t) do {                                                           \
        int _k0 = (t) * ABK;                                                         \
        for (int _i = tid; _i < ABK * 16; _i += 128) {                               \
            int _r = _i >> 4, _c4 = (_i & 15) * 4;                                   \
            cp16(sb + (AKS_F + _r * AST + _c4) * 4,                                  \
                 &qkv[base + (size_t)(_k0 + _r) * D3 + DMODEL + _c4]);               \
        }                                                                            \
        if (tid < 16) cp16(sb + AMS_F * 4 + tid * 16, &mkb[_k0 + tid * 4]);          \
    } while (0)
    #define LOAD_V(t) do {                                                           \
        int _k0 = (t) * ABK;                                                         \
        for (int _i = tid; _i < ABK * 16; _i += 128) {                               \
            int _r = _i >> 4, _c4 = (_i & 15) * 4;                                   \
            cp16(sb + (AVS_F + _r * AST + _c4) * 4,                                  \
                 &vtb[(size_t)_r * LDIM + _k0 + _c4]);                               \
        }                                                                            \
    } while (0)

    LOAD_K(0);
    asm volatile("cp.async.commit_group;" ::: "memory");   // {Q + K0 + mask0}
    LOAD_V(0);
    asm volatile("cp.async.commit_group;" ::: "memory");   // {V0}

    float O[2][8][4];
    #pragma unroll
    for (int mt = 0; mt < 2; mt++)
        #pragma unroll
        for (int t = 0; t < 8; t++)
            #pragma unroll
            for (int j = 0; j < 4; j++) O[mt][t][j] = 0.0f;
    float lsum[2][2] = {{0.0f, 0.0f}, {0.0f, 0.0f}};

    const uint32_t aAddr = sb + (AQS_F + (wq0 + (lane & 15)) * AST) * 4 + ((lane >> 4) << 4);
    const uint32_t bRowO = (((lane >> 4) << 3) + (lane & 7)) * AST;
    const uint32_t bK    = sb + (AKS_F + bRowO) * 4 + (((lane >> 3) & 1) << 4);
    const uint32_t bV    = sb + (AVS_F + bRowO) * 4 + (((lane >> 3) & 1) << 4);
    float*         Pw    = smf + APS_F + w * 32 * AST;                  // warp's P block
    const uint32_t pR    = sb + (APS_F + (w * 32 + (lane & 15)) * AST) * 4
                              + ((lane >> 4) << 4);
    const int* ms = (const int*)((const char*)smf + AMS_F * 4);

    const int NT = LDIM / ABK;   // 32
    for (int t = 0; t < NT; t++) {
        // pending groups here: {K(t)(+Q/mask), V(t)} -> complete K(t)
        asm volatile("cp.async.wait_group 1;" ::: "memory");
        __syncthreads();

        // ---- S init = mask bias; S += Q K(t)^T ----
        float S[2][8][4];
        #pragma unroll
        for (int nt = 0; nt < 8; nt++) {
            int2 mk = *(const int2*)&ms[nt * 8 + 2 * q];
            float bx = mk.x ? 0.0f : -3.0e38f;
            float by = mk.y ? 0.0f : -3.0e38f;
            S[0][nt][0] = bx; S[0][nt][1] = by; S[0][nt][2] = bx; S[0][nt][3] = by;
            S[1][nt][0] = bx; S[1][nt][1] = by; S[1][nt][2] = bx; S[1][nt][3] = by;
        }
        #pragma unroll
        for (int ks = 0; ks < 8; ks++) {
            uint32_t av0[4], av1[4];
            ldsm4(av0[0], av0[1], av0[2], av0[3], aAddr + ks * 32);
            ldsm4(av1[0], av1[1], av1[2], av1[3], aAddr + 16 * AST * 4 + ks * 32);
            #pragma unroll
            for (int ntp = 0; ntp < 4; ntp++) {
                uint32_t b0, b1, b2, b3;
                ldsm4(b0, b1, b2, b3, bK + ntp * 16 * AST * 4 + ks * 32);
                mma_tf32(S[0][2 * ntp],     av0, b0, b1);
                mma_tf32(S[0][2 * ntp + 1], av0, b2, b3);
                mma_tf32(S[1][2 * ntp],     av1, b0, b1);
                mma_tf32(S[1][2 * ntp + 1], av1, b2, b3);
            }
        }

        // ---- P = exp2(S * c); lsum += raw P; store tf32r(P) to smem ----
        #pragma unroll
        for (int mt = 0; mt < 2; mt++)
            #pragma unroll
            for (int nt = 0; nt < 8; nt++) {
                float p0 = ex2(S[mt][nt][0] * EXPC);
                float p1 = ex2(S[mt][nt][1] * EXPC);
                float p2 = ex2(S[mt][nt][2] * EXPC);
                float p3 = ex2(S[mt][nt][3] * EXPC);
                lsum[mt][0] += p0 + p1;
                lsum[mt][1] += p2 + p3;
                int r = mt * 16 + g;
                int col = nt * 8 + 2 * q;
                *(float2*)&Pw[r * AST + col]       = make_float2(tf32r(p0), tf32r(p1));
                *(float2*)&Pw[(r + 8) * AST + col] = make_float2(tf32r(p2), tf32r(p3));
            }
        __syncwarp();
        __syncthreads();                 // all warps done reading K(t) and mask(t)

        if (t + 1 < NT) {
            LOAD_K(t + 1);
            asm volatile("cp.async.commit_group;" ::: "memory");
        }
        // complete V(t): pending {V(t), K(t+1)?}
        if (t + 1 < NT) { asm volatile("cp.async.wait_group 1;" ::: "memory"); }
        else            { asm volatile("cp.async.wait_group 0;" ::: "memory"); }
        __syncthreads();

        // ---- O += P~ V(t): A-frags from smem P, B-frags from V ----
        #pragma unroll
        for (int j = 0; j < 8; j++) {
            uint32_t pa0[4], pa1[4];
            ldsm4(pa0[0], pa0[1], pa0[2], pa0[3], pR + j * 32);
            ldsm4(pa1[0], pa1[1], pa1[2], pa1[3], pR + 16 * AST * 4 + j * 32);
            #pragma unroll
            for (int np = 0; np < 4; np++) {
                uint32_t b0, b1, b2, b3;
                ldsm4(b0, b1, b2, b3, bV + np * 16 * AST * 4 + j * 32);
                mma_tf32(O[0][2 * np],     pa0, b0, b1);
                mma_tf32(O[0][2 * np + 1], pa0, b2, b3);
                mma_tf32(O[1][2 * np],     pa1, b0, b1);
                mma_tf32(O[1][2 * np + 1], pa1, b2, b3);
            }
        }

        __syncthreads();                 // all warps done with V(t)
        if (t + 1 < NT) {
            LOAD_V(t + 1);
            asm volatile("cp.async.commit_group;" ::: "memory");
        }
    }

    // ---- row-sum reduce + epilogue (per 16-row half) ----
    #pragma unroll
    for (int mt = 0; mt < 2; mt++) {
        float l0 = lsum[mt][0], l1 = lsum[mt][1];
        l0 += __shfl_xor_sync(0xffffffffu, l0, 1);
        l0 += __shfl_xor_sync(0xffffffffu, l0, 2);
        l1 += __shfl_xor_sync(0xffffffffu, l1, 1);
        l1 += __shfl_xor_sync(0xffffffffu, l1, 2);
        float il0 = 1.0f / l0, il1 = 1.0f / l1;

        int row0 = q0 + wq0 + mt * 16 + g;
        size_t o0 = ((size_t)(b * LDIM + row0)) * DMODEL + h * DKH;
        #pragma unroll
        for (int nt = 0; nt < 8; nt++) {
            int col = nt * 8 + 2 * q;
            float2 v0 = make_float2(tf32r(O[mt][nt][0] * il0), tf32r(O[mt][nt][1] * il0));
            float2 v1 = make_float2(tf32r(O[mt][nt][2] * il1), tf32r(O[mt][nt][3] * il1));
            *(float2*)&out[o0 + col]              = v0;
            *(float2*)&out[o0 + 8 * DMODEL + col] = v1;
        }
    }
    #undef LOAD_K
    #undef LOAD_V
}

// ---------------------------------------------------------------------------
// Launch
// ---------------------------------------------------------------------------
extern "C" void kernel_launch(void* const* d_in, const int* in_sizes, int n_in,
                              void* d_out, int out_size)
{
    const float* x     = (const float*)d_in[0];
    const int*   mask  = (const int*)  d_in[1];
    const float* Wqkv  = (const float*)d_in[2];
    const float* bqkv  = (const float*)d_in[3];
    const float* Wout  = (const float*)d_in[4];
    const float* bout  = (const float*)d_in[5];
    float* out = (float*)d_out;

    float *qkv, *attn, *xr, *wqkvT, *woutT, *vt;
    cudaGetSymbolAddress((void**)&qkv,   g_qkv);
    cudaGetSymbolAddress((void**)&attn,  g_attn);
    cudaGetSymbolAddress((void**)&xr,    g_x);
    cudaGetSymbolAddress((void**)&wqkvT, g_wqkvT);
    cudaGetSymbolAddress((void**)&woutT, g_woutT);
    cudaGetSymbolAddress((void**)&vt,    g_vt);

    cudaFuncSetAttribute(gemm_mma_kernel<true>,
                         cudaFuncAttributeMaxDynamicSharedMemorySize, GS_TOTAL);
    cudaFuncSetAttribute(gemm_mma_kernel<false>,
                         cudaFuncAttributeMaxDynamicSharedMemorySize, GS_TOTAL);
    cudaFuncSetAttribute(attn_mma_kernel,
                         cudaFuncAttributeMaxDynamicSharedMemorySize, ATTN_SM_BYTES);

    // Prep
    round_tf32_kernel<<<(ROWS * DMODEL / 4 + 255) / 256, 256>>>(x, xr, ROWS * DMODEL / 4);
    transpose_tf32_kernel<<<dim3(D3 / 32, GK / 32), dim3(32, 8)>>>(Wqkv, wqkvT, GK, D3);
    transpose_tf32_kernel<<<dim3(DMODEL / 32, GK / 32), dim3(32, 8)>>>(Wout, woutT, GK, DMODEL);

    // 1) QKV projection (tf32-rounded output)
    gemm_mma_kernel<true><<<dim3(D3 / 128, ROWS / 128), 128, GS_TOTAL>>>(
        xr, wqkvT, bqkv, qkv, D3);

    // 1b) V -> Vt [bh][d][L]
    vtrans_kernel<<<dim3(LDIM / 32, DKH / 32, BDIM * HEADS), dim3(32, 8)>>>(qkv, vt);

    // 2) Flash attention (all-tf32, shuffle-free PV)
    attn_mma_kernel<<<dim3(LDIM / ABQ, BDIM * HEADS), 128, ATTN_SM_BYTES>>>(
        qkv, vt, mask, attn);

    // 3) Output projection (full-precision output)
    gemm_mma_kernel<false><<<dim3(DMODEL / 128, ROWS / 128), 128, GS_TOTAL>>>(
        attn, woutT, bout, out, DMODEL);
}

// round 14
// speedup vs baseline: 1.4212x; 1.2522x over previous
#include <cuda_runtime.h>
#include <math.h>
#include <stdint.h>

// Problem constants
#define BDIM   2
#define LDIM   2048
#define DMODEL 1024
#define HEADS  16
#define DKH    64
#define D3     (3 * DMODEL)
#define ROWS   (BDIM * LDIM)   // 4096
#define GK     1024            // K for both projection GEMMs

// Scratch (allocation-free: __device__ globals)
__device__ float g_qkv[(size_t)ROWS * D3];       // [B*L, 3*D], tf32-rounded values
__device__ float g_attn[(size_t)ROWS * DMODEL];  // [B,L,H,dk] (tf32-rounded)
__device__ float g_x[(size_t)ROWS * DMODEL];     // tf32-rounded x
__device__ float g_wqkvT[(size_t)D3 * GK];       // [3072][1024] k-major, tf32-rounded
__device__ float g_woutT[(size_t)DMODEL * GK];   // [1024][1024] k-major, tf32-rounded
__device__ float g_kc[(size_t)BDIM * HEADS * LDIM * DKH];  // compacted K [bh][j][64]
__device__ float g_vtc[(size_t)BDIM * HEADS * DKH * LDIM]; // compacted Vt [bh][d][j]
__device__ int   g_idx[BDIM * LDIM];             // compacted key index list
__device__ int   g_cmask[BDIM * LDIM];           // compacted mask (1 for j<cnt)
__device__ int   g_cnt[BDIM];                    // unmasked count per batch

// ===========================================================================
// Helpers
// ===========================================================================
__device__ __forceinline__ float tf32r(float x) {
    uint32_t y;
    asm("cvt.rna.tf32.f32 %0, %1;" : "=r"(y) : "f"(x));
    return __uint_as_float(y);
}
__device__ __forceinline__ float ex2(float x) {
    float y;
    asm("ex2.approx.f32 %0, %1;" : "=f"(y) : "f"(x));
    return y;
}
__device__ __forceinline__ uint32_t smem_u32(const void* p) {
    uint32_t a;
    asm("{ .reg .u64 t; cvta.to.shared.u64 t, %1; cvt.u32.u64 %0, t; }" : "=r"(a) : "l"(p));
    return a;
}
#define SWZ128(x) ((x) ^ (((x) >> 3) & 0x70))

__device__ __forceinline__ void cp16(uint32_t dst, const void* src) {
    asm volatile("cp.async.cg.shared.global [%0], [%1], 16;" :: "r"(dst), "l"(src));
}
__device__ __forceinline__ void ldsm4(uint32_t& r0, uint32_t& r1, uint32_t& r2, uint32_t& r3,
                                      uint32_t addr) {
    asm volatile("ldmatrix.sync.aligned.m8n8.x4.shared.b16 {%0,%1,%2,%3}, [%4];"
                 : "=r"(r0), "=r"(r1), "=r"(r2), "=r"(r3) : "r"(addr));
}
__device__ __forceinline__ void mma_tf32(float* c, const uint32_t* a, uint32_t b0, uint32_t b1) {
    asm volatile("mma.sync.aligned.m16n8k8.row.col.f32.tf32.tf32.f32 "
                 "{%0,%1,%2,%3}, {%4,%5,%6,%7}, {%8,%9}, {%0,%1,%2,%3};"
                 : "+f"(c[0]), "+f"(c[1]), "+f"(c[2]), "+f"(c[3])
                 : "r"(a[0]), "r"(a[1]), "r"(a[2]), "r"(a[3]), "r"(b0), "r"(b1));
}

// ===========================================================================
// Prep kernels
// ===========================================================================
__global__ void round_tf32_kernel(const float* __restrict__ in, float* __restrict__ out, int n4) {
    int i = blockIdx.x * blockDim.x + threadIdx.x;
    if (i < n4) {
        float4 v = ((const float4*)in)[i];
        v.x = tf32r(v.x); v.y = tf32r(v.y); v.z = tf32r(v.z); v.w = tf32r(v.w);
        ((float4*)out)[i] = v;
    }
}

__global__ void transpose_tf32_kernel(const float* __restrict__ in, float* __restrict__ out,
                                      int K, int N) {
    __shared__ float t[32][33];
    int n0 = blockIdx.x * 32, k0 = blockIdx.y * 32;
    for (int j = threadIdx.y; j < 32; j += 8)
        t[j][threadIdx.x] = tf32r(in[(size_t)(k0 + j) * N + n0 + threadIdx.x]);
    __syncthreads();
    for (int j = threadIdx.y; j < 32; j += 8)
        out[(size_t)(n0 + j) * K + k0 + threadIdx.x] = t[threadIdx.x][j];
}

// Deterministic block scan: per-batch compacted index list + count.
// 1 block of 256 threads per batch; each thread owns 8 consecutive keys.
__global__ void mask_scan_kernel(const int* __restrict__ mask,
                                 int* __restrict__ idx, int* __restrict__ cnt) {
    __shared__ int wsum[8];
    const int b = blockIdx.x;
    const int* m = mask + b * LDIM;
    const int t = threadIdx.x;
    const int base = t * 8;
    int v[8], s = 0;
    #pragma unroll
    for (int i = 0; i < 8; i++) { v[i] = m[base + i]; s += v[i]; }
    const int lane = t & 31, wid = t >> 5;
    int pre = s;
    #pragma unroll
    for (int o = 1; o < 32; o <<= 1) {
        int x = __shfl_up_sync(0xffffffffu, pre, o);
        if (lane >= o) pre += x;
    }
    if (lane == 31) wsum[wid] = pre;
    __syncthreads();
    int woff = 0;
    for (int i = 0; i < wid; i++) woff += wsum[i];
    int off = woff + pre - s;
    #pragma unroll
    for (int i = 0; i < 8; i++)
        if (v[i]) idx[b * LDIM + off++] = base + i;
    if (t == 255) cnt[b] = woff + pre;
}

// cmask[b][j] = (j < cnt[b])
__global__ void cmask_kernel(const int* __restrict__ cnt, int* __restrict__ cmask) {
    int i = blockIdx.x * 256 + threadIdx.x;      // 0..4095
    int b = i >> 11, j = i & (LDIM - 1);
    cmask[i] = (j < cnt[b]) ? 1 : 0;
}

// Gather compacted K rows: kc[bh][j][64]; zero rows for j >= cnt.
__global__ void kgather_kernel(const float* __restrict__ qkv, const int* __restrict__ idx,
                               const int* __restrict__ cnt, float* __restrict__ kc) {
    int j  = blockIdx.x * 128 + threadIdx.x;     // 0..2047
    int bh = blockIdx.y;
    int b  = bh >> 4, h = bh & 15;
    int c  = cnt[b];
    float4* dst = (float4*)(kc + ((size_t)bh * LDIM + j) * DKH);
    if (j < c) {
        const float4* src = (const float4*)(qkv + (size_t)b * LDIM * D3
                            + (size_t)idx[b * LDIM + j] * D3 + DMODEL + h * DKH);
        #pragma unroll
        for (int i = 0; i < 16; i++) dst[i] = src[i];
    } else {
        float4 z = make_float4(0.f, 0.f, 0.f, 0.f);
        #pragma unroll
        for (int i = 0; i < 16; i++) dst[i] = z;
    }
}

// Gathered V transpose: vtc[bh][d][j] (zero for j >= cnt). block (32,8)
__global__ void vtrans_gather_kernel(const float* __restrict__ qkv, const int* __restrict__ idx,
                                     const int* __restrict__ cnt, float* __restrict__ vtc) {
    __shared__ float t[32][33];
    int j0 = blockIdx.x * 32, d0 = blockIdx.y * 32;
    int bh = blockIdx.z;
    int b  = bh >> 4, h = bh & 15;
    int c  = cnt[b];
    const float* src = qkv + (size_t)b * LDIM * D3 + 2 * DMODEL + h * DKH;
    for (int j = threadIdx.y; j < 32; j += 8) {
        int jj = j0 + j;
        float val = 0.0f;
        if (jj < c) val = src[(size_t)idx[b * LDIM + jj] * D3 + d0 + threadIdx.x];
        t[j][threadIdx.x] = val;
    }
    __syncthreads();
    float* dst = vtc + ((size_t)bh * DKH) * LDIM;
    for (int j = threadIdx.y; j < 32; j += 8)
        dst[(size_t)(d0 + j) * LDIM + j0 + threadIdx.x] = t[threadIdx.x][j];
}

// ===========================================================================
// tf32 mma.sync GEMM (R12-validated): 128 threads, 4 warps of 64x64,
// 3-stage cp.async pipeline, one __syncthreads per K-chunk.
// ===========================================================================
#define GBK    32
#define GTILE  (128 * GBK * 4)          // 16KB per operand tile
#define GSTG   3
#define GS_TOTAL (GSTG * 2 * GTILE)     // 96KB

__device__ __forceinline__ void gemm_load_tile(const float* __restrict__ src, int row0, int k0,
                                               uint32_t smemBase, int tid) {
    #pragma unroll
    for (int j = 0; j < 8; j++) {
        int i   = tid + j * 128;
        int row = i >> 3;
        int c   = i & 7;
        cp16(smemBase + SWZ128(row * 128 + c * 16),
             src + (size_t)(row0 + row) * GK + k0 + c * 4);
    }
}

template<bool RND>
__global__ __launch_bounds__(128, 2) void gemm_mma_kernel(
    const float* __restrict__ A, const float* __restrict__ Bt,
    const float* __restrict__ bias, float* __restrict__ C, int N)
{
    extern __shared__ char smc[];
    const uint32_t sb = smem_u32(smc);
    const int tid  = threadIdx.x;
    const int lane = tid & 31;
    const int w    = tid >> 5;
    const int m0   = blockIdx.y * 128;
    const int n0   = blockIdx.x * 128;
    const int wm   = (w & 1) * 64;
    const int wn   = (w >> 1) * 64;

    const int aOff = (wm + (lane & 15)) * 128 + ((lane >> 4) << 4);
    const int bOff = (wn + ((lane >> 4) << 3) + (lane & 7)) * 128 + (((lane >> 3) & 1) << 4);

    float acc[32][4];
    #pragma unroll
    for (int t = 0; t < 32; t++)
        #pragma unroll
        for (int j = 0; j < 4; j++) acc[t][j] = 0.0f;

    gemm_load_tile(A,  m0, 0, sb, tid);
    gemm_load_tile(Bt, n0, 0, sb + GTILE, tid);
    asm volatile("cp.async.commit_group;" ::: "memory");
    gemm_load_tile(A,  m0, GBK, sb + 2 * GTILE, tid);
    gemm_load_tile(Bt, n0, GBK, sb + 3 * GTILE, tid);
    asm volatile("cp.async.commit_group;" ::: "memory");

    const int NCHUNK = GK / GBK;   // 32
    for (int c = 0; c < NCHUNK; c++) {
        if (c < NCHUNK - 1) { asm volatile("cp.async.wait_group 1;" ::: "memory"); }
        else                { asm volatile("cp.async.wait_group 0;" ::: "memory"); }
        __syncthreads();

        if (c + 2 < NCHUNK) {
            const uint32_t sp = sb + ((c + 2) % GSTG) * 2 * GTILE;
            gemm_load_tile(A,  m0, (c + 2) * GBK, sp, tid);
            gemm_load_tile(Bt, n0, (c + 2) * GBK, sp + GTILE, tid);
            asm volatile("cp.async.commit_group;" ::: "memory");
        }

        const uint32_t ba = sb + (c % GSTG) * 2 * GTILE;
        const uint32_t bb = ba + GTILE;
        #pragma unroll
        for (int ks = 0; ks < 4; ks++) {
            uint32_t a[4][4], b[4][4];
            #pragma unroll
            for (int mt = 0; mt < 4; mt++)
                ldsm4(a[mt][0], a[mt][1], a[mt][2], a[mt][3],
                      ba + SWZ128(aOff + mt * 2048 + ks * 32));
            #pragma unroll
            for (int np = 0; np < 4; np++)
                ldsm4(b[np][0], b[np][1], b[np][2], b[np][3],
                      bb + SWZ128(bOff + np * 2048 + ks * 32));
            #pragma unroll
            for (int mt = 0; mt < 4; mt++)
                #pragma unroll
                for (int nt = 0; nt < 8; nt++)
                    mma_tf32(acc[mt * 8 + nt], a[mt],
                             b[nt >> 1][(nt & 1) * 2], b[nt >> 1][(nt & 1) * 2 + 1]);
        }
    }

    #pragma unroll
    for (int mt = 0; mt < 4; mt++) {
        #pragma unroll
        for (int nt = 0; nt < 8; nt++) {
            const float* cc = acc[mt * 8 + nt];
            int row = m0 + wm + mt * 16 + (lane >> 2);
            int col = n0 + wn + nt * 8 + (lane & 3) * 2;
            float2 bv = *(const float2*)&bias[col];
            float2 o0 = make_float2(cc[0] + bv.x, cc[1] + bv.y);
            float2 o1 = make_float2(cc[2] + bv.x, cc[3] + bv.y);
            if (RND) {
                o0.x = tf32r(o0.x); o0.y = tf32r(o0.y);
                o1.x = tf32r(o1.x); o1.y = tf32r(o1.y);
            }
            *(float2*)&C[(size_t)row * N + col]       = o0;
            *(float2*)&C[(size_t)(row + 8) * N + col] = o1;
        }
    }
}

// ===========================================================================
// Tensor-core flash attention over COMPACTED keys (exact: masked keys have
// P=0 and are simply removed; padded tail columns use cmask=0 -> P=0).
// 128 threads, 4 warps of 32 q-rows; single-buffered K/V phase-split
// prefetch; P staged per-warp in smem (shuffle-free PV); single-ex2 softmax.
// ===========================================================================
#define ABQ 128
#define ABK 64
#define AST 68
#define AQS_F 0
#define AKS_F (ABQ * AST)            // 8704
#define AVS_F (AKS_F + ABK * AST)    // 13056
#define APS_F (AVS_F + ABK * AST)    // 17408
#define AMS_F (APS_F + ABQ * AST)    // 26112
#define ATTN_SM_BYTES (AMS_F * 4 + 256)   // 104704
#define EXPC 0.18033688011112042f   // 0.125 * log2(e)

__global__ void __launch_bounds__(128, 2) attn_mma_kernel(
    const float* __restrict__ qkv, const float* __restrict__ kc,
    const float* __restrict__ vtc, const int* __restrict__ cmask,
    const int* __restrict__ cnt, float* __restrict__ out)
{
    extern __shared__ float smf[];
    const uint32_t sb = smem_u32(smf);

    const int tid  = threadIdx.x;
    const int lane = tid & 31;
    const int w    = tid >> 5;      // 0..3
    const int g    = lane >> 2;
    const int q    = lane & 3;
    const int b    = blockIdx.y >> 4;
    const int h    = blockIdx.y & 15;
    const int q0   = blockIdx.x * ABQ;
    const int wq0  = w * 32;        // 32 q-rows per warp

    const size_t base = (size_t)b * LDIM * D3 + (size_t)h * DKH;
    const float* kcb  = kc  + (size_t)blockIdx.y * LDIM * DKH;
    const float* vtb  = vtc + ((size_t)blockIdx.y * DKH) * LDIM;
    const int*   mkb  = cmask + b * LDIM;
    const int NT = (__ldg(&cnt[b]) + ABK - 1) >> 6;   // compacted tiles

    // Q tile (joins K(0)'s cp.async group)
    for (int i = tid; i < ABQ * 16; i += 128) {
        int r = i >> 4, c4 = (i & 15) * 4;
        cp16(sb + (AQS_F + r * AST + c4) * 4, &qkv[base + (size_t)(q0 + r) * D3 + c4]);
    }
    #define LOAD_K(t) do {                                                           \
        int _k0 = (t) * ABK;                                                         \
        for (int _i = tid; _i < ABK * 16; _i += 128) {                               \
            int _r = _i >> 4, _c4 = (_i & 15) * 4;                                   \
            cp16(sb + (AKS_F + _r * AST + _c4) * 4,                                  \
                 &kcb[(size_t)(_k0 + _r) * DKH + _c4]);                              \
        }                                                                            \
        if (tid < 16) cp16(sb + AMS_F * 4 + tid * 16, &mkb[_k0 + tid * 4]);          \
    } while (0)
    #define LOAD_V(t) do {                                                           \
        int _k0 = (t) * ABK;                                                         \
        for (int _i = tid; _i < ABK * 16; _i += 128) {                               \
            int _r = _i >> 4, _c4 = (_i & 15) * 4;                                   \
            cp16(sb + (AVS_F + _r * AST + _c4) * 4,                                  \
                 &vtb[(size_t)_r * LDIM + _k0 + _c4]);                               \
        }                                                                            \
    } while (0)

    LOAD_K(0);
    asm volatile("cp.async.commit_group;" ::: "memory");   // {Q + K0 + mask0}
    LOAD_V(0);
    asm volatile("cp.async.commit_group;" ::: "memory");   // {V0}

    float O[2][8][4];
    #pragma unroll
    for (int mt = 0; mt < 2; mt++)
        #pragma unroll
        for (int t = 0; t < 8; t++)
            #pragma unroll
            for (int j = 0; j < 4; j++) O[mt][t][j] = 0.0f;
    float lsum[2][2] = {{0.0f, 0.0f}, {0.0f, 0.0f}};

    const uint32_t aAddr = sb + (AQS_F + (wq0 + (lane & 15)) * AST) * 4 + ((lane >> 4) << 4);
    const uint32_t bRowO = (((lane >> 4) << 3) + (lane & 7)) * AST;
    const uint32_t bK    = sb + (AKS_F + bRowO) * 4 + (((lane >> 3) & 1) << 4);
    const uint32_t bV    = sb + (AVS_F + bRowO) * 4 + (((lane >> 3) & 1) << 4);
    float*         Pw    = smf + APS_F + w * 32 * AST;
    const uint32_t pR    = sb + (APS_F + (w * 32 + (lane & 15)) * AST) * 4
                              + ((lane >> 4) << 4);
    const int* ms = (const int*)((const char*)smf + AMS_F * 4);

    for (int t = 0; t < NT; t++) {
        // pending groups here: {K(t)(+Q/mask), V(t)} -> complete K(t)
        asm volatile("cp.async.wait_group 1;" ::: "memory");
        __syncthreads();

        // ---- S init = mask bias; S += Q K(t)^T ----
        float S[2][8][4];
        #pragma unroll
        for (int nt = 0; nt < 8; nt++) {
            int2 mk = *(const int2*)&ms[nt * 8 + 2 * q];
            float bx = mk.x ? 0.0f : -3.0e38f;
            float by = mk.y ? 0.0f : -3.0e38f;
            S[0][nt][0] = bx; S[0][nt][1] = by; S[0][nt][2] = bx; S[0][nt][3] = by;
            S[1][nt][0] = bx; S[1][nt][1] = by; S[1][nt][2] = bx; S[1][nt][3] = by;
        }
        #pragma unroll
        for (int ks = 0; ks < 8; ks++) {
            uint32_t av0[4], av1[4];
            ldsm4(av0[0], av0[1], av0[2], av0[3], aAddr + ks * 32);
            ldsm4(av1[0], av1[1], av1[2], av1[3], aAddr + 16 * AST * 4 + ks * 32);
            #pragma unroll
            for (int ntp = 0; ntp < 4; ntp++) {
                uint32_t b0, b1, b2, b3;
                ldsm4(b0, b1, b2, b3, bK + ntp * 16 * AST * 4 + ks * 32);
                mma_tf32(S[0][2 * ntp],     av0, b0, b1);
                mma_tf32(S[0][2 * ntp + 1], av0, b2, b3);
                mma_tf32(S[1][2 * ntp],     av1, b0, b1);
                mma_tf32(S[1][2 * ntp + 1], av1, b2, b3);
            }
        }

        // ---- P = exp2(S * c); lsum += raw P; store tf32r(P) to smem ----
        #pragma unroll
        for (int mt = 0; mt < 2; mt++)
            #pragma unroll
            for (int nt = 0; nt < 8; nt++) {
                float p0 = ex2(S[mt][nt][0] * EXPC);
                float p1 = ex2(S[mt][nt][1] * EXPC);
                float p2 = ex2(S[mt][nt][2] * EXPC);
                float p3 = ex2(S[mt][nt][3] * EXPC);
                lsum[mt][0] += p0 + p1;
                lsum[mt][1] += p2 + p3;
                int r = mt * 16 + g;
                int col = nt * 8 + 2 * q;
                *(float2*)&Pw[r * AST + col]       = make_float2(tf32r(p0), tf32r(p1));
                *(float2*)&Pw[(r + 8) * AST + col] = make_float2(tf32r(p2), tf32r(p3));
            }
        __syncwarp();
        __syncthreads();                 // all warps done reading K(t) and mask(t)

        if (t + 1 < NT) {
            LOAD_K(t + 1);
            asm volatile("cp.async.commit_group;" ::: "memory");
        }
        // complete V(t): pending {V(t), K(t+1)?}
        if (t + 1 < NT) { asm volatile("cp.async.wait_group 1;" ::: "memory"); }
        else            { asm volatile("cp.async.wait_group 0;" ::: "memory"); }
        __syncthreads();

        // ---- O += P~ V(t): A-frags from smem P, B-frags from V ----
        #pragma unroll
        for (int j = 0; j < 8; j++) {
            uint32_t pa0[4], pa1[4];
            ldsm4(pa0[0], pa0[1], pa0[2], pa0[3], pR + j * 32);
            ldsm4(pa1[0], pa1[1], pa1[2], pa1[3], pR + 16 * AST * 4 + j * 32);
            #pragma unroll
            for (int np = 0; np < 4; np++) {
                uint32_t b0, b1, b2, b3;
                ldsm4(b0, b1, b2, b3, bV + np * 16 * AST * 4 + j * 32);
                mma_tf32(O[0][2 * np],     pa0, b0, b1);
                mma_tf32(O[0][2 * np + 1], pa0, b2, b3);
                mma_tf32(O[1][2 * np],     pa1, b0, b1);
                mma_tf32(O[1][2 * np + 1], pa1, b2, b3);
            }
        }

        __syncthreads();                 // all warps done with V(t)
        if (t + 1 < NT) {
            LOAD_V(t + 1);
            asm volatile("cp.async.commit_group;" ::: "memory");
        }
    }

    // ---- row-sum reduce + epilogue (per 16-row half) ----
    #pragma unroll
    for (int mt = 0; mt < 2; mt++) {
        float l0 = lsum[mt][0], l1 = lsum[mt][1];
        l0 += __shfl_xor_sync(0xffffffffu, l0, 1);
        l0 += __shfl_xor_sync(0xffffffffu, l0, 2);
        l1 += __shfl_xor_sync(0xffffffffu, l1, 1);
        l1 += __shfl_xor_sync(0xffffffffu, l1, 2);
        float il0 = 1.0f / l0, il1 = 1.0f / l1;

        int row0 = q0 + wq0 + mt * 16 + g;
        size_t o0 = ((size_t)(b * LDIM + row0)) * DMODEL + h * DKH;
        #pragma unroll
        for (int nt = 0; nt < 8; nt++) {
            int col = nt * 8 + 2 * q;
            float2 v0 = make_float2(tf32r(O[mt][nt][0] * il0), tf32r(O[mt][nt][1] * il0));
            float2 v1 = make_float2(tf32r(O[mt][nt][2] * il1), tf32r(O[mt][nt][3] * il1));
            *(float2*)&out[o0 + col]              = v0;
            *(float2*)&out[o0 + 8 * DMODEL + col] = v1;
        }
    }
    #undef LOAD_K
    #undef LOAD_V
}

// ---------------------------------------------------------------------------
// Launch
// ---------------------------------------------------------------------------
extern "C" void kernel_launch(void* const* d_in, const int* in_sizes, int n_in,
                              void* d_out, int out_size)
{
    const float* x     = (const float*)d_in[0];
    const int*   mask  = (const int*)  d_in[1];
    const float* Wqkv  = (const float*)d_in[2];
    const float* bqkv  = (const float*)d_in[3];
    const float* Wout  = (const float*)d_in[4];
    const float* bout  = (const float*)d_in[5];
    float* out = (float*)d_out;

    float *qkv, *attn, *xr, *wqkvT, *woutT, *kc, *vtc;
    int *idx, *cmask, *cnt;
    cudaGetSymbolAddress((void**)&qkv,   g_qkv);
    cudaGetSymbolAddress((void**)&attn,  g_attn);
    cudaGetSymbolAddress((void**)&xr,    g_x);
    cudaGetSymbolAddress((void**)&wqkvT, g_wqkvT);
    cudaGetSymbolAddress((void**)&woutT, g_woutT);
    cudaGetSymbolAddress((void**)&kc,    g_kc);
    cudaGetSymbolAddress((void**)&vtc,   g_vtc);
    cudaGetSymbolAddress((void**)&idx,   g_idx);
    cudaGetSymbolAddress((void**)&cmask, g_cmask);
    cudaGetSymbolAddress((void**)&cnt,   g_cnt);

    cudaFuncSetAttribute(gemm_mma_kernel<true>,
                         cudaFuncAttributeMaxDynamicSharedMemorySize, GS_TOTAL);
    cudaFuncSetAttribute(gemm_mma_kernel<false>,
                         cudaFuncAttributeMaxDynamicSharedMemorySize, GS_TOTAL);
    cudaFuncSetAttribute(attn_mma_kernel,
                         cudaFuncAttributeMaxDynamicSharedMemorySize, ATTN_SM_BYTES);

    // Prep
    round_tf32_kernel<<<(ROWS * DMODEL / 4 + 255) / 256, 256>>>(x, xr, ROWS * DMODEL / 4);
    transpose_tf32_kernel<<<dim3(D3 / 32, GK / 32), dim3(32, 8)>>>(Wqkv, wqkvT, GK, D3);
    transpose_tf32_kernel<<<dim3(DMODEL / 32, GK / 32), dim3(32, 8)>>>(Wout, woutT, GK, DMODEL);
    mask_scan_kernel<<<BDIM, 256>>>(mask, idx, cnt);
    cmask_kernel<<<(BDIM * LDIM) / 256, 256>>>(cnt, cmask);

    // 1) QKV projection (tf32-rounded output)
    gemm_mma_kernel<true><<<dim3(D3 / 128, ROWS / 128), 128, GS_TOTAL>>>(
        xr, wqkvT, bqkv, qkv, D3);

    // 1b) Compact K and Vt by unmasked keys
    kgather_kernel<<<dim3(LDIM / 128, BDIM * HEADS), 128>>>(qkv, idx, cnt, kc);
    vtrans_gather_kernel<<<dim3(LDIM / 32, DKH / 32, BDIM * HEADS), dim3(32, 8)>>>(
        qkv, idx, cnt, vtc);

    // 2) Flash attention over compacted keys (all-tf32, shuffle-free PV)
    attn_mma_kernel<<<dim3(LDIM / ABQ, BDIM * HEADS), 128, ATTN_SM_BYTES>>>(
        qkv, kc, vtc, cmask, cnt, attn);

    // 3) Output projection (full-precision output)
    gemm_mma_kernel<false><<<dim3(DMODEL / 128, ROWS / 128), 128, GS_TOTAL>>>(
        attn, woutT, bout, out, DMODEL);
}

// round 15
// speedup vs baseline: 1.6356x; 1.1508x over previous
#include <cuda_runtime.h>
#include <math.h>
#include <stdint.h>

// Problem constants
#define BDIM   2
#define LDIM   2048
#define DMODEL 1024
#define HEADS  16
#define DKH    64
#define D3     (3 * DMODEL)
#define ROWS   (BDIM * LDIM)   // 4096
#define GK     1024            // K for all projection GEMMs

// Scratch (allocation-free: __device__ globals)
__device__ float g_q[(size_t)ROWS * DMODEL];     // Q [row][1024], tf32-rounded
__device__ float g_vc[(size_t)ROWS * DMODEL];    // compacted V rows [b*2048+j][1024]
__device__ float g_attn[(size_t)ROWS * DMODEL];  // [B,L,H,dk] (tf32-rounded)
__device__ float g_x[(size_t)ROWS * DMODEL];     // tf32-rounded x
__device__ float g_xc[(size_t)ROWS * DMODEL];    // compacted x rows
__device__ float g_wqkvT[(size_t)D3 * GK];       // [3072][1024] k-major, tf32-rounded
__device__ float g_woutT[(size_t)DMODEL * GK];   // [1024][1024] k-major, tf32-rounded
__device__ float g_kc[(size_t)BDIM * HEADS * LDIM * DKH];  // compacted K [bh][j][64]
__device__ float g_vtc[(size_t)BDIM * HEADS * DKH * LDIM]; // compacted Vt [bh][d][j]
__device__ int   g_idx[BDIM * LDIM];             // compacted key index list
__device__ int   g_cmask[BDIM * LDIM];           // compacted mask (1 for j<cnt)
__device__ int   g_cnt[BDIM];                    // unmasked count per batch

// ===========================================================================
// Helpers
// ===========================================================================
__device__ __forceinline__ float tf32r(float x) {
    uint32_t y;
    asm("cvt.rna.tf32.f32 %0, %1;" : "=r"(y) : "f"(x));
    return __uint_as_float(y);
}
__device__ __forceinline__ float ex2(float x) {
    float y;
    asm("ex2.approx.f32 %0, %1;" : "=f"(y) : "f"(x));
    return y;
}
__device__ __forceinline__ uint32_t smem_u32(const void* p) {
    uint32_t a;
    asm("{ .reg .u64 t; cvta.to.shared.u64 t, %1; cvt.u32.u64 %0, t; }" : "=r"(a) : "l"(p));
    return a;
}
#define SWZ128(x) ((x) ^ (((x) >> 3) & 0x70))

__device__ __forceinline__ void cp16(uint32_t dst, const void* src) {
    asm volatile("cp.async.cg.shared.global [%0], [%1], 16;" :: "r"(dst), "l"(src));
}
__device__ __forceinline__ void ldsm4(uint32_t& r0, uint32_t& r1, uint32_t& r2, uint32_t& r3,
                                      uint32_t addr) {
    asm volatile("ldmatrix.sync.aligned.m8n8.x4.shared.b16 {%0,%1,%2,%3}, [%4];"
                 : "=r"(r0), "=r"(r1), "=r"(r2), "=r"(r3) : "r"(addr));
}
__device__ __forceinline__ void mma_tf32(float* c, const uint32_t* a, uint32_t b0, uint32_t b1) {
    asm volatile("mma.sync.aligned.m16n8k8.row.col.f32.tf32.tf32.f32 "
                 "{%0,%1,%2,%3}, {%4,%5,%6,%7}, {%8,%9}, {%0,%1,%2,%3};"
                 : "+f"(c[0]), "+f"(c[1]), "+f"(c[2]), "+f"(c[3])
                 : "r"(a[0]), "r"(a[1]), "r"(a[2]), "r"(a[3]), "r"(b0), "r"(b1));
}

// ===========================================================================
// Prep kernels
// ===========================================================================
__global__ void round_tf32_kernel(const float* __restrict__ in, float* __restrict__ out, int n4) {
    int i = blockIdx.x * blockDim.x + threadIdx.x;
    if (i < n4) {
        float4 v = ((const float4*)in)[i];
        v.x = tf32r(v.x); v.y = tf32r(v.y); v.z = tf32r(v.z); v.w = tf32r(v.w);
        ((float4*)out)[i] = v;
    }
}

__global__ void transpose_tf32_kernel(const float* __restrict__ in, float* __restrict__ out,
                                      int K, int N) {
    __shared__ float t[32][33];
    int n0 = blockIdx.x * 32, k0 = blockIdx.y * 32;
    for (int j = threadIdx.y; j < 32; j += 8)
        t[j][threadIdx.x] = tf32r(in[(size_t)(k0 + j) * N + n0 + threadIdx.x]);
    __syncthreads();
    for (int j = threadIdx.y; j < 32; j += 8)
        out[(size_t)(n0 + j) * K + k0 + threadIdx.x] = t[threadIdx.x][j];
}

// Deterministic block scan: per-batch compacted index list + count.
__global__ void mask_scan_kernel(const int* __restrict__ mask,
                                 int* __restrict__ idx, int* __restrict__ cnt) {
    __shared__ int wsum[8];
    const int b = blockIdx.x;
    const int* m = mask + b * LDIM;
    const int t = threadIdx.x;
    const int base = t * 8;
    int v[8], s = 0;
    #pragma unroll
    for (int i = 0; i < 8; i++) { v[i] = m[base + i]; s += v[i]; }
    const int lane = t & 31, wid = t >> 5;
    int pre = s;
    #pragma unroll
    for (int o = 1; o < 32; o <<= 1) {
        int x = __shfl_up_sync(0xffffffffu, pre, o);
        if (lane >= o) pre += x;
    }
    if (lane == 31) wsum[wid] = pre;
    __syncthreads();
    int woff = 0;
    for (int i = 0; i < wid; i++) woff += wsum[i];
    int off = woff + pre - s;
    #pragma unroll
    for (int i = 0; i < 8; i++)
        if (v[i]) idx[b * LDIM + off++] = base + i;
    if (t == 255) cnt[b] = woff + pre;
}

// cmask[b][j] = (j < cnt[b])
__global__ void cmask_kernel(const int* __restrict__ cnt, int* __restrict__ cmask) {
    int i = blockIdx.x * 256 + threadIdx.x;
    int b = i >> 11, j = i & (LDIM - 1);
    cmask[i] = (j < cnt[b]) ? 1 : 0;
}

// Gather compacted x rows (zero-pad to 128-multiple). grid 4096, block 256.
__global__ void xgather_kernel(const float* __restrict__ xr, const int* __restrict__ idx,
                               const int* __restrict__ cnt, float* __restrict__ xc) {
    int row = blockIdx.x;
    int b = row >> 11, j = row & (LDIM - 1);
    int c = cnt[b];
    int cp = (c + 127) & ~127;
    if (j >= cp) return;
    float4* dst = (float4*)(xc + (size_t)row * DMODEL);
    if (j < c) {
        const float4* src = (const float4*)(xr
            + (size_t)(b * LDIM + idx[b * LDIM + j]) * DMODEL);
        dst[threadIdx.x] = src[threadIdx.x];
    } else {
        dst[threadIdx.x] = make_float4(0.f, 0.f, 0.f, 0.f);
    }
}

// Compacted V transpose: vtc[bh][d][j] from vc[b*2048+j][h*64+d]. block (32,8)
__global__ void vtrans_c_kernel(const float* __restrict__ vc, const int* __restrict__ cnt,
                                float* __restrict__ vtc) {
    __shared__ float t[32][33];
    int j0 = blockIdx.x * 32, d0 = blockIdx.y * 32;
    int bh = blockIdx.z;
    int b  = bh >> 4, h = bh & 15;
    int cp = (cnt[b] + 127) & ~127;
    if (j0 >= cp) return;
    const float* src = vc + (size_t)b * LDIM * DMODEL + h * DKH;
    for (int j = threadIdx.y; j < 32; j += 8)
        t[j][threadIdx.x] = src[(size_t)(j0 + j) * DMODEL + d0 + threadIdx.x];
    __syncthreads();
    float* dst = vtc + ((size_t)bh * DKH) * LDIM;
    for (int j = threadIdx.y; j < 32; j += 8)
        dst[(size_t)(d0 + j) * LDIM + j0 + threadIdx.x] = t[threadIdx.x][j];
}

// ===========================================================================
// tf32 mma.sync GEMM (R12-validated): 128 threads, 4 warps of 64x64,
// 3-stage cp.async pipeline, one __syncthreads per K-chunk.
// ===========================================================================
#define GBK    32
#define GTILE  (128 * GBK * 4)          // 16KB per operand tile
#define GSTG   3
#define GS_TOTAL (GSTG * 2 * GTILE)     // 96KB

__device__ __forceinline__ void gemm_load_tile(const float* __restrict__ src, int row0, int k0,
                                               uint32_t smemBase, int tid) {
    #pragma unroll
    for (int j = 0; j < 8; j++) {
        int i   = tid + j * 128;
        int row = i >> 3;
        int c   = i & 7;
        cp16(smemBase + SWZ128(row * 128 + c * 16),
             src + (size_t)(row0 + row) * GK + k0 + c * 4);
    }
}

// Shared mainloop: accumulates the 64x64 warp tile into acc[32][4].
__device__ __forceinline__ void gemm_mainloop(
    const float* __restrict__ A, const float* __restrict__ Bt,
    uint32_t sb, int tid, int m0, int n0, int aOff, int bOff, float acc[32][4])
{
    gemm_load_tile(A,  m0, 0, sb, tid);
    gemm_load_tile(Bt, n0, 0, sb + GTILE, tid);
    asm volatile("cp.async.commit_group;" ::: "memory");
    gemm_load_tile(A,  m0, GBK, sb + 2 * GTILE, tid);
    gemm_load_tile(Bt, n0, GBK, sb + 3 * GTILE, tid);
    asm volatile("cp.async.commit_group;" ::: "memory");

    const int NCHUNK = GK / GBK;   // 32
    for (int c = 0; c < NCHUNK; c++) {
        if (c < NCHUNK - 1) { asm volatile("cp.async.wait_group 1;" ::: "memory"); }
        else                { asm volatile("cp.async.wait_group 0;" ::: "memory"); }
        __syncthreads();

        if (c + 2 < NCHUNK) {
            const uint32_t sp = sb + ((c + 2) % GSTG) * 2 * GTILE;
            gemm_load_tile(A,  m0, (c + 2) * GBK, sp, tid);
            gemm_load_tile(Bt, n0, (c + 2) * GBK, sp + GTILE, tid);
            asm volatile("cp.async.commit_group;" ::: "memory");
        }

        const uint32_t ba = sb + (c % GSTG) * 2 * GTILE;
        const uint32_t bb = ba + GTILE;
        #pragma unroll
        for (int ks = 0; ks < 4; ks++) {
            uint32_t a[4][4], b[4][4];
            #pragma unroll
            for (int mt = 0; mt < 4; mt++)
                ldsm4(a[mt][0], a[mt][1], a[mt][2], a[mt][3],
                      ba + SWZ128(aOff + mt * 2048 + ks * 32));
            #pragma unroll
            for (int np = 0; np < 4; np++)
                ldsm4(b[np][0], b[np][1], b[np][2], b[np][3],
                      bb + SWZ128(bOff + np * 2048 + ks * 32));
            #pragma unroll
            for (int mt = 0; mt < 4; mt++)
                #pragma unroll
                for (int nt = 0; nt < 8; nt++)
                    mma_tf32(acc[mt * 8 + nt], a[mt],
                             b[nt >> 1][(nt & 1) * 2], b[nt >> 1][(nt & 1) * 2 + 1]);
        }
    }
}

template<bool RND>
__global__ __launch_bounds__(128, 2) void gemm_mma_kernel(
    const float* __restrict__ A, const float* __restrict__ Bt,
    const float* __restrict__ bias, float* __restrict__ C, int N)
{
    extern __shared__ char smc[];
    const uint32_t sb = smem_u32(smc);
    const int tid  = threadIdx.x;
    const int lane = tid & 31;
    const int w    = tid >> 5;
    const int m0   = blockIdx.y * 128;
    const int n0   = blockIdx.x * 128;
    const int wm   = (w & 1) * 64;
    const int wn   = (w >> 1) * 64;

    const int aOff = (wm + (lane & 15)) * 128 + ((lane >> 4) << 4);
    const int bOff = (wn + ((lane >> 4) << 3) + (lane & 7)) * 128 + (((lane >> 3) & 1) << 4);

    float acc[32][4];
    #pragma unroll
    for (int t = 0; t < 32; t++)
        #pragma unroll
        for (int j = 0; j < 4; j++) acc[t][j] = 0.0f;

    gemm_mainloop(A, Bt, sb, tid, m0, n0, aOff, bOff, acc);

    #pragma unroll
    for (int mt = 0; mt < 4; mt++) {
        #pragma unroll
        for (int nt = 0; nt < 8; nt++) {
            const float* cc = acc[mt * 8 + nt];
            int row = m0 + wm + mt * 16 + (lane >> 2);
            int col = n0 + wn + nt * 8 + (lane & 3) * 2;
            float2 bv = *(const float2*)&bias[col];
            float2 o0 = make_float2(cc[0] + bv.x, cc[1] + bv.y);
            float2 o1 = make_float2(cc[2] + bv.x, cc[3] + bv.y);
            if (RND) {
                o0.x = tf32r(o0.x); o0.y = tf32r(o0.y);
                o1.x = tf32r(o1.x); o1.y = tf32r(o1.y);
            }
            *(float2*)&C[(size_t)row * N + col]       = o0;
            *(float2*)&C[(size_t)(row + 8) * N + col] = o1;
        }
    }
}

// KV projection over compacted rows. A = xc; Bt = wqkvT + 1024*GK; N = 2048.
// Early-exits row blocks past ceil128(cnt). K cols -> kc[bh][j][64]; V -> vc.
__global__ __launch_bounds__(128, 2) void gemm_kv_kernel(
    const float* __restrict__ A, const float* __restrict__ Bt,
    const float* __restrict__ bias, const int* __restrict__ cnt,
    float* __restrict__ kc, float* __restrict__ vc)
{
    const int m0 = blockIdx.y * 128;
    const int bb = m0 >> 11;
    const int j0 = m0 & (LDIM - 1);
    const int cp = (cnt[bb] + 127) & ~127;
    if (j0 >= cp) return;

    extern __shared__ char smc[];
    const uint32_t sb = smem_u32(smc);
    const int tid  = threadIdx.x;
    const int lane = tid & 31;
    const int w    = tid >> 5;
    const int n0   = blockIdx.x * 128;
    const int wm   = (w & 1) * 64;
    const int wn   = (w >> 1) * 64;

    const int aOff = (wm + (lane & 15)) * 128 + ((lane >> 4) << 4);
    const int bOff = (wn + ((lane >> 4) << 3) + (lane & 7)) * 128 + (((lane >> 3) & 1) << 4);

    float acc[32][4];
    #pragma unroll
    for (int t = 0; t < 32; t++)
        #pragma unroll
        for (int j = 0; j < 4; j++) acc[t][j] = 0.0f;

    gemm_mainloop(A, Bt, sb, tid, m0, n0, aOff, bOff, acc);

    #pragma unroll
    for (int mt = 0; mt < 4; mt++) {
        #pragma unroll
        for (int nt = 0; nt < 8; nt++) {
            const float* cc = acc[mt * 8 + nt];
            int row = m0 + wm + mt * 16 + (lane >> 2);
            int col = n0 + wn + nt * 8 + (lane & 3) * 2;
            float2 bv = *(const float2*)&bias[col];
            float2 o0 = make_float2(tf32r(cc[0] + bv.x), tf32r(cc[1] + bv.y));
            float2 o1 = make_float2(tf32r(cc[2] + bv.x), tf32r(cc[3] + bv.y));
            int b = row >> 11, j = row & (LDIM - 1);
            if (col < DMODEL) {   // K -> kc[bh][j][64]
                int h = col >> 6, d = col & 63;
                size_t o = (((size_t)(b * HEADS + h)) * LDIM) * DKH + d;
                *(float2*)&kc[o + (size_t)j * DKH]       = o0;
                *(float2*)&kc[o + (size_t)(j + 8) * DKH] = o1;
            } else {              // V -> vc[row][col-1024]
                int c2 = col - DMODEL;
                *(float2*)&vc[(size_t)row * DMODEL + c2]       = o0;
                *(float2*)&vc[(size_t)(row + 8) * DMODEL + c2] = o1;
            }
        }
    }
}

// ===========================================================================
// Tensor-core flash attention over COMPACTED keys (R14-validated core).
// Q from dense g_q [row][1024]; kc/vtc/cmask as before.
// ===========================================================================
#define ABQ 128
#define ABK 64
#define AST 68
#define AQS_F 0
#define AKS_F (ABQ * AST)            // 8704
#define AVS_F (AKS_F + ABK * AST)    // 13056
#define APS_F (AVS_F + ABK * AST)    // 17408
#define AMS_F (APS_F + ABQ * AST)    // 26112
#define ATTN_SM_BYTES (AMS_F * 4 + 256)   // 104704
#define EXPC 0.18033688011112042f   // 0.125 * log2(e)

__global__ void __launch_bounds__(128, 2) attn_mma_kernel(
    const float* __restrict__ gq, const float* __restrict__ kc,
    const float* __restrict__ vtc, const int* __restrict__ cmask,
    const int* __restrict__ cnt, float* __restrict__ out)
{
    extern __shared__ float smf[];
    const uint32_t sb = smem_u32(smf);

    const int tid  = threadIdx.x;
    const int lane = tid & 31;
    const int w    = tid >> 5;
    const int g    = lane >> 2;
    const int q    = lane & 3;
    const int b    = blockIdx.y >> 4;
    const int h    = blockIdx.y & 15;
    const int q0   = blockIdx.x * ABQ;
    const int wq0  = w * 32;

    const size_t qbase = (size_t)(b * LDIM + q0) * DMODEL + h * DKH;
    const float* kcb  = kc  + (size_t)blockIdx.y * LDIM * DKH;
    const float* vtb  = vtc + ((size_t)blockIdx.y * DKH) * LDIM;
    const int*   mkb  = cmask + b * LDIM;
    const int NT = (__ldg(&cnt[b]) + ABK - 1) >> 6;

    for (int i = tid; i < ABQ * 16; i += 128) {
        int r = i >> 4, c4 = (i & 15) * 4;
        cp16(sb + (AQS_F + r * AST + c4) * 4, &gq[qbase + (size_t)r * DMODEL + c4]);
    }
    #define LOAD_K(t) do {                                                           \
        int _k0 = (t) * ABK;                                                         \
        for (int _i = tid; _i < ABK * 16; _i += 128) {                               \
            int _r = _i >> 4, _c4 = (_i & 15) * 4;                                   \
            cp16(sb + (AKS_F + _r * AST + _c4) * 4,                                  \
                 &kcb[(size_t)(_k0 + _r) * DKH + _c4]);                              \
        }                                                                            \
        if (tid < 16) cp16(sb + AMS_F * 4 + tid * 16, &mkb[_k0 + tid * 4]);          \
    } while (0)
    #define LOAD_V(t) do {                                                           \
        int _k0 = (t) * ABK;                                                         \
        for (int _i = tid; _i < ABK * 16; _i += 128) {                               \
            int _r = _i >> 4, _c4 = (_i & 15) * 4;                                   \
            cp16(sb + (AVS_F + _r * AST + _c4) * 4,                                  \
                 &vtb[(size_t)_r * LDIM + _k0 + _c4]);                               \
        }                                                                            \
    } while (0)

    LOAD_K(0);
    asm volatile("cp.async.commit_group;" ::: "memory");
    LOAD_V(0);
    asm volatile("cp.async.commit_group;" ::: "memory");

    float O[2][8][4];
    #pragma unroll
    for (int mt = 0; mt < 2; mt++)
        #pragma unroll
        for (int t = 0; t < 8; t++)
            #pragma unroll
            for (int j = 0; j < 4; j++) O[mt][t][j] = 0.0f;
    float lsum[2][2] = {{0.0f, 0.0f}, {0.0f, 0.0f}};

    const uint32_t aAddr = sb + (AQS_F + (wq0 + (lane & 15)) * AST) * 4 + ((lane >> 4) << 4);
    const uint32_t bRowO = (((lane >> 4) << 3) + (lane & 7)) * AST;
    const uint32_t bK    = sb + (AKS_F + bRowO) * 4 + (((lane >> 3) & 1) << 4);
    const uint32_t bV    = sb + (AVS_F + bRowO) * 4 + (((lane >> 3) & 1) << 4);
    float*         Pw    = smf + APS_F + w * 32 * AST;
    const uint32_t pR    = sb + (APS_F + (w * 32 + (lane & 15)) * AST) * 4
                              + ((lane >> 4) << 4);
    const int* ms = (const int*)((const char*)smf + AMS_F * 4);

    for (int t = 0; t < NT; t++) {
        asm volatile("cp.async.wait_group 1;" ::: "memory");
        __syncthreads();

        float S[2][8][4];
        #pragma unroll
        for (int nt = 0; nt < 8; nt++) {
            int2 mk = *(const int2*)&ms[nt * 8 + 2 * q];
            float bx = mk.x ? 0.0f : -3.0e38f;
            float by = mk.y ? 0.0f : -3.0e38f;
            S[0][nt][0] = bx; S[0][nt][1] = by; S[0][nt][2] = bx; S[0][nt][3] = by;
            S[1][nt][0] = bx; S[1][nt][1] = by; S[1][nt][2] = bx; S[1][nt][3] = by;
        }
        #pragma unroll
        for (int ks = 0; ks < 8; ks++) {
            uint32_t av0[4], av1[4];
            ldsm4(av0[0], av0[1], av0[2], av0[3], aAddr + ks * 32);
            ldsm4(av1[0], av1[1], av1[2], av1[3], aAddr + 16 * AST * 4 + ks * 32);
            #pragma unroll
            for (int ntp = 0; ntp < 4; ntp++) {
                uint32_t b0, b1, b2, b3;
                ldsm4(b0, b1, b2, b3, bK + ntp * 16 * AST * 4 + ks * 32);
                mma_tf32(S[0][2 * ntp],     av0, b0, b1);
                mma_tf32(S[0][2 * ntp + 1], av0, b2, b3);
                mma_tf32(S[1][2 * ntp],     av1, b0, b1);
                mma_tf32(S[1][2 * ntp + 1], av1, b2, b3);
            }
        }

        #pragma unroll
        for (int mt = 0; mt < 2; mt++)
            #pragma unroll
            for (int nt = 0; nt < 8; nt++) {
                float p0 = ex2(S[mt][nt][0] * EXPC);
                float p1 = ex2(S[mt][nt][1] * EXPC);
                float p2 = ex2(S[mt][nt][2] * EXPC);
                float p3 = ex2(S[mt][nt][3] * EXPC);
                lsum[mt][0] += p0 + p1;
                lsum[mt][1] += p2 + p3;
                int r = mt * 16 + g;
                int col = nt * 8 + 2 * q;
                *(float2*)&Pw[r * AST + col]       = make_float2(tf32r(p0), tf32r(p1));
                *(float2*)&Pw[(r + 8) * AST + col] = make_float2(tf32r(p2), tf32r(p3));
            }
        __syncwarp();
        __syncthreads();

        if (t + 1 < NT) {
            LOAD_K(t + 1);
            asm volatile("cp.async.commit_group;" ::: "memory");
        }
        if (t + 1 < NT) { asm volatile("cp.async.wait_group 1;" ::: "memory"); }
        else            { asm volatile("cp.async.wait_group 0;" ::: "memory"); }
        __syncthreads();

        #pragma unroll
        for (int j = 0; j < 8; j++) {
            uint32_t pa0[4], pa1[4];
            ldsm4(pa0[0], pa0[1], pa0[2], pa0[3], pR + j * 32);
            ldsm4(pa1[0], pa1[1], pa1[2], pa1[3], pR + 16 * AST * 4 + j * 32);
            #pragma unroll
            for (int np = 0; np < 4; np++) {
                uint32_t b0, b1, b2, b3;
                ldsm4(b0, b1, b2, b3, bV + np * 16 * AST * 4 + j * 32);
                mma_tf32(O[0][2 * np],     pa0, b0, b1);
                mma_tf32(O[0][2 * np + 1], pa0, b2, b3);
                mma_tf32(O[1][2 * np],     pa1, b0, b1);
                mma_tf32(O[1][2 * np + 1], pa1, b2, b3);
            }
        }

        __syncthreads();
        if (t + 1 < NT) {
            LOAD_V(t + 1);
            asm volatile("cp.async.commit_group;" ::: "memory");
        }
    }

    #pragma unroll
    for (int mt = 0; mt < 2; mt++) {
        float l0 = lsum[mt][0], l1 = lsum[mt][1];
        l0 += __shfl_xor_sync(0xffffffffu, l0, 1);
        l0 += __shfl_xor_sync(0xffffffffu, l0, 2);
        l1 += __shfl_xor_sync(0xffffffffu, l1, 1);
        l1 += __shfl_xor_sync(0xffffffffu, l1, 2);
        float il0 = 1.0f / l0, il1 = 1.0f / l1;

        int row0 = q0 + wq0 + mt * 16 + g;
        size_t o0 = ((size_t)(b * LDIM + row0)) * DMODEL + h * DKH;
        #pragma unroll
        for (int nt = 0; nt < 8; nt++) {
            int col = nt * 8 + 2 * q;
            float2 v0 = make_float2(tf32r(O[mt][nt][0] * il0), tf32r(O[mt][nt][1] * il0));
            float2 v1 = make_float2(tf32r(O[mt][nt][2] * il1), tf32r(O[mt][nt][3] * il1));
            *(float2*)&out[o0 + col]              = v0;
            *(float2*)&out[o0 + 8 * DMODEL + col] = v1;
        }
    }
    #undef LOAD_K
    #undef LOAD_V
}

// ---------------------------------------------------------------------------
// Launch
// ---------------------------------------------------------------------------
extern "C" void kernel_launch(void* const* d_in, const int* in_sizes, int n_in,
                              void* d_out, int out_size)
{
    const float* x     = (const float*)d_in[0];
    const int*   mask  = (const int*)  d_in[1];
    const float* Wqkv  = (const float*)d_in[2];
    const float* bqkv  = (const float*)d_in[3];
    const float* Wout  = (const float*)d_in[4];
    const float* bout  = (const float*)d_in[5];
    float* out = (float*)d_out;

    float *gq, *vc, *attn, *xr, *xc, *wqkvT, *woutT, *kc, *vtc;
    int *idx, *cmask, *cnt;
    cudaGetSymbolAddress((void**)&gq,    g_q);
    cudaGetSymbolAddress((void**)&vc,    g_vc);
    cudaGetSymbolAddress((void**)&attn,  g_attn);
    cudaGetSymbolAddress((void**)&xr,    g_x);
    cudaGetSymbolAddress((void**)&xc,    g_xc);
    cudaGetSymbolAddress((void**)&wqkvT, g_wqkvT);
    cudaGetSymbolAddress((void**)&woutT, g_woutT);
    cudaGetSymbolAddress((void**)&kc,    g_kc);
    cudaGetSymbolAddress((void**)&vtc,   g_vtc);
    cudaGetSymbolAddress((void**)&idx,   g_idx);
    cudaGetSymbolAddress((void**)&cmask, g_cmask);
    cudaGetSymbolAddress((void**)&cnt,   g_cnt);

    cudaFuncSetAttribute(gemm_mma_kernel<true>,
                         cudaFuncAttributeMaxDynamicSharedMemorySize, GS_TOTAL);
    cudaFuncSetAttribute(gemm_mma_kernel<false>,
                         cudaFuncAttributeMaxDynamicSharedMemorySize, GS_TOTAL);
    cudaFuncSetAttribute(gemm_kv_kernel,
                         cudaFuncAttributeMaxDynamicSharedMemorySize, GS_TOTAL);
    cudaFuncSetAttribute(attn_mma_kernel,
                         cudaFuncAttributeMaxDynamicSharedMemorySize, ATTN_SM_BYTES);

    // Prep
    round_tf32_kernel<<<(ROWS * DMODEL / 4 + 255) / 256, 256>>>(x, xr, ROWS * DMODEL / 4);
    transpose_tf32_kernel<<<dim3(D3 / 32, GK / 32), dim3(32, 8)>>>(Wqkv, wqkvT, GK, D3);
    transpose_tf32_kernel<<<dim3(DMODEL / 32, GK / 32), dim3(32, 8)>>>(Wout, woutT, GK, DMODEL);
    mask_scan_kernel<<<BDIM, 256>>>(mask, idx, cnt);
    cmask_kernel<<<(BDIM * LDIM) / 256, 256>>>(cnt, cmask);
    xgather_kernel<<<ROWS, 256>>>(xr, idx, cnt, xc);

    // 1a) Q projection: all rows x N=1024
    gemm_mma_kernel<true><<<dim3(DMODEL / 128, ROWS / 128), 128, GS_TOTAL>>>(
        xr, wqkvT, bqkv, gq, DMODEL);

    // 1b) KV projection over compacted rows: N=2048, early-exit past cnt
    gemm_kv_kernel<<<dim3(2 * DMODEL / 128, ROWS / 128), 128, GS_TOTAL>>>(
        xc, wqkvT + (size_t)DMODEL * GK, bqkv + DMODEL, cnt, kc, vc);

    // 1c) Compacted V transpose
    vtrans_c_kernel<<<dim3(LDIM / 32, DKH / 32, BDIM * HEADS), dim3(32, 8)>>>(
        vc, cnt, vtc);

    // 2) Flash attention over compacted keys
    attn_mma_kernel<<<dim3(LDIM / ABQ, BDIM * HEADS), 128, ATTN_SM_BYTES>>>(
        gq, kc, vtc, cmask, cnt, attn);

    // 3) Output projection (full-precision output)
    gemm_mma_kernel<false><<<dim3(DMODEL / 128, ROWS / 128), 128, GS_TOTAL>>>(
        attn, woutT, bout, out, DMODEL);
}

// round 16
// speedup vs baseline: 1.7008x; 1.0399x over previous
#include <cuda_runtime.h>
#include <math.h>
#include <stdint.h>

// Problem constants
#define BDIM   2
#define LDIM   2048
#define DMODEL 1024
#define HEADS  16
#define DKH    64
#define D3     (3 * DMODEL)
#define ROWS   (BDIM * LDIM)   // 4096
#define GK     1024            // K for all projection GEMMs

// Scratch (allocation-free: __device__ globals)
__device__ float g_q[(size_t)ROWS * DMODEL];     // Q [row][1024], tf32-rounded
__device__ float g_vc[(size_t)ROWS * DMODEL];    // compacted V rows [b*2048+j][1024]
__device__ float g_attn[(size_t)ROWS * DMODEL];  // [B,L,H,dk] (tf32-rounded)
__device__ float g_x[(size_t)ROWS * DMODEL];     // tf32-rounded x
__device__ float g_xc[(size_t)ROWS * DMODEL];    // compacted x rows
__device__ float g_wqkvT[(size_t)D3 * GK];       // [3072][1024] k-major, tf32-rounded
__device__ float g_woutT[(size_t)DMODEL * GK];   // [1024][1024] k-major, tf32-rounded
__device__ float g_kc[(size_t)BDIM * HEADS * LDIM * DKH];  // compacted K [bh][j][64]
__device__ float g_vtc[(size_t)BDIM * HEADS * DKH * LDIM]; // compacted Vt [bh][d][j]
__device__ int   g_idx[BDIM * LDIM];             // compacted key index list
__device__ int   g_cmask[BDIM * LDIM];           // compacted mask (1 for j<cnt)
__device__ int   g_cnt[BDIM];                    // unmasked count per batch

// ===========================================================================
// Helpers
// ===========================================================================
__device__ __forceinline__ float tf32r(float x) {
    uint32_t y;
    asm("cvt.rna.tf32.f32 %0, %1;" : "=r"(y) : "f"(x));
    return __uint_as_float(y);
}
__device__ __forceinline__ float ex2(float x) {
    float y;
    asm("ex2.approx.f32 %0, %1;" : "=f"(y) : "f"(x));
    return y;
}
__device__ __forceinline__ uint32_t smem_u32(const void* p) {
    uint32_t a;
    asm("{ .reg .u64 t; cvta.to.shared.u64 t, %1; cvt.u32.u64 %0, t; }" : "=r"(a) : "l"(p));
    return a;
}
#define SWZ128(x) ((x) ^ (((x) >> 3) & 0x70))

__device__ __forceinline__ void cp16(uint32_t dst, const void* src) {
    asm volatile("cp.async.cg.shared.global [%0], [%1], 16;" :: "r"(dst), "l"(src));
}
__device__ __forceinline__ void ldsm4(uint32_t& r0, uint32_t& r1, uint32_t& r2, uint32_t& r3,
                                      uint32_t addr) {
    asm volatile("ldmatrix.sync.aligned.m8n8.x4.shared.b16 {%0,%1,%2,%3}, [%4];"
                 : "=r"(r0), "=r"(r1), "=r"(r2), "=r"(r3) : "r"(addr));
}
__device__ __forceinline__ void mma_tf32(float* c, const uint32_t* a, uint32_t b0, uint32_t b1) {
    asm volatile("mma.sync.aligned.m16n8k8.row.col.f32.tf32.tf32.f32 "
                 "{%0,%1,%2,%3}, {%4,%5,%6,%7}, {%8,%9}, {%0,%1,%2,%3};"
                 : "+f"(c[0]), "+f"(c[1]), "+f"(c[2]), "+f"(c[3])
                 : "r"(a[0]), "r"(a[1]), "r"(a[2]), "r"(a[3]), "r"(b0), "r"(b1));
}

// ===========================================================================
// Fused prep kernel: role by blockIdx.x, 256 threads each.
//  [0,4096)        : tf32-round x -> xr            (1 float4/thread)
//  [4096,7168)     : Wqkv [1024][3072] -> wqkvT [3072][1024] (32x32 tiles)
//  [7168,8192)     : Wout [1024][1024] -> woutT   (32x32 tiles)
//  [8192,8194)     : per-batch mask scan -> idx/cnt, then cmask
// ===========================================================================
__global__ __launch_bounds__(256) void prep_fused_kernel(
    const float* __restrict__ x, const float* __restrict__ Wqkv,
    const float* __restrict__ Wout, const int* __restrict__ mask,
    float* __restrict__ xr, float* __restrict__ wqkvT, float* __restrict__ woutT,
    int* __restrict__ idx, int* __restrict__ cnt, int* __restrict__ cmask)
{
    __shared__ float tsh[32][33];
    __shared__ int wsum[8];
    __shared__ int total_s;

    const int blk = blockIdx.x;
    const int tid = threadIdx.x;

    if (blk < 4096) {                       // round x
        int i = blk * 256 + tid;
        float4 v = ((const float4*)x)[i];
        v.x = tf32r(v.x); v.y = tf32r(v.y); v.z = tf32r(v.z); v.w = tf32r(v.w);
        ((float4*)xr)[i] = v;
    } else if (blk < 8192) {                // weight transpose (K=1024 both)
        const float* in;
        float* out;
        int n0, k0, N;
        if (blk < 7168) {                   // Wqkv: tiles (96 x 32)
            int t = blk - 4096;
            in = Wqkv; out = wqkvT; N = D3;
            n0 = (t % 96) * 32; k0 = (t / 96) * 32;
        } else {                            // Wout: tiles (32 x 32)
            int t = blk - 7168;
            in = Wout; out = woutT; N = DMODEL;
            n0 = (t % 32) * 32; k0 = (t / 32) * 32;
        }
        int tx = tid & 31, ty = tid >> 5;
        for (int j = ty; j < 32; j += 8)
            tsh[j][tx] = tf32r(in[(size_t)(k0 + j) * N + n0 + tx]);
        __syncthreads();
        for (int j = ty; j < 32; j += 8)
            out[(size_t)(n0 + j) * GK + k0 + tx] = tsh[tx][j];
    } else {                                // mask scan + cmask, batch b
        const int b = blk - 8192;
        const int* m = mask + b * LDIM;
        const int base = tid * 8;
        int v[8], s = 0;
        #pragma unroll
        for (int i = 0; i < 8; i++) { v[i] = m[base + i]; s += v[i]; }
        const int lane = tid & 31, wid = tid >> 5;
        int pre = s;
        #pragma unroll
        for (int o = 1; o < 32; o <<= 1) {
            int xk = __shfl_up_sync(0xffffffffu, pre, o);
            if (lane >= o) pre += xk;
        }
        if (lane == 31) wsum[wid] = pre;
        __syncthreads();
        int woff = 0;
        for (int i = 0; i < wid; i++) woff += wsum[i];
        int off = woff + pre - s;
        #pragma unroll
        for (int i = 0; i < 8; i++)
            if (v[i]) idx[b * LDIM + off++] = base + i;
        if (tid == 255) { cnt[b] = woff + pre; total_s = woff + pre; }
        __syncthreads();
        int tot = total_s;
        for (int k = tid; k < LDIM; k += 256)
            cmask[b * LDIM + k] = (k < tot) ? 1 : 0;
    }
}

// Gather compacted x rows (zero-pad to 128-multiple). grid 4096, block 256.
__global__ void xgather_kernel(const float* __restrict__ xr, const int* __restrict__ idx,
                               const int* __restrict__ cnt, float* __restrict__ xc) {
    int row = blockIdx.x;
    int b = row >> 11, j = row & (LDIM - 1);
    int c = cnt[b];
    int cp = (c + 127) & ~127;
    if (j >= cp) return;
    float4* dst = (float4*)(xc + (size_t)row * DMODEL);
    if (j < c) {
        const float4* src = (const float4*)(xr
            + (size_t)(b * LDIM + idx[b * LDIM + j]) * DMODEL);
        dst[threadIdx.x] = src[threadIdx.x];
    } else {
        dst[threadIdx.x] = make_float4(0.f, 0.f, 0.f, 0.f);
    }
}

// Compacted V transpose: vtc[bh][d][j] from vc[b*2048+j][h*64+d]. block (32,8)
__global__ void vtrans_c_kernel(const float* __restrict__ vc, const int* __restrict__ cnt,
                                float* __restrict__ vtc) {
    __shared__ float t[32][33];
    int j0 = blockIdx.x * 32, d0 = blockIdx.y * 32;
    int bh = blockIdx.z;
    int b  = bh >> 4, h = bh & 15;
    int cp = (cnt[b] + 127) & ~127;
    if (j0 >= cp) return;
    const float* src = vc + (size_t)b * LDIM * DMODEL + h * DKH;
    for (int j = threadIdx.y; j < 32; j += 8)
        t[j][threadIdx.x] = src[(size_t)(j0 + j) * DMODEL + d0 + threadIdx.x];
    __syncthreads();
    float* dst = vtc + ((size_t)bh * DKH) * LDIM;
    for (int j = threadIdx.y; j < 32; j += 8)
        dst[(size_t)(d0 + j) * LDIM + j0 + threadIdx.x] = t[threadIdx.x][j];
}

// ===========================================================================
// tf32 mma.sync GEMM core (R12-validated): 128 threads, 4 warps of 64x64,
// 3-stage cp.async pipeline, one __syncthreads per K-chunk.
// ===========================================================================
#define GBK    32
#define GTILE  (128 * GBK * 4)          // 16KB per operand tile
#define GSTG   3
#define GS_TOTAL (GSTG * 2 * GTILE)     // 96KB

__device__ __forceinline__ void gemm_load_tile(const float* __restrict__ src, int row0, int k0,
                                               uint32_t smemBase, int tid) {
    #pragma unroll
    for (int j = 0; j < 8; j++) {
        int i   = tid + j * 128;
        int row = i >> 3;
        int c   = i & 7;
        cp16(smemBase + SWZ128(row * 128 + c * 16),
             src + (size_t)(row0 + row) * GK + k0 + c * 4);
    }
}

__device__ __forceinline__ void gemm_mainloop(
    const float* __restrict__ A, const float* __restrict__ Bt,
    uint32_t sb, int tid, int m0, int n0, int aOff, int bOff, float acc[32][4])
{
    gemm_load_tile(A,  m0, 0, sb, tid);
    gemm_load_tile(Bt, n0, 0, sb + GTILE, tid);
    asm volatile("cp.async.commit_group;" ::: "memory");
    gemm_load_tile(A,  m0, GBK, sb + 2 * GTILE, tid);
    gemm_load_tile(Bt, n0, GBK, sb + 3 * GTILE, tid);
    asm volatile("cp.async.commit_group;" ::: "memory");

    const int NCHUNK = GK / GBK;   // 32
    for (int c = 0; c < NCHUNK; c++) {
        if (c < NCHUNK - 1) { asm volatile("cp.async.wait_group 1;" ::: "memory"); }
        else                { asm volatile("cp.async.wait_group 0;" ::: "memory"); }
        __syncthreads();

        if (c + 2 < NCHUNK) {
            const uint32_t sp = sb + ((c + 2) % GSTG) * 2 * GTILE;
            gemm_load_tile(A,  m0, (c + 2) * GBK, sp, tid);
            gemm_load_tile(Bt, n0, (c + 2) * GBK, sp + GTILE, tid);
            asm volatile("cp.async.commit_group;" ::: "memory");
        }

        const uint32_t ba = sb + (c % GSTG) * 2 * GTILE;
        const uint32_t bb = ba + GTILE;
        #pragma unroll
        for (int ks = 0; ks < 4; ks++) {
            uint32_t a[4][4], b[4][4];
            #pragma unroll
            for (int mt = 0; mt < 4; mt++)
                ldsm4(a[mt][0], a[mt][1], a[mt][2], a[mt][3],
                      ba + SWZ128(aOff + mt * 2048 + ks * 32));
            #pragma unroll
            for (int np = 0; np < 4; np++)
                ldsm4(b[np][0], b[np][1], b[np][2], b[np][3],
                      bb + SWZ128(bOff + np * 2048 + ks * 32));
            #pragma unroll
            for (int mt = 0; mt < 4; mt++)
                #pragma unroll
                for (int nt = 0; nt < 8; nt++)
                    mma_tf32(acc[mt * 8 + nt], a[mt],
                             b[nt >> 1][(nt & 1) * 2], b[nt >> 1][(nt & 1) * 2 + 1]);
        }
    }
}

// Generic GEMM (used for out-projection; RND for others if needed)
template<bool RND>
__global__ __launch_bounds__(128, 2) void gemm_mma_kernel(
    const float* __restrict__ A, const float* __restrict__ Bt,
    const float* __restrict__ bias, float* __restrict__ C, int N)
{
    extern __shared__ char smc[];
    const uint32_t sb = smem_u32(smc);
    const int tid  = threadIdx.x;
    const int lane = tid & 31;
    const int w    = tid >> 5;
    const int m0   = blockIdx.y * 128;
    const int n0   = blockIdx.x * 128;
    const int wm   = (w & 1) * 64;
    const int wn   = (w >> 1) * 64;

    const int aOff = (wm + (lane & 15)) * 128 + ((lane >> 4) << 4);
    const int bOff = (wn + ((lane >> 4) << 3) + (lane & 7)) * 128 + (((lane >> 3) & 1) << 4);

    float acc[32][4];
    #pragma unroll
    for (int t = 0; t < 32; t++)
        #pragma unroll
        for (int j = 0; j < 4; j++) acc[t][j] = 0.0f;

    gemm_mainloop(A, Bt, sb, tid, m0, n0, aOff, bOff, acc);

    #pragma unroll
    for (int mt = 0; mt < 4; mt++) {
        #pragma unroll
        for (int nt = 0; nt < 8; nt++) {
            const float* cc = acc[mt * 8 + nt];
            int row = m0 + wm + mt * 16 + (lane >> 2);
            int col = n0 + wn + nt * 8 + (lane & 3) * 2;
            float2 bv = *(const float2*)&bias[col];
            float2 o0 = make_float2(cc[0] + bv.x, cc[1] + bv.y);
            float2 o1 = make_float2(cc[2] + bv.x, cc[3] + bv.y);
            if (RND) {
                o0.x = tf32r(o0.x); o0.y = tf32r(o0.y);
                o1.x = tf32r(o1.x); o1.y = tf32r(o1.y);
            }
            *(float2*)&C[(size_t)row * N + col]       = o0;
            *(float2*)&C[(size_t)(row + 8) * N + col] = o1;
        }
    }
}

// Fused QKV projection: one launch, grid (24, 32).
//  blockIdx.x <  16 : KV part over compacted rows (early-exit; scatter epi)
//  blockIdx.x >= 16 : Q part over all rows (RND epi into gq)
__global__ __launch_bounds__(128, 2) void gemm_qkv_kernel(
    const float* __restrict__ xr, const float* __restrict__ xc,
    const float* __restrict__ wqkvT, const float* __restrict__ bqkv,
    const int* __restrict__ cnt,
    float* __restrict__ gq, float* __restrict__ kc, float* __restrict__ vc)
{
    const bool kvPart = (blockIdx.x < 16);
    const int m0 = blockIdx.y * 128;
    if (kvPart) {
        const int bb = m0 >> 11;
        const int j0 = m0 & (LDIM - 1);
        const int cp = (cnt[bb] + 127) & ~127;
        if (j0 >= cp) return;
    }

    extern __shared__ char smc[];
    const uint32_t sb = smem_u32(smc);
    const int tid  = threadIdx.x;
    const int lane = tid & 31;
    const int w    = tid >> 5;
    const int n0   = (kvPart ? blockIdx.x : (blockIdx.x - 16)) * 128;
    const int wm   = (w & 1) * 64;
    const int wn   = (w >> 1) * 64;

    const int aOff = (wm + (lane & 15)) * 128 + ((lane >> 4) << 4);
    const int bOff = (wn + ((lane >> 4) << 3) + (lane & 7)) * 128 + (((lane >> 3) & 1) << 4);

    const float* A    = kvPart ? xc : xr;
    const float* Bt   = kvPart ? (wqkvT + (size_t)DMODEL * GK) : wqkvT;
    const float* bias = kvPart ? nullptr : nullptr;  // handled below

    float acc[32][4];
    #pragma unroll
    for (int t = 0; t < 32; t++)
        #pragma unroll
        for (int j = 0; j < 4; j++) acc[t][j] = 0.0f;

    gemm_mainloop(A, Bt, sb, tid, m0, n0, aOff, bOff, acc);

    if (kvPart) {
        const float* bq = bqkv + DMODEL;
        #pragma unroll
        for (int mt = 0; mt < 4; mt++) {
            #pragma unroll
            for (int nt = 0; nt < 8; nt++) {
                const float* cc = acc[mt * 8 + nt];
                int row = m0 + wm + mt * 16 + (lane >> 2);
                int col = n0 + wn + nt * 8 + (lane & 3) * 2;
                float2 bv = *(const float2*)&bq[col];
                float2 o0 = make_float2(tf32r(cc[0] + bv.x), tf32r(cc[1] + bv.y));
                float2 o1 = make_float2(tf32r(cc[2] + bv.x), tf32r(cc[3] + bv.y));
                int b = row >> 11, j = row & (LDIM - 1);
                if (col < DMODEL) {   // K -> kc[bh][j][64]
                    int h = col >> 6, d = col & 63;
                    size_t o = (((size_t)(b * HEADS + h)) * LDIM) * DKH + d;
                    *(float2*)&kc[o + (size_t)j * DKH]       = o0;
                    *(float2*)&kc[o + (size_t)(j + 8) * DKH] = o1;
                } else {              // V -> vc[row][col-1024]
                    int c2 = col - DMODEL;
                    *(float2*)&vc[(size_t)row * DMODEL + c2]       = o0;
                    *(float2*)&vc[(size_t)(row + 8) * DMODEL + c2] = o1;
                }
            }
        }
    } else {
        #pragma unroll
        for (int mt = 0; mt < 4; mt++) {
            #pragma unroll
            for (int nt = 0; nt < 8; nt++) {
                const float* cc = acc[mt * 8 + nt];
                int row = m0 + wm + mt * 16 + (lane >> 2);
                int col = n0 + wn + nt * 8 + (lane & 3) * 2;
                float2 bv = *(const float2*)&bqkv[col];
                float2 o0 = make_float2(tf32r(cc[0] + bv.x), tf32r(cc[1] + bv.y));
                float2 o1 = make_float2(tf32r(cc[2] + bv.x), tf32r(cc[3] + bv.y));
                *(float2*)&gq[(size_t)row * DMODEL + col]       = o0;
                *(float2*)&gq[(size_t)(row + 8) * DMODEL + col] = o1;
            }
        }
    }
}

// ===========================================================================
// Tensor-core flash attention over COMPACTED keys (R14/R15-validated core).
// ===========================================================================
#define ABQ 128
#define ABK 64
#define AST 68
#define AQS_F 0
#define AKS_F (ABQ * AST)            // 8704
#define AVS_F (AKS_F + ABK * AST)    // 13056
#define APS_F (AVS_F + ABK * AST)    // 17408
#define AMS_F (APS_F + ABQ * AST)    // 26112
#define ATTN_SM_BYTES (AMS_F * 4 + 256)   // 104704
#define EXPC 0.18033688011112042f   // 0.125 * log2(e)

__global__ void __launch_bounds__(128, 2) attn_mma_kernel(
    const float* __restrict__ gq, const float* __restrict__ kc,
    const float* __restrict__ vtc, const int* __restrict__ cmask,
    const int* __restrict__ cnt, float* __restrict__ out)
{
    extern __shared__ float smf[];
    const uint32_t sb = smem_u32(smf);

    const int tid  = threadIdx.x;
    const int lane = tid & 31;
    const int w    = tid >> 5;
    const int g    = lane >> 2;
    const int q    = lane & 3;
    const int b    = blockIdx.y >> 4;
    const int h    = blockIdx.y & 15;
    const int q0   = blockIdx.x * ABQ;
    const int wq0  = w * 32;

    const size_t qbase = (size_t)(b * LDIM + q0) * DMODEL + h * DKH;
    const float* kcb  = kc  + (size_t)blockIdx.y * LDIM * DKH;
    const float* vtb  = vtc + ((size_t)blockIdx.y * DKH) * LDIM;
    const int*   mkb  = cmask + b * LDIM;
    const int NT = (__ldg(&cnt[b]) + ABK - 1) >> 6;

    for (int i = tid; i < ABQ * 16; i += 128) {
        int r = i >> 4, c4 = (i & 15) * 4;
        cp16(sb + (AQS_F + r * AST + c4) * 4, &gq[qbase + (size_t)r * DMODEL + c4]);
    }
    #define LOAD_K(t) do {                                                           \
        int _k0 = (t) * ABK;                                                         \
        for (int _i = tid; _i < ABK * 16; _i += 128) {                               \
            int _r = _i >> 4, _c4 = (_i & 15) * 4;                                   \
            cp16(sb + (AKS_F + _r * AST + _c4) * 4,                                  \
                 &kcb[(size_t)(_k0 + _r) * DKH + _c4]);                              \
        }                                                                            \
        if (tid < 16) cp16(sb + AMS_F * 4 + tid * 16, &mkb[_k0 + tid * 4]);          \
    } while (0)
    #define LOAD_V(t) do {                                                           \
        int _k0 = (t) * ABK;                                                         \
        for (int _i = tid; _i < ABK * 16; _i += 128) {                               \
            int _r = _i >> 4, _c4 = (_i & 15) * 4;                                   \
            cp16(sb + (AVS_F + _r * AST + _c4) * 4,                                  \
                 &vtb[(size_t)_r * LDIM + _k0 + _c4]);                               \
        }                                                                            \
    } while (0)

    LOAD_K(0);
    asm volatile("cp.async.commit_group;" ::: "memory");
    LOAD_V(0);
    asm volatile("cp.async.commit_group;" ::: "memory");

    float O[2][8][4];
    #pragma unroll
    for (int mt = 0; mt < 2; mt++)
        #pragma unroll
        for (int t = 0; t < 8; t++)
            #pragma unroll
            for (int j = 0; j < 4; j++) O[mt][t][j] = 0.0f;
    float lsum[2][2] = {{0.0f, 0.0f}, {0.0f, 0.0f}};

    const uint32_t aAddr = sb + (AQS_F + (wq0 + (lane & 15)) * AST) * 4 + ((lane >> 4) << 4);
    const uint32_t bRowO = (((lane >> 4) << 3) + (lane & 7)) * AST;
    const uint32_t bK    = sb + (AKS_F + bRowO) * 4 + (((lane >> 3) & 1) << 4);
    const uint32_t bV    = sb + (AVS_F + bRowO) * 4 + (((lane >> 3) & 1) << 4);
    float*         Pw    = smf + APS_F + w * 32 * AST;
    const uint32_t pR    = sb + (APS_F + (w * 32 + (lane & 15)) * AST) * 4
                              + ((lane >> 4) << 4);
    const int* ms = (const int*)((const char*)smf + AMS_F * 4);

    for (int t = 0; t < NT; t++) {
        asm volatile("cp.async.wait_group 1;" ::: "memory");
        __syncthreads();

        float S[2][8][4];
        #pragma unroll
        for (int nt = 0; nt < 8; nt++) {
            int2 mk = *(const int2*)&ms[nt * 8 + 2 * q];
            float bx = mk.x ? 0.0f : -3.0e38f;
            float by = mk.y ? 0.0f : -3.0e38f;
            S[0][nt][0] = bx; S[0][nt][1] = by; S[0][nt][2] = bx; S[0][nt][3] = by;
            S[1][nt][0] = bx; S[1][nt][1] = by; S[1][nt][2] = bx; S[1][nt][3] = by;
        }
        #pragma unroll
        for (int ks = 0; ks < 8; ks++) {
            uint32_t av0[4], av1[4];
            ldsm4(av0[0], av0[1], av0[2], av0[3], aAddr + ks * 32);
            ldsm4(av1[0], av1[1], av1[2], av1[3], aAddr + 16 * AST * 4 + ks * 32);
            #pragma unroll
            for (int ntp = 0; ntp < 4; ntp++) {
                uint32_t b0, b1, b2, b3;
                ldsm4(b0, b1, b2, b3, bK + ntp * 16 * AST * 4 + ks * 32);
                mma_tf32(S[0][2 * ntp],     av0, b0, b1);
                mma_tf32(S[0][2 * ntp + 1], av0, b2, b3);
                mma_tf32(S[1][2 * ntp],     av1, b0, b1);
                mma_tf32(S[1][2 * ntp + 1], av1, b2, b3);
            }
        }

        #pragma unroll
        for (int mt = 0; mt < 2; mt++)
            #pragma unroll
            for (int nt = 0; nt < 8; nt++) {
                float p0 = ex2(S[mt][nt][0] * EXPC);
                float p1 = ex2(S[mt][nt][1] * EXPC);
                float p2 = ex2(S[mt][nt][2] * EXPC);
                float p3 = ex2(S[mt][nt][3] * EXPC);
                lsum[mt][0] += p0 + p1;
                lsum[mt][1] += p2 + p3;
                int r = mt * 16 + g;
                int col = nt * 8 + 2 * q;
                *(float2*)&Pw[r * AST + col]       = make_float2(tf32r(p0), tf32r(p1));
                *(float2*)&Pw[(r + 8) * AST + col] = make_float2(tf32r(p2), tf32r(p3));
            }
        __syncwarp();
        __syncthreads();

        if (t + 1 < NT) {
            LOAD_K(t + 1);
            asm volatile("cp.async.commit_group;" ::: "memory");
        }
        if (t + 1 < NT) { asm volatile("cp.async.wait_group 1;" ::: "memory"); }
        else            { asm volatile("cp.async.wait_group 0;" ::: "memory"); }
        __syncthreads();

        #pragma unroll
        for (int j = 0; j < 8; j++) {
            uint32_t pa0[4], pa1[4];
            ldsm4(pa0[0], pa0[1], pa0[2], pa0[3], pR + j * 32);
            ldsm4(pa1[0], pa1[1], pa1[2], pa1[3], pR + 16 * AST * 4 + j * 32);
            #pragma unroll
            for (int np = 0; np < 4; np++) {
                uint32_t b0, b1, b2, b3;
                ldsm4(b0, b1, b2, b3, bV + np * 16 * AST * 4 + j * 32);
                mma_tf32(O[0][2 * np],     pa0, b0, b1);
                mma_tf32(O[0][2 * np + 1], pa0, b2, b3);
                mma_tf32(O[1][2 * np],     pa1, b0, b1);
                mma_tf32(O[1][2 * np + 1], pa1, b2, b3);
            }
        }

        __syncthreads();
        if (t + 1 < NT) {
            LOAD_V(t + 1);
            asm volatile("cp.async.commit_group;" ::: "memory");
        }
    }

    #pragma unroll
    for (int mt = 0; mt < 2; mt++) {
        float l0 = lsum[mt][0], l1 = lsum[mt][1];
        l0 += __shfl_xor_sync(0xffffffffu, l0, 1);
        l0 += __shfl_xor_sync(0xffffffffu, l0, 2);
        l1 += __shfl_xor_sync(0xffffffffu, l1, 1);
        l1 += __shfl_xor_sync(0xffffffffu, l1, 2);
        float il0 = 1.0f / l0, il1 = 1.0f / l1;

        int row0 = q0 + wq0 + mt * 16 + g;
        size_t o0 = ((size_t)(b * LDIM + row0)) * DMODEL + h * DKH;
        #pragma unroll
        for (int nt = 0; nt < 8; nt++) {
            int col = nt * 8 + 2 * q;
            float2 v0 = make_float2(tf32r(O[mt][nt][0] * il0), tf32r(O[mt][nt][1] * il0));
            float2 v1 = make_float2(tf32r(O[mt][nt][2] * il1), tf32r(O[mt][nt][3] * il1));
            *(float2*)&out[o0 + col]              = v0;
            *(float2*)&out[o0 + 8 * DMODEL + col] = v1;
        }
    }
    #undef LOAD_K
    #undef LOAD_V
}

// ---------------------------------------------------------------------------
// Launch
// ---------------------------------------------------------------------------
extern "C" void kernel_launch(void* const* d_in, const int* in_sizes, int n_in,
                              void* d_out, int out_size)
{
    const float* x     = (const float*)d_in[0];
    const int*   mask  = (const int*)  d_in[1];
    const float* Wqkv  = (const float*)d_in[2];
    const float* bqkv  = (const float*)d_in[3];
    const float* Wout  = (const float*)d_in[4];
    const float* bout  = (const float*)d_in[5];
    float* out = (float*)d_out;

    float *gq, *vc, *attn, *xr, *xc, *wqkvT, *woutT, *kc, *vtc;
    int *idx, *cmask, *cnt;
    cudaGetSymbolAddress((void**)&gq,    g_q);
    cudaGetSymbolAddress((void**)&vc,    g_vc);
    cudaGetSymbolAddress((void**)&attn,  g_attn);
    cudaGetSymbolAddress((void**)&xr,    g_x);
    cudaGetSymbolAddress((void**)&xc,    g_xc);
    cudaGetSymbolAddress((void**)&wqkvT, g_wqkvT);
    cudaGetSymbolAddress((void**)&woutT, g_woutT);
    cudaGetSymbolAddress((void**)&kc,    g_kc);
    cudaGetSymbolAddress((void**)&vtc,   g_vtc);
    cudaGetSymbolAddress((void**)&idx,   g_idx);
    cudaGetSymbolAddress((void**)&cmask, g_cmask);
    cudaGetSymbolAddress((void**)&cnt,   g_cnt);

    cudaFuncSetAttribute(gemm_mma_kernel<false>,
                         cudaFuncAttributeMaxDynamicSharedMemorySize, GS_TOTAL);
    cudaFuncSetAttribute(gemm_qkv_kernel,
                         cudaFuncAttributeMaxDynamicSharedMemorySize, GS_TOTAL);
    cudaFuncSetAttribute(attn_mma_kernel,
                         cudaFuncAttributeMaxDynamicSharedMemorySize, ATTN_SM_BYTES);

    // 1) Fused prep: round x | transpose Wqkv | transpose Wout | scan+cmask
    prep_fused_kernel<<<8194, 256>>>(x, Wqkv, Wout, mask,
                                     xr, wqkvT, woutT, idx, cnt, cmask);

    // 2) Compacted x rows
    xgather_kernel<<<ROWS, 256>>>(xr, idx, cnt, xc);

    // 3) Fused QKV projection: KV (compacted, early-exit) + Q, one launch
    gemm_qkv_kernel<<<dim3(24, ROWS / 128), 128, GS_TOTAL>>>(
        xr, xc, wqkvT, bqkv, cnt, gq, kc, vc);

    // 4) Compacted V transpose
    vtrans_c_kernel<<<dim3(LDIM / 32, DKH / 32, BDIM * HEADS), dim3(32, 8)>>>(
        vc, cnt, vtc);

    // 5) Flash attention over compacted keys
    attn_mma_kernel<<<dim3(LDIM / ABQ, BDIM * HEADS), 128, ATTN_SM_BYTES>>>(
        gq, kc, vtc, cmask, cnt, attn);

    // 6) Output projection (full-precision output)
    gemm_mma_kernel<false><<<dim3(DMODEL / 128, ROWS / 128), 128, GS_TOTAL>>>(
        attn, woutT, bout, out, DMODEL);
}

// round 17
// speedup vs baseline: 1.7376x; 1.0216x over previous
#include <cuda_runtime.h>
#include <math.h>
#include <stdint.h>

// Problem constants
#define BDIM   2
#define LDIM   2048
#define DMODEL 1024
#define HEADS  16
#define DKH    64
#define D3     (3 * DMODEL)
#define ROWS   (BDIM * LDIM)   // 4096
#define GK     1024            // K for all projection GEMMs

// Scratch (allocation-free: __device__ globals)
__device__ float g_q[(size_t)ROWS * DMODEL];     // Q [row][1024], tf32-rounded
__device__ float g_attn[(size_t)ROWS * DMODEL];  // [B,L,H,dk] (tf32-rounded)
__device__ float g_x[(size_t)ROWS * DMODEL];     // tf32-rounded x
__device__ float g_wqkvT[(size_t)D3 * GK];       // [3072][1024] k-major, tf32-rounded
__device__ float g_woutT[(size_t)DMODEL * GK];   // [1024][1024] k-major, tf32-rounded
__device__ float g_kc[(size_t)BDIM * HEADS * LDIM * DKH];  // compacted K [bh][j][64]
__device__ float g_vtc[(size_t)BDIM * HEADS * DKH * LDIM]; // compacted Vt [bh][d][j]
__device__ float g_zero[GK];                     // never written -> stays 0
__device__ int   g_idx[BDIM * LDIM];             // compacted key index (-1 = pad)
__device__ int   g_cmask[BDIM * LDIM];           // compacted mask (1 for j<cnt)
__device__ int   g_cnt[BDIM];                    // unmasked count per batch

// ===========================================================================
// Helpers
// ===========================================================================
__device__ __forceinline__ float tf32r(float x) {
    uint32_t y;
    asm("cvt.rna.tf32.f32 %0, %1;" : "=r"(y) : "f"(x));
    return __uint_as_float(y);
}
__device__ __forceinline__ float ex2(float x) {
    float y;
    asm("ex2.approx.f32 %0, %1;" : "=f"(y) : "f"(x));
    return y;
}
__device__ __forceinline__ uint32_t smem_u32(const void* p) {
    uint32_t a;
    asm("{ .reg .u64 t; cvta.to.shared.u64 t, %1; cvt.u32.u64 %0, t; }" : "=r"(a) : "l"(p));
    return a;
}
#define SWZ128(x) ((x) ^ (((x) >> 3) & 0x70))

__device__ __forceinline__ void cp16(uint32_t dst, const void* src) {
    asm volatile("cp.async.cg.shared.global [%0], [%1], 16;" :: "r"(dst), "l"(src));
}
__device__ __forceinline__ void ldsm4(uint32_t& r0, uint32_t& r1, uint32_t& r2, uint32_t& r3,
                                      uint32_t addr) {
    asm volatile("ldmatrix.sync.aligned.m8n8.x4.shared.b16 {%0,%1,%2,%3}, [%4];"
                 : "=r"(r0), "=r"(r1), "=r"(r2), "=r"(r3) : "r"(addr));
}
__device__ __forceinline__ void mma_tf32(float* c, const uint32_t* a, uint32_t b0, uint32_t b1) {
    asm volatile("mma.sync.aligned.m16n8k8.row.col.f32.tf32.tf32.f32 "
                 "{%0,%1,%2,%3}, {%4,%5,%6,%7}, {%8,%9}, {%0,%1,%2,%3};"
                 : "+f"(c[0]), "+f"(c[1]), "+f"(c[2]), "+f"(c[3])
                 : "r"(a[0]), "r"(a[1]), "r"(a[2]), "r"(a[3]), "r"(b0), "r"(b1));
}

// ===========================================================================
// Fused prep kernel: role by blockIdx.x, 256 threads each.
//  [0,4096)    : tf32-round x -> xr
//  [4096,7168) : Wqkv -> wqkvT (32x32 tiles)
//  [7168,8192) : Wout -> woutT
//  [8192,8194) : mask scan -> idx (pad=-1) / cnt / cmask
// ===========================================================================
__global__ __launch_bounds__(256) void prep_fused_kernel(
    const float* __restrict__ x, const float* __restrict__ Wqkv,
    const float* __restrict__ Wout, const int* __restrict__ mask,
    float* __restrict__ xr, float* __restrict__ wqkvT, float* __restrict__ woutT,
    int* __restrict__ idx, int* __restrict__ cnt, int* __restrict__ cmask)
{
    __shared__ float tsh[32][33];
    __shared__ int wsum[8];
    __shared__ int total_s;

    const int blk = blockIdx.x;
    const int tid = threadIdx.x;

    if (blk < 4096) {                       // round x
        int i = blk * 256 + tid;
        float4 v = ((const float4*)x)[i];
        v.x = tf32r(v.x); v.y = tf32r(v.y); v.z = tf32r(v.z); v.w = tf32r(v.w);
        ((float4*)xr)[i] = v;
    } else if (blk < 8192) {                // weight transpose (K=1024 both)
        const float* in;
        float* out;
        int n0, k0, N;
        if (blk < 7168) {
            int t = blk - 4096;
            in = Wqkv; out = wqkvT; N = D3;
            n0 = (t % 96) * 32; k0 = (t / 96) * 32;
        } else {
            int t = blk - 7168;
            in = Wout; out = woutT; N = DMODEL;
            n0 = (t % 32) * 32; k0 = (t / 32) * 32;
        }
        int tx = tid & 31, ty = tid >> 5;
        for (int j = ty; j < 32; j += 8)
            tsh[j][tx] = tf32r(in[(size_t)(k0 + j) * N + n0 + tx]);
        __syncthreads();
        for (int j = ty; j < 32; j += 8)
            out[(size_t)(n0 + j) * GK + k0 + tx] = tsh[tx][j];
    } else {                                // mask scan + cmask + idx padding
        const int b = blk - 8192;
        const int* m = mask + b * LDIM;
        const int base = tid * 8;
        int v[8], s = 0;
        #pragma unroll
        for (int i = 0; i < 8; i++) { v[i] = m[base + i]; s += v[i]; }
        const int lane = tid & 31, wid = tid >> 5;
        int pre = s;
        #pragma unroll
        for (int o = 1; o < 32; o <<= 1) {
            int xk = __shfl_up_sync(0xffffffffu, pre, o);
            if (lane >= o) pre += xk;
        }
        if (lane == 31) wsum[wid] = pre;
        __syncthreads();
        int woff = 0;
        for (int i = 0; i < wid; i++) woff += wsum[i];
        int off = woff + pre - s;
        #pragma unroll
        for (int i = 0; i < 8; i++)
            if (v[i]) idx[b * LDIM + off++] = base + i;
        if (tid == 255) { cnt[b] = woff + pre; total_s = woff + pre; }
        __syncthreads();
        int tot = total_s;
        for (int k = tid; k < LDIM; k += 256) {
            cmask[b * LDIM + k] = (k < tot) ? 1 : 0;
            if (k >= tot) idx[b * LDIM + k] = -1;
        }
    }
}

// ===========================================================================
// tf32 mma.sync GEMM core: 128 threads, 4 warps of 64x64, 3-stage cp.async.
// ===========================================================================
#define GBK    32
#define GTILE  (128 * GBK * 4)          // 16KB per operand tile
#define GSTG   3
#define GS_BODY (GSTG * 2 * GTILE)      // 96KB pipeline
#define GS_TOTAL (GS_BODY + 512)        // + sIdx table

__device__ __forceinline__ void gemm_load_tile(const float* __restrict__ src, int row0, int k0,
                                               uint32_t smemBase, int tid) {
    #pragma unroll
    for (int j = 0; j < 8; j++) {
        int i   = tid + j * 128;
        int row = i >> 3;
        int c   = i & 7;
        cp16(smemBase + SWZ128(row * 128 + c * 16),
             src + (size_t)(row0 + row) * GK + k0 + c * 4);
    }
}

// Indirect A-tile load: row -> xr[bbase + sIdx[row]] or zero row.
__device__ __forceinline__ void gemm_load_tileA_idx(
    const float* __restrict__ xr, const float* __restrict__ zrow,
    const int* __restrict__ sIdx, size_t bbase, int k0, uint32_t smemBase, int tid)
{
    #pragma unroll
    for (int j = 0; j < 8; j++) {
        int i   = tid + j * 128;
        int row = i >> 3;
        int c   = i & 7;
        int ix  = sIdx[row];
        const float* src = (ix >= 0)
            ? xr + (bbase + (size_t)ix) * GK + k0 + c * 4
            : zrow + k0 + c * 4;
        cp16(smemBase + SWZ128(row * 128 + c * 16), src);
    }
}

#define GEMM_COMPUTE_CHUNK(ba, bb)                                                  \
    do {                                                                            \
        _Pragma("unroll")                                                           \
        for (int ks = 0; ks < 4; ks++) {                                            \
            uint32_t a[4][4], bfr[4][4];                                            \
            _Pragma("unroll")                                                       \
            for (int mt = 0; mt < 4; mt++)                                          \
                ldsm4(a[mt][0], a[mt][1], a[mt][2], a[mt][3],                       \
                      (ba) + SWZ128(aOff + mt * 2048 + ks * 32));                   \
            _Pragma("unroll")                                                       \
            for (int np = 0; np < 4; np++)                                          \
                ldsm4(bfr[np][0], bfr[np][1], bfr[np][2], bfr[np][3],               \
                      (bb) + SWZ128(bOff + np * 2048 + ks * 32));                   \
            _Pragma("unroll")                                                       \
            for (int mt = 0; mt < 4; mt++)                                          \
                _Pragma("unroll")                                                   \
                for (int nt = 0; nt < 8; nt++)                                      \
                    mma_tf32(acc[mt * 8 + nt], a[mt],                               \
                             bfr[nt >> 1][(nt & 1) * 2], bfr[nt >> 1][(nt & 1) * 2 + 1]); \
        }                                                                           \
    } while (0)

__device__ __forceinline__ void gemm_mainloop(
    const float* __restrict__ A, const float* __restrict__ Bt,
    uint32_t sb, int tid, int m0, int n0, int aOff, int bOff, float acc[32][4])
{
    gemm_load_tile(A,  m0, 0, sb, tid);
    gemm_load_tile(Bt, n0, 0, sb + GTILE, tid);
    asm volatile("cp.async.commit_group;" ::: "memory");
    gemm_load_tile(A,  m0, GBK, sb + 2 * GTILE, tid);
    gemm_load_tile(Bt, n0, GBK, sb + 3 * GTILE, tid);
    asm volatile("cp.async.commit_group;" ::: "memory");

    const int NCHUNK = GK / GBK;   // 32
    for (int c = 0; c < NCHUNK; c++) {
        if (c < NCHUNK - 1) { asm volatile("cp.async.wait_group 1;" ::: "memory"); }
        else                { asm volatile("cp.async.wait_group 0;" ::: "memory"); }
        __syncthreads();

        if (c + 2 < NCHUNK) {
            const uint32_t sp = sb + ((c + 2) % GSTG) * 2 * GTILE;
            gemm_load_tile(A,  m0, (c + 2) * GBK, sp, tid);
            gemm_load_tile(Bt, n0, (c + 2) * GBK, sp + GTILE, tid);
            asm volatile("cp.async.commit_group;" ::: "memory");
        }
        const uint32_t ba = sb + (c % GSTG) * 2 * GTILE;
        GEMM_COMPUTE_CHUNK(ba, ba + GTILE);
    }
}

__device__ __forceinline__ void gemm_mainloop_idx(
    const float* __restrict__ xr, const float* __restrict__ zrow,
    const int* __restrict__ sIdx, size_t bbase, const float* __restrict__ Bt,
    uint32_t sb, int tid, int n0, int aOff, int bOff, float acc[32][4])
{
    gemm_load_tileA_idx(xr, zrow, sIdx, bbase, 0, sb, tid);
    gemm_load_tile(Bt, n0, 0, sb + GTILE, tid);
    asm volatile("cp.async.commit_group;" ::: "memory");
    gemm_load_tileA_idx(xr, zrow, sIdx, bbase, GBK, sb + 2 * GTILE, tid);
    gemm_load_tile(Bt, n0, GBK, sb + 3 * GTILE, tid);
    asm volatile("cp.async.commit_group;" ::: "memory");

    const int NCHUNK = GK / GBK;
    for (int c = 0; c < NCHUNK; c++) {
        if (c < NCHUNK - 1) { asm volatile("cp.async.wait_group 1;" ::: "memory"); }
        else                { asm volatile("cp.async.wait_group 0;" ::: "memory"); }
        __syncthreads();

        if (c + 2 < NCHUNK) {
            const uint32_t sp = sb + ((c + 2) % GSTG) * 2 * GTILE;
            gemm_load_tileA_idx(xr, zrow, sIdx, bbase, (c + 2) * GBK, sp, tid);
            gemm_load_tile(Bt, n0, (c + 2) * GBK, sp + GTILE, tid);
            asm volatile("cp.async.commit_group;" ::: "memory");
        }
        const uint32_t ba = sb + (c % GSTG) * 2 * GTILE;
        GEMM_COMPUTE_CHUNK(ba, ba + GTILE);
    }
}

// Generic GEMM (out-projection)
template<bool RND>
__global__ __launch_bounds__(128, 2) void gemm_mma_kernel(
    const float* __restrict__ A, const float* __restrict__ Bt,
    const float* __restrict__ bias, float* __restrict__ C, int N)
{
    extern __shared__ char smc[];
    const uint32_t sb = smem_u32(smc);
    const int tid  = threadIdx.x;
    const int lane = tid & 31;
    const int w    = tid >> 5;
    const int m0   = blockIdx.y * 128;
    const int n0   = blockIdx.x * 128;
    const int wm   = (w & 1) * 64;
    const int wn   = (w >> 1) * 64;

    const int aOff = (wm + (lane & 15)) * 128 + ((lane >> 4) << 4);
    const int bOff = (wn + ((lane >> 4) << 3) + (lane & 7)) * 128 + (((lane >> 3) & 1) << 4);

    float acc[32][4];
    #pragma unroll
    for (int t = 0; t < 32; t++)
        #pragma unroll
        for (int j = 0; j < 4; j++) acc[t][j] = 0.0f;

    gemm_mainloop(A, Bt, sb, tid, m0, n0, aOff, bOff, acc);

    #pragma unroll
    for (int mt = 0; mt < 4; mt++) {
        #pragma unroll
        for (int nt = 0; nt < 8; nt++) {
            const float* cc = acc[mt * 8 + nt];
            int row = m0 + wm + mt * 16 + (lane >> 2);
            int col = n0 + wn + nt * 8 + (lane & 3) * 2;
            float2 bv = *(const float2*)&bias[col];
            float2 o0 = make_float2(cc[0] + bv.x, cc[1] + bv.y);
            float2 o1 = make_float2(cc[2] + bv.x, cc[3] + bv.y);
            if (RND) {
                o0.x = tf32r(o0.x); o0.y = tf32r(o0.y);
                o1.x = tf32r(o1.x); o1.y = tf32r(o1.y);
            }
            *(float2*)&C[(size_t)row * N + col]       = o0;
            *(float2*)&C[(size_t)(row + 8) * N + col] = o1;
        }
    }
}

// Fused QKV projection: grid (24, 32).
//  blockIdx.x < 16 : KV part, compacted rows via smem index table.
//    K cols -> kc scatter;  V cols -> smem-staged transpose -> vtc coalesced.
//  blockIdx.x >= 16: Q part over all rows -> gq (tf32-rounded).
__global__ __launch_bounds__(128, 2) void gemm_qkv_kernel(
    const float* __restrict__ xr, const float* __restrict__ wqkvT,
    const float* __restrict__ bqkv, const int* __restrict__ idx,
    const int* __restrict__ cnt, const float* __restrict__ zrow,
    float* __restrict__ gq, float* __restrict__ kc, float* __restrict__ vtc)
{
    extern __shared__ char smc[];
    const uint32_t sb = smem_u32(smc);
    const int tid  = threadIdx.x;
    const int lane = tid & 31;
    const int w    = tid >> 5;
    const int m0   = blockIdx.y * 128;
    const bool kvPart = (blockIdx.x < 16);
    const int wm   = (w & 1) * 64;
    const int wn   = (w >> 1) * 64;
    const int aOff = (wm + (lane & 15)) * 128 + ((lane >> 4) << 4);
    const int bOff = (wn + ((lane >> 4) << 3) + (lane & 7)) * 128 + (((lane >> 3) & 1) << 4);

    float acc[32][4];
    #pragma unroll
    for (int t = 0; t < 32; t++)
        #pragma unroll
        for (int j = 0; j < 4; j++) acc[t][j] = 0.0f;

    if (kvPart) {
        const int bb = m0 >> 11;
        const int j0 = m0 & (LDIM - 1);
        const int cp = (cnt[bb] + 127) & ~127;
        if (j0 >= cp) return;

        int* sIdx = (int*)(smc + GS_BODY);
        if (tid < 128) sIdx[tid] = idx[bb * LDIM + j0 + tid];
        __syncthreads();

        const int n0 = blockIdx.x * 128;
        gemm_mainloop_idx(xr, zrow, sIdx, (size_t)bb * LDIM,
                          wqkvT + (size_t)DMODEL * GK, sb, tid, n0, aOff, bOff, acc);

        const float* bq = bqkv + DMODEL;
        if (n0 < DMODEL) {
            // K part: scatter into kc[bh][j][64]
            #pragma unroll
            for (int mt = 0; mt < 4; mt++) {
                #pragma unroll
                for (int nt = 0; nt < 8; nt++) {
                    const float* cc = acc[mt * 8 + nt];
                    int jl  = wm + mt * 16 + (lane >> 2);
                    int col = n0 + wn + nt * 8 + (lane & 3) * 2;
                    float2 bv = *(const float2*)&bq[col];
                    float2 o0 = make_float2(tf32r(cc[0] + bv.x), tf32r(cc[1] + bv.y));
                    float2 o1 = make_float2(tf32r(cc[2] + bv.x), tf32r(cc[3] + bv.y));
                    int h = col >> 6, d = col & 63;
                    size_t o = (((size_t)(bb * HEADS + h)) * LDIM) * DKH + d;
                    *(float2*)&kc[o + (size_t)(j0 + jl) * DKH]       = o0;
                    *(float2*)&kc[o + (size_t)(j0 + jl + 8) * DKH]  = o1;
                }
            }
        } else {
            // V part: stage [col][j] in smem, then coalesced write to vtc
            __syncthreads();                 // pipeline smem now free
            float* vs = (float*)smc;         // [128][132]
            const int n0v = n0 - DMODEL;
            #pragma unroll
            for (int mt = 0; mt < 4; mt++) {
                #pragma unroll
                for (int nt = 0; nt < 8; nt++) {
                    const float* cc = acc[mt * 8 + nt];
                    int jl = wm + mt * 16 + (lane >> 2);
                    int cl = wn + nt * 8 + (lane & 3) * 2;
                    float2 bv = *(const float2*)&bq[DMODEL + n0v + cl - DMODEL + DMODEL];
                    // (bq + DMODEL) would double-count; compute bias directly:
                    bv = *(const float2*)&bqkv[2 * DMODEL + n0v + cl];
                    vs[cl * 132 + jl]            = tf32r(cc[0] + bv.x);
                    vs[(cl + 1) * 132 + jl]      = tf32r(cc[1] + bv.y);
                    vs[cl * 132 + jl + 8]        = tf32r(cc[2] + bv.x);
                    vs[(cl + 1) * 132 + jl + 8]  = tf32r(cc[3] + bv.y);
                }
            }
            __syncthreads();
            for (int r = w; r < 128; r += 4) {
                int c2 = n0v + r;
                int h = c2 >> 6, d = c2 & 63;
                float4 v = *(float4*)&vs[r * 132 + lane * 4];
                *(float4*)&vtc[(((size_t)(bb * HEADS + h)) * DKH + d) * LDIM
                               + j0 + lane * 4] = v;
            }
        }
    } else {
        const int n0 = (blockIdx.x - 16) * 128;
        gemm_mainloop(xr, wqkvT, sb, tid, m0, n0, aOff, bOff, acc);
        #pragma unroll
        for (int mt = 0; mt < 4; mt++) {
            #pragma unroll
            for (int nt = 0; nt < 8; nt++) {
                const float* cc = acc[mt * 8 + nt];
                int row = m0 + wm + mt * 16 + (lane >> 2);
                int col = n0 + wn + nt * 8 + (lane & 3) * 2;
                float2 bv = *(const float2*)&bqkv[col];
                float2 o0 = make_float2(tf32r(cc[0] + bv.x), tf32r(cc[1] + bv.y));
                float2 o1 = make_float2(tf32r(cc[2] + bv.x), tf32r(cc[3] + bv.y));
                *(float2*)&gq[(size_t)row * DMODEL + col]       = o0;
                *(float2*)&gq[(size_t)(row + 8) * DMODEL + col] = o1;
            }
        }
    }
}

// ===========================================================================
// Tensor-core flash attention over COMPACTED keys (R14-16 validated core).
// ===========================================================================
#define ABQ 128
#define ABK 64
#define AST 68
#define AQS_F 0
#define AKS_F (ABQ * AST)
#define AVS_F (AKS_F + ABK * AST)
#define APS_F (AVS_F + ABK * AST)
#define AMS_F (APS_F + ABQ * AST)
#define ATTN_SM_BYTES (AMS_F * 4 + 256)
#define EXPC 0.18033688011112042f   // 0.125 * log2(e)

__global__ void __launch_bounds__(128, 2) attn_mma_kernel(
    const float* __restrict__ gq, const float* __restrict__ kc,
    const float* __restrict__ vtc, const int* __restrict__ cmask,
    const int* __restrict__ cnt, float* __restrict__ out)
{
    extern __shared__ float smf[];
    const uint32_t sb = smem_u32(smf);

    const int tid  = threadIdx.x;
    const int lane = tid & 31;
    const int w    = tid >> 5;
    const int g    = lane >> 2;
    const int q    = lane & 3;
    const int b    = blockIdx.y >> 4;
    const int h    = blockIdx.y & 15;
    const int q0   = blockIdx.x * ABQ;
    const int wq0  = w * 32;

    const size_t qbase = (size_t)(b * LDIM + q0) * DMODEL + h * DKH;
    const float* kcb  = kc  + (size_t)blockIdx.y * LDIM * DKH;
    const float* vtb  = vtc + ((size_t)blockIdx.y * DKH) * LDIM;
    const int*   mkb  = cmask + b * LDIM;
    const int NT = (__ldg(&cnt[b]) + ABK - 1) >> 6;

    for (int i = tid; i < ABQ * 16; i += 128) {
        int r = i >> 4, c4 = (i & 15) * 4;
        cp16(sb + (AQS_F + r * AST + c4) * 4, &gq[qbase + (size_t)r * DMODEL + c4]);
    }
    #define LOAD_K(t) do {                                                           \
        int _k0 = (t) * ABK;                                                         \
        for (int _i = tid; _i < ABK * 16; _i += 128) {                               \
            int _r = _i >> 4, _c4 = (_i & 15) * 4;                                   \
            cp16(sb + (AKS_F + _r * AST + _c4) * 4,                                  \
                 &kcb[(size_t)(_k0 + _r) * DKH + _c4]);                              \
        }                                                                            \
        if (tid < 16) cp16(sb + AMS_F * 4 + tid * 16, &mkb[_k0 + tid * 4]);          \
    } while (0)
    #define LOAD_V(t) do {                                                           \
        int _k0 = (t) * ABK;                                                         \
        for (int _i = tid; _i < ABK * 16; _i += 128) {                               \
            int _r = _i >> 4, _c4 = (_i & 15) * 4;                                   \
            cp16(sb + (AVS_F + _r * AST + _c4) * 4,                                  \
                 &vtb[(size_t)_r * LDIM + _k0 + _c4]);                               \
        }                                                                            \
    } while (0)

    LOAD_K(0);
    asm volatile("cp.async.commit_group;" ::: "memory");
    LOAD_V(0);
    asm volatile("cp.async.commit_group;" ::: "memory");

    float O[2][8][4];
    #pragma unroll
    for (int mt = 0; mt < 2; mt++)
        #pragma unroll
        for (int t = 0; t < 8; t++)
            #pragma unroll
            for (int j = 0; j < 4; j++) O[mt][t][j] = 0.0f;
    float lsum[2][2] = {{0.0f, 0.0f}, {0.0f, 0.0f}};

    const uint32_t aAddr = sb + (AQS_F + (wq0 + (lane & 15)) * AST) * 4 + ((lane >> 4) << 4);
    const uint32_t bRowO = (((lane >> 4) << 3) + (lane & 7)) * AST;
    const uint32_t bK    = sb + (AKS_F + bRowO) * 4 + (((lane >> 3) & 1) << 4);
    const uint32_t bV    = sb + (AVS_F + bRowO) * 4 + (((lane >> 3) & 1) << 4);
    float*         Pw    = smf + APS_F + w * 32 * AST;
    const uint32_t pR    = sb + (APS_F + (w * 32 + (lane & 15)) * AST) * 4
                              + ((lane >> 4) << 4);
    const int* ms = (const int*)((const char*)smf + AMS_F * 4);

    for (int t = 0; t < NT; t++) {
        asm volatile("cp.async.wait_group 1;" ::: "memory");
        __syncthreads();

        float S[2][8][4];
        #pragma unroll
        for (int nt = 0; nt < 8; nt++) {
            int2 mk = *(const int2*)&ms[nt * 8 + 2 * q];
            float bx = mk.x ? 0.0f : -3.0e38f;
            float by = mk.y ? 0.0f : -3.0e38f;
            S[0][nt][0] = bx; S[0][nt][1] = by; S[0][nt][2] = bx; S[0][nt][3] = by;
            S[1][nt][0] = bx; S[1][nt][1] = by; S[1][nt][2] = bx; S[1][nt][3] = by;
        }
        #pragma unroll
        for (int ks = 0; ks < 8; ks++) {
            uint32_t av0[4], av1[4];
            ldsm4(av0[0], av0[1], av0[2], av0[3], aAddr + ks * 32);
            ldsm4(av1[0], av1[1], av1[2], av1[3], aAddr + 16 * AST * 4 + ks * 32);
            #pragma unroll
            for (int ntp = 0; ntp < 4; ntp++) {
                uint32_t b0, b1, b2, b3;
                ldsm4(b0, b1, b2, b3, bK + ntp * 16 * AST * 4 + ks * 32);
                mma_tf32(S[0][2 * ntp],     av0, b0, b1);
                mma_tf32(S[0][2 * ntp + 1], av0, b2, b3);
                mma_tf32(S[1][2 * ntp],     av1, b0, b1);
                mma_tf32(S[1][2 * ntp + 1], av1, b2, b3);
            }
        }

        #pragma unroll
        for (int mt = 0; mt < 2; mt++)
            #pragma unroll
            for (int nt = 0; nt < 8; nt++) {
                float p0 = ex2(S[mt][nt][0] * EXPC);
                float p1 = ex2(S[mt][nt][1] * EXPC);
                float p2 = ex2(S[mt][nt][2] * EXPC);
                float p3 = ex2(S[mt][nt][3] * EXPC);
                lsum[mt][0] += p0 + p1;
                lsum[mt][1] += p2 + p3;
                int r = mt * 16 + g;
                int col = nt * 8 + 2 * q;
                *(float2*)&Pw[r * AST + col]       = make_float2(tf32r(p0), tf32r(p1));
                *(float2*)&Pw[(r + 8) * AST + col] = make_float2(tf32r(p2), tf32r(p3));
            }
        __syncwarp();
        __syncthreads();

        if (t + 1 < NT) {
            LOAD_K(t + 1);
            asm volatile("cp.async.commit_group;" ::: "memory");
        }
        if (t + 1 < NT) { asm volatile("cp.async.wait_group 1;" ::: "memory"); }
        else            { asm volatile("cp.async.wait_group 0;" ::: "memory"); }
        __syncthreads();

        #pragma unroll
        for (int j = 0; j < 8; j++) {
            uint32_t pa0[4], pa1[4];
            ldsm4(pa0[0], pa0[1], pa0[2], pa0[3], pR + j * 32);
            ldsm4(pa1[0], pa1[1], pa1[2], pa1[3], pR + 16 * AST * 4 + j * 32);
            #pragma unroll
            for (int np = 0; np < 4; np++) {
                uint32_t b0, b1, b2, b3;
                ldsm4(b0, b1, b2, b3, bV + np * 16 * AST * 4 + j * 32);
                mma_tf32(O[0][2 * np],     pa0, b0, b1);
                mma_tf32(O[0][2 * np + 1], pa0, b2, b3);
                mma_tf32(O[1][2 * np],     pa1, b0, b1);
                mma_tf32(O[1][2 * np + 1], pa1, b2, b3);
            }
        }

        __syncthreads();
        if (t + 1 < NT) {
            LOAD_V(t + 1);
            asm volatile("cp.async.commit_group;" ::: "memory");
        }
    }

    #pragma unroll
    for (int mt = 0; mt < 2; mt++) {
        float l0 = lsum[mt][0], l1 = lsum[mt][1];
        l0 += __shfl_xor_sync(0xffffffffu, l0, 1);
        l0 += __shfl_xor_sync(0xffffffffu, l0, 2);
        l1 += __shfl_xor_sync(0xffffffffu, l1, 1);
        l1 += __shfl_xor_sync(0xffffffffu, l1, 2);
        float il0 = 1.0f / l0, il1 = 1.0f / l1;

        int row0 = q0 + wq0 + mt * 16 + g;
        size_t o0 = ((size_t)(b * LDIM + row0)) * DMODEL + h * DKH;
        #pragma unroll
        for (int nt = 0; nt < 8; nt++) {
            int col = nt * 8 + 2 * q;
            float2 v0 = make_float2(tf32r(O[mt][nt][0] * il0), tf32r(O[mt][nt][1] * il0));
            float2 v1 = make_float2(tf32r(O[mt][nt][2] * il1), tf32r(O[mt][nt][3] * il1));
            *(float2*)&out[o0 + col]              = v0;
            *(float2*)&out[o0 + 8 * DMODEL + col] = v1;
        }
    }
    #undef LOAD_K
    #undef LOAD_V
}

// ---------------------------------------------------------------------------
// Launch
// ---------------------------------------------------------------------------
extern "C" void kernel_launch(void* const* d_in, const int* in_sizes, int n_in,
                              void* d_out, int out_size)
{
    const float* x     = (const float*)d_in[0];
    const int*   mask  = (const int*)  d_in[1];
    const float* Wqkv  = (const float*)d_in[2];
    const float* bqkv  = (const float*)d_in[3];
    const float* Wout  = (const float*)d_in[4];
    const float* bout  = (const float*)d_in[5];
    float* out = (float*)d_out;

    float *gq, *attn, *xr, *wqkvT, *woutT, *kc, *vtc, *zrow;
    int *idx, *cmask, *cnt;
    cudaGetSymbolAddress((void**)&gq,    g_q);
    cudaGetSymbolAddress((void**)&attn,  g_attn);
    cudaGetSymbolAddress((void**)&xr,    g_x);
    cudaGetSymbolAddress((void**)&wqkvT, g_wqkvT);
    cudaGetSymbolAddress((void**)&woutT, g_woutT);
    cudaGetSymbolAddress((void**)&kc,    g_kc);
    cudaGetSymbolAddress((void**)&vtc,   g_vtc);
    cudaGetSymbolAddress((void**)&zrow,  g_zero);
    cudaGetSymbolAddress((void**)&idx,   g_idx);
    cudaGetSymbolAddress((void**)&cmask, g_cmask);
    cudaGetSymbolAddress((void**)&cnt,   g_cnt);

    cudaFuncSetAttribute(gemm_mma_kernel<false>,
                         cudaFuncAttributeMaxDynamicSharedMemorySize, GS_TOTAL);
    cudaFuncSetAttribute(gemm_qkv_kernel,
                         cudaFuncAttributeMaxDynamicSharedMemorySize, GS_TOTAL);
    cudaFuncSetAttribute(attn_mma_kernel,
                         cudaFuncAttributeMaxDynamicSharedMemorySize, ATTN_SM_BYTES);

    // 1) Fused prep: round x | transpose Wqkv | transpose Wout | scan+cmask+idx
    prep_fused_kernel<<<8194, 256>>>(x, Wqkv, Wout, mask,
                                     xr, wqkvT, woutT, idx, cnt, cmask);

    // 2) Fused QKV projection: KV (gather-on-load, transposed-V epilogue) + Q
    gemm_qkv_kernel<<<dim3(24, ROWS / 128), 128, GS_TOTAL>>>(
        xr, wqkvT, bqkv, idx, cnt, zrow, gq, kc, vtc);

    // 3) Flash attention over compacted keys
    attn_mma_kernel<<<dim3(LDIM / ABQ, BDIM * HEADS), 128, ATTN_SM_BYTES>>>(
        gq, kc, vtc, cmask, cnt, attn);

    // 4) Output projection (full-precision output)
    gemm_mma_kernel<false><<<dim3(DMODEL / 128, ROWS / 128), 128, GS_TOTAL>>>(
        attn, woutT, bout, out, DMODEL);
}